// round 4
// baseline (speedup 1.0000x reference)
#include <cuda_runtime.h>
#include <cstdint>

#define BB 2
#define NNx 768
#define DDx 512
#define HHx 16
#define DHx 32
#define INNERx 512
#define PDx 128
#define NEG_INFx -10000.0f
#define LN_EPS 1e-5f

typedef unsigned long long u64;

// ---------------- f32x2 packed-math helpers (exact fp32 semantics) ----------------
__device__ __forceinline__ void ffma2(u64& d, u64 a, u64 b) {
    asm("fma.rn.f32x2 %0, %1, %2, %0;" : "+l"(d) : "l"(a), "l"(b));
}
__device__ __forceinline__ float2 up2(u64 v) {
    float2 f;
    asm("mov.b64 {%0, %1}, %2;" : "=f"(f.x), "=f"(f.y) : "l"(v));
    return f;
}
__device__ __forceinline__ float hadd2(u64 v) {
    float2 f = up2(v);
    return f.x + f.y;
}
__device__ __forceinline__ u64 splat2(float x) {
    u64 r;
    asm("mov.b64 %0, {%1, %1};" : "=l"(r) : "f"(x));
    return r;
}
__device__ __forceinline__ uint32_t f2tf32(float f) {
    uint32_t r;
    asm("cvt.rna.tf32.f32 %0, %1;" : "=r"(r) : "f"(f));
    return r;
}
__device__ __forceinline__ void mma_tf32(float& c0, float& c1, float& c2, float& c3,
                                         uint32_t a0, uint32_t a1, uint32_t a2, uint32_t a3,
                                         uint32_t b0, uint32_t b1) {
    asm("mma.sync.aligned.m16n8k8.row.col.f32.tf32.tf32.f32 "
        "{%0,%1,%2,%3}, {%4,%5,%6,%7}, {%8,%9}, {%0,%1,%2,%3};"
        : "+f"(c0), "+f"(c1), "+f"(c2), "+f"(c3)
        : "r"(a0), "r"(a1), "r"(a2), "r"(a3), "r"(b0), "r"(b1));
}

// ---------------- scratch (static device memory: allowed) ----------------
__device__ float g_x[BB * NNx * DDx];
__device__ float g_qkvg[BB * NNx * 2048];                  // [q|k|v|g]
__device__ float g_qh[BB * HHx * NNx * DHx];
__device__ float g_kh[BB * HHx * NNx * DHx];
__device__ float g_vh[BB * HHx * NNx * DHx];
__device__ float g_bias[(size_t)BB * HHx * NNx * NNx];     // masked bias  75.5 MB
__device__ float g_og[BB * NNx * INNERx];
__device__ float g_Wt[HHx * PDx];                          // tf32-rounded W'[h][e]
__device__ float g_sh[HHx];
__device__ float g_th[HHx];

// ---------------- K0: fold pair-LN affine into projection weights ----------------
__global__ void k_prep(const float* __restrict__ bias_w,
                       const float* __restrict__ pnw,
                       const float* __restrict__ pnb) {
    int t = threadIdx.x;
    for (int idx = t; idx < HHx * PDx; idx += blockDim.x) {
        int h = idx >> 7, e = idx & 127;
        uint32_t tv = f2tf32(pnw[e] * bias_w[e * HHx + h]);
        g_Wt[idx] = __uint_as_float(tv);
    }
    if (t < HHx) {
        float s = 0.f, tt = 0.f;
        for (int e = 0; e < PDx; e++) {
            s  += pnw[e] * bias_w[e * HHx + t];
            tt += pnb[e] * bias_w[e * HHx + t];
        }
        g_sh[t] = s;
        g_th[t] = tt;
    }
}

// ---------------- K1: node LayerNorm ----------------
__global__ void k_ln_node(const float* __restrict__ nf,
                          const float* __restrict__ w,
                          const float* __restrict__ bp) {
    int row = blockIdx.x;
    const float* in = nf + (size_t)row * DDx;
    float s = 0.f, ss = 0.f;
    for (int c = threadIdx.x; c < DDx; c += 256) {
        float t = in[c];
        s += t; ss += t * t;
    }
#pragma unroll
    for (int o = 16; o > 0; o >>= 1) {
        s  += __shfl_xor_sync(~0u, s, o);
        ss += __shfl_xor_sync(~0u, ss, o);
    }
    __shared__ float red[16];
    int wid = threadIdx.x >> 5, lid = threadIdx.x & 31;
    if (lid == 0) { red[wid] = s; red[8 + wid] = ss; }
    __syncthreads();
    __shared__ float sm, sr;
    if (threadIdx.x == 0) {
        float S = 0.f, SS = 0.f;
        for (int i = 0; i < 8; i++) { S += red[i]; SS += red[8 + i]; }
        float m = S / DDx;
        sm = m;
        sr = rsqrtf(SS / DDx - m * m + LN_EPS);
    }
    __syncthreads();
    float m = sm, r = sr;
    for (int c = threadIdx.x; c < DDx; c += 256)
        g_x[(size_t)row * DDx + c] = (in[c] - m) * r * w[c] + bp[c];
}

// ---------------- K2: fused QKV+G GEMM (f32x2, i-pair packed) ----------------
__global__ void k_gemm_qkvg(const float* __restrict__ Wq, const float* __restrict__ bq,
                            const float* __restrict__ Wg, const float* __restrict__ bgp) {
    __shared__ __align__(16) float As[16][128];
    __shared__ __align__(16) float Bs[16][64];
    int bm = blockIdx.y * 128, bn = blockIdx.x * 64;
    int tid = threadIdx.x;
    int tr = tid >> 4, tc = tid & 15;
    u64 acc[4][4];
#pragma unroll
    for (int i = 0; i < 4; i++)
#pragma unroll
        for (int j = 0; j < 4; j++) acc[i][j] = 0ull;

    for (int k0 = 0; k0 < 512; k0 += 16) {
#pragma unroll
        for (int q = 0; q < 2; q++) {
            int f = tid * 2 + q;
            int r = f >> 2, c4 = (f & 3) << 2;
            float4 a = *(const float4*)&g_x[(size_t)(bm + r) * 512 + k0 + c4];
            As[c4 + 0][r] = a.x; As[c4 + 1][r] = a.y;
            As[c4 + 2][r] = a.z; As[c4 + 3][r] = a.w;
        }
        {
            int r = tid >> 4, c = (tid & 15) << 2;
            int n = bn + c;
            float4 bv;
            if (n < 1536) bv = *(const float4*)&Wq[(size_t)(k0 + r) * 1536 + n];
            else          bv = *(const float4*)&Wg[(size_t)(k0 + r) * 512 + (n - 1536)];
            *(float4*)&Bs[r][c] = bv;
        }
        __syncthreads();
#pragma unroll
        for (int kk = 0; kk < 16; kk++) {
            ulonglong2 aLo = *(const ulonglong2*)&As[kk][tr * 8];
            ulonglong2 aHi = *(const ulonglong2*)&As[kk][tr * 8 + 4];
            float4 b0 = *(const float4*)&Bs[kk][tc * 4];
            u64 s0 = splat2(b0.x), s1 = splat2(b0.y), s2 = splat2(b0.z), s3 = splat2(b0.w);
            ffma2(acc[0][0], aLo.x, s0); ffma2(acc[0][1], aLo.x, s1);
            ffma2(acc[0][2], aLo.x, s2); ffma2(acc[0][3], aLo.x, s3);
            ffma2(acc[1][0], aLo.y, s0); ffma2(acc[1][1], aLo.y, s1);
            ffma2(acc[1][2], aLo.y, s2); ffma2(acc[1][3], aLo.y, s3);
            ffma2(acc[2][0], aHi.x, s0); ffma2(acc[2][1], aHi.x, s1);
            ffma2(acc[2][2], aHi.x, s2); ffma2(acc[2][3], aHi.x, s3);
            ffma2(acc[3][0], aHi.y, s0); ffma2(acc[3][1], aHi.y, s1);
            ffma2(acc[3][2], aHi.y, s2); ffma2(acc[3][3], aHi.y, s3);
        }
        __syncthreads();
    }
#pragma unroll
    for (int ip = 0; ip < 4; ip++) {
        int r0 = bm + tr * 8 + ip * 2;
#pragma unroll
        for (int j = 0; j < 4; j++) {
            int col = bn + tc * 4 + j;
            float bias = (col < 1536) ? bq[col] : bgp[col - 1536];
            float2 v = up2(acc[ip][j]);
            g_qkvg[(size_t)r0 * 2048 + col]       = v.x + bias;
            g_qkvg[(size_t)(r0 + 1) * 2048 + col] = v.y + bias;
        }
    }
}

// ---------------- K3: q/k LN over INNER + transpose q,k,v to head-major ----------------
__global__ void k_lnqk(const float* __restrict__ qw, const float* __restrict__ qb,
                       const float* __restrict__ kw, const float* __restrict__ kb) {
    int bn = blockIdx.x;
    const float* row = g_qkvg + (size_t)bn * 2048;
    int b = bn / NNx, nn = bn % NNx;
    float s1 = 0.f, ss1 = 0.f, s2 = 0.f, ss2 = 0.f;
    for (int c = threadIdx.x; c < 512; c += 256) {
        float a = row[c], b2 = row[512 + c];
        s1 += a; ss1 += a * a; s2 += b2; ss2 += b2 * b2;
    }
#pragma unroll
    for (int o = 16; o > 0; o >>= 1) {
        s1  += __shfl_xor_sync(~0u, s1, o);  ss1 += __shfl_xor_sync(~0u, ss1, o);
        s2  += __shfl_xor_sync(~0u, s2, o);  ss2 += __shfl_xor_sync(~0u, ss2, o);
    }
    __shared__ float red[4][8];
    int w = threadIdx.x >> 5, lane = threadIdx.x & 31;
    if (lane == 0) { red[0][w] = s1; red[1][w] = ss1; red[2][w] = s2; red[3][w] = ss2; }
    __syncthreads();
    __shared__ float st[4];
    if (threadIdx.x == 0) {
        float a = 0.f, bb = 0.f, c = 0.f, d = 0.f;
        for (int i = 0; i < 8; i++) { a += red[0][i]; bb += red[1][i]; c += red[2][i]; d += red[3][i]; }
        float m1 = a / 512.f, m2 = c / 512.f;
        st[0] = m1; st[1] = rsqrtf(bb / 512.f - m1 * m1 + LN_EPS);
        st[2] = m2; st[3] = rsqrtf(d / 512.f - m2 * m2 + LN_EPS);
    }
    __syncthreads();
    float m1 = st[0], r1 = st[1], m2 = st[2], r2 = st[3];
    for (int c = threadIdx.x; c < 512; c += 256) {
        int h = c >> 5, d = c & 31;
        size_t oidx = (((size_t)(b * HHx + h)) * NNx + nn) * DHx + d;
        g_qh[oidx] = (row[c]       - m1) * r1 * qw[c] + qb[c];
        g_kh[oidx] = (row[512 + c] - m2) * r2 * kw[c] + kb[c];
        g_vh[oidx] = row[1024 + c];
    }
}

// ---------------- K4: pair bias via tf32 mma.sync (LN folded, W in registers) ----------------
// Block: 64 j x 16 h of one (b,i). 8 warps: warp w -> m-tile (w>>1, 16 j's), n-tile (w&1, 8 h's).
#define SPS 132
__global__ void k_pairbias(const float* __restrict__ pair, const int* __restrict__ mask) {
    __shared__ __align__(16) float sp[64 * SPS];     // tf32-rounded p tile (33792 B)
    __shared__ float outT[HHx * 64];
    __shared__ float smM[64], smR[64];
    __shared__ float sh_s[HHx], th_s[HHx];

    int tid = threadIdx.x, w = tid >> 5, lane = tid & 31;
    int j0 = blockIdx.x * 64;
    int i  = blockIdx.y, b = blockIdx.z;
    size_t rowbase = ((size_t)(b * NNx + i)) * NNx;

    int mt = w >> 1, nt = w & 1;
    int lg = lane >> 2, lt = lane & 3;       // group id / thread-in-group

    // B fragments for all 16 k-steps live in registers for the whole block.
    uint32_t bfrag[32];
    {
        const float* Wb = g_Wt + (nt * 8 + lg) * PDx + lt;
#pragma unroll
        for (int ks = 0; ks < 16; ks++) {
            bfrag[2 * ks]     = __float_as_uint(Wb[ks * 8]);
            bfrag[2 * ks + 1] = __float_as_uint(Wb[ks * 8 + 4]);
        }
    }
    if (tid < HHx) { sh_s[tid] = g_sh[tid]; th_s[tid] = g_th[tid]; }

    // stage 64x128 p-tile, rounding to tf32 (coalesced float4)
    const float* pbase = pair + (rowbase + j0) * (size_t)PDx;
#pragma unroll
    for (int it = 0; it < 8; it++) {
        int f = tid + it * 256;
        int r = f >> 5, c4 = (f & 31) << 2;
        float4 v = *(const float4*)&pbase[(size_t)r * PDx + c4];
        uint4 t;
        t.x = f2tf32(v.x); t.y = f2tf32(v.y); t.z = f2tf32(v.z); t.w = f2tf32(v.w);
        *(uint4*)&sp[r * SPS + c4] = t;
    }
    __syncthreads();

    // fp32 row stats from the (rounded) tile: 4 threads per row
    {
        int r = tid >> 2, seg = tid & 3;
        const float* p = sp + r * SPS + seg * 32;
        float s = 0.f, ss = 0.f;
#pragma unroll
        for (int c = 0; c < 8; c++) {
            float4 v = *(const float4*)&p[c * 4];
            s  += v.x + v.y + v.z + v.w;
            ss += v.x * v.x + v.y * v.y + v.z * v.z + v.w * v.w;
        }
        s  += __shfl_xor_sync(~0u, s, 1);  ss += __shfl_xor_sync(~0u, ss, 1);
        s  += __shfl_xor_sync(~0u, s, 2);  ss += __shfl_xor_sync(~0u, ss, 2);
        if (seg == 0) {
            float m = s * (1.0f / PDx);
            smM[r] = m;
            smR[r] = rsqrtf(ss * (1.0f / PDx) - m * m + LN_EPS);
        }
    }
    __syncthreads();

    // mma mainloop: C[16x8] per warp over K=128
    float c0 = 0.f, c1 = 0.f, c2 = 0.f, c3 = 0.f;
    const float* Ab = sp + (mt * 16 + lg) * SPS + lt;
#pragma unroll
    for (int ks = 0; ks < 16; ks++) {
        uint32_t a0 = __float_as_uint(Ab[ks * 8]);
        uint32_t a1 = __float_as_uint(Ab[ks * 8 + 8 * SPS]);
        uint32_t a2 = __float_as_uint(Ab[ks * 8 + 4]);
        uint32_t a3 = __float_as_uint(Ab[ks * 8 + 8 * SPS + 4]);
        mma_tf32(c0, c1, c2, c3, a0, a1, a2, a3, bfrag[2 * ks], bfrag[2 * ks + 1]);
    }

    // epilogue: exact-fp32 LN affine + mask, into transposed tile
    {
        int row0 = mt * 16 + lg;
        int row1 = row0 + 8;
        int col  = nt * 8 + 2 * lt;
        const int* maskrow = mask + rowbase + j0;
        float r0 = smR[row0], m0 = smM[row0];
        float r1 = smR[row1], m1 = smM[row1];
        int mk0 = maskrow[row0], mk1 = maskrow[row1];
        float sh0 = sh_s[col], sh1 = sh_s[col + 1];
        float th0 = th_s[col], th1 = th_s[col + 1];
        float v00 = r0 * c0 - r0 * m0 * sh0 + th0;
        float v01 = r0 * c1 - r0 * m0 * sh1 + th1;
        float v10 = r1 * c2 - r1 * m1 * sh0 + th0;
        float v11 = r1 * c3 - r1 * m1 * sh1 + th1;
        if (mk0 == 0) { v00 = NEG_INFx; v01 = NEG_INFx; }
        if (mk1 == 0) { v10 = NEG_INFx; v11 = NEG_INFx; }
        outT[col * 64 + row0]       = v00;
        outT[(col + 1) * 64 + row0] = v01;
        outT[col * 64 + row1]       = v10;
        outT[(col + 1) * 64 + row1] = v11;
    }
    __syncthreads();

    // coalesced write of [16][64] bias tile
    {
        int h = tid >> 4, c = (tid & 15) << 2;
        float4 v = *(const float4*)&outT[h * 64 + c];
        *(float4*)&g_bias[(((size_t)(b * HHx + h)) * NNx + i) * NNx + j0 + c] = v;
    }
}

// ---------------- K5: attention, 12 rows/block, warp owns 2 rows ----------------
__global__ void k_attn() {
    __shared__ __align__(16) float S[12][NNx];
    __shared__ __align__(16) float qs[12][DHx];
    int i0 = blockIdx.x * 12;
    int h = blockIdx.y, b = blockIdx.z;
    int tid = threadIdx.x;
    int w = tid >> 5, lane = tid & 31;
    size_t bhbase = (size_t)(b * HHx + h) * NNx;

    for (int idx = tid; idx < 12 * DHx; idx += 192) {
        int r = idx >> 5, d = idx & 31;
        qs[r][d] = g_qh[(bhbase + i0 + r) * DHx + d];
    }
    __syncthreads();

    const float scale = 0.17677669529663687f;
    int il0 = 2 * w, il1 = 2 * w + 1;
    int iA = i0 + il0, iB = i0 + il1;
    const float* b0row = g_bias + (bhbase + iA) * NNx;
    const float* b1row = g_bias + (bhbase + iB) * NNx;
    const float* q0p = &qs[il0][0];
    const float* q1p = &qs[il1][0];

    for (int jt = 0; jt < NNx / 32; jt++) {
        int j = jt * 32 + lane;
        const float* kr = g_kh + (bhbase + j) * DHx;
        u64 acc0 = 0, acc1 = 0;
#pragma unroll
        for (int d4 = 0; d4 < 8; d4++) {
            ulonglong2 kv = *(const ulonglong2*)(kr + d4 * 4);
            ulonglong2 q0 = *(const ulonglong2*)(q0p + d4 * 4);
            ulonglong2 q1 = *(const ulonglong2*)(q1p + d4 * 4);
            ffma2(acc0, kv.x, q0.x); ffma2(acc0, kv.y, q0.y);
            ffma2(acc1, kv.x, q1.x); ffma2(acc1, kv.y, q1.y);
        }
        S[il0][j] = hadd2(acc0) * scale + b0row[j];
        S[il1][j] = hadd2(acc1) * scale + b1row[j];
    }
    __syncwarp();

    float inv0, inv1;
#pragma unroll
    for (int rr = 0; rr < 2; rr++) {
        float* Sr = (rr == 0) ? &S[il0][0] : &S[il1][0];
        float mx = -3.4e38f;
        for (int c = lane; c < NNx; c += 32) mx = fmaxf(mx, Sr[c]);
#pragma unroll
        for (int o = 16; o > 0; o >>= 1) mx = fmaxf(mx, __shfl_xor_sync(~0u, mx, o));
        float sum = 0.f;
        for (int c = lane; c < NNx; c += 32) {
            float e = __expf(Sr[c] - mx);
            Sr[c] = e;
            sum += e;
        }
#pragma unroll
        for (int o = 16; o > 0; o >>= 1) sum += __shfl_xor_sync(~0u, sum, o);
        if (rr == 0) inv0 = 1.0f / sum; else inv1 = 1.0f / sum;
    }
    __syncwarp();

    int half = lane >> 4;
    int dp = (lane & 15) * 2;
    const float* vbase = g_vh + bhbase * DHx;
    float a00 = 0.f, a01 = 0.f, a10 = 0.f, a11 = 0.f;
    int jb = half * (NNx / 2);
    for (int jj = 0; jj < NNx / 2; jj += 4) {
        int j = jb + jj;
        float4 pA = *(const float4*)&S[il0][j];
        float4 pB = *(const float4*)&S[il1][j];
        const float* vp = vbase + (size_t)j * DHx + dp;
        float2 v0 = *(const float2*)(vp);
        float2 v1 = *(const float2*)(vp + 32);
        float2 v2 = *(const float2*)(vp + 64);
        float2 v3 = *(const float2*)(vp + 96);
        a00 += pA.x * v0.x + pA.y * v1.x + pA.z * v2.x + pA.w * v3.x;
        a01 += pA.x * v0.y + pA.y * v1.y + pA.z * v2.y + pA.w * v3.y;
        a10 += pB.x * v0.x + pB.y * v1.x + pB.z * v2.x + pB.w * v3.x;
        a11 += pB.x * v0.y + pB.y * v1.y + pB.z * v2.y + pB.w * v3.y;
    }
    a00 += __shfl_down_sync(~0u, a00, 16);
    a01 += __shfl_down_sync(~0u, a01, 16);
    a10 += __shfl_down_sync(~0u, a10, 16);
    a11 += __shfl_down_sync(~0u, a11, 16);

    if (half == 0) {
        size_t bnA = (size_t)b * NNx + iA;
        size_t bnB = (size_t)b * NNx + iB;
        float2 gA = *(const float2*)&g_qkvg[bnA * 2048 + 1536 + h * DHx + dp];
        float2 gB = *(const float2*)&g_qkvg[bnB * 2048 + 1536 + h * DHx + dp];
        float2 oA, oB;
        oA.x = a00 * inv0 * (1.0f / (1.0f + __expf(-gA.x)));
        oA.y = a01 * inv0 * (1.0f / (1.0f + __expf(-gA.y)));
        oB.x = a10 * inv1 * (1.0f / (1.0f + __expf(-gB.x)));
        oB.y = a11 * inv1 * (1.0f / (1.0f + __expf(-gB.y)));
        *(float2*)&g_og[bnA * INNERx + h * DHx + dp] = oA;
        *(float2*)&g_og[bnB * INNERx + h * DHx + dp] = oB;
    }
}

// ---------------- K6: output GEMM (f32x2, i-pair packed) ----------------
__global__ void k_gemm_out(const float* __restrict__ W, const float* __restrict__ bo,
                           float* __restrict__ C) {
    __shared__ __align__(16) float As[16][128];
    __shared__ __align__(16) float Bs[16][64];
    int bm = blockIdx.y * 128, bn = blockIdx.x * 64;
    int tid = threadIdx.x;
    int tr = tid >> 4, tc = tid & 15;
    u64 acc[4][4];
#pragma unroll
    for (int i = 0; i < 4; i++)
#pragma unroll
        for (int j = 0; j < 4; j++) acc[i][j] = 0ull;

    for (int k0 = 0; k0 < 512; k0 += 16) {
#pragma unroll
        for (int q = 0; q < 2; q++) {
            int f = tid * 2 + q;
            int r = f >> 2, c4 = (f & 3) << 2;
            float4 a = *(const float4*)&g_og[(size_t)(bm + r) * 512 + k0 + c4];
            As[c4 + 0][r] = a.x; As[c4 + 1][r] = a.y;
            As[c4 + 2][r] = a.z; As[c4 + 3][r] = a.w;
        }
        {
            int r = tid >> 4, c = (tid & 15) << 2;
            float4 bv = *(const float4*)&W[(size_t)(k0 + r) * 512 + bn + c];
            *(float4*)&Bs[r][c] = bv;
        }
        __syncthreads();
#pragma unroll
        for (int kk = 0; kk < 16; kk++) {
            ulonglong2 aLo = *(const ulonglong2*)&As[kk][tr * 8];
            ulonglong2 aHi = *(const ulonglong2*)&As[kk][tr * 8 + 4];
            float4 b0 = *(const float4*)&Bs[kk][tc * 4];
            u64 s0 = splat2(b0.x), s1 = splat2(b0.y), s2 = splat2(b0.z), s3 = splat2(b0.w);
            ffma2(acc[0][0], aLo.x, s0); ffma2(acc[0][1], aLo.x, s1);
            ffma2(acc[0][2], aLo.x, s2); ffma2(acc[0][3], aLo.x, s3);
            ffma2(acc[1][0], aLo.y, s0); ffma2(acc[1][1], aLo.y, s1);
            ffma2(acc[1][2], aLo.y, s2); ffma2(acc[1][3], aLo.y, s3);
            ffma2(acc[2][0], aHi.x, s0); ffma2(acc[2][1], aHi.x, s1);
            ffma2(acc[2][2], aHi.x, s2); ffma2(acc[2][3], aHi.x, s3);
            ffma2(acc[3][0], aHi.y, s0); ffma2(acc[3][1], aHi.y, s1);
            ffma2(acc[3][2], aHi.y, s2); ffma2(acc[3][3], aHi.y, s3);
        }
        __syncthreads();
    }
#pragma unroll
    for (int ip = 0; ip < 4; ip++) {
        int r0 = bm + tr * 8 + ip * 2;
#pragma unroll
        for (int j = 0; j < 4; j++) {
            int col = bn + tc * 4 + j;
            float2 v = up2(acc[ip][j]);
            C[(size_t)r0 * 512 + col]       = v.x + bo[col];
            C[(size_t)(r0 + 1) * 512 + col] = v.y + bo[col];
        }
    }
}

// ---------------- launch ----------------
extern "C" void kernel_launch(void* const* d_in, const int* in_sizes, int n_in,
                              void* d_out, int out_size) {
    const float* node = (const float*)d_in[0];
    const float* pair = (const float*)d_in[1];
    const int*   mask = (const int*)d_in[2];
    const float* nnw  = (const float*)d_in[3];
    const float* nnb  = (const float*)d_in[4];
    const float* qkvw = (const float*)d_in[5];
    const float* qkvb = (const float*)d_in[6];
    const float* gw   = (const float*)d_in[7];
    const float* gb   = (const float*)d_in[8];
    const float* qlw  = (const float*)d_in[9];
    const float* qlb  = (const float*)d_in[10];
    const float* klw  = (const float*)d_in[11];
    const float* klb  = (const float*)d_in[12];
    const float* pnw  = (const float*)d_in[13];
    const float* pnb  = (const float*)d_in[14];
    const float* bw   = (const float*)d_in[15];
    const float* ow   = (const float*)d_in[16];
    const float* ob   = (const float*)d_in[17];
    float* out = (float*)d_out;

    k_prep<<<1, 256>>>(bw, pnw, pnb);
    k_ln_node<<<BB * NNx, 256>>>(node, nnw, nnb);
    k_gemm_qkvg<<<dim3(2048 / 64, (BB * NNx) / 128), 256>>>(qkvw, qkvb, gw, gb);
    k_lnqk<<<BB * NNx, 256>>>(qlw, qlb, klw, klb);
    k_pairbias<<<dim3(NNx / 64, NNx, BB), 256>>>(pair, mask);
    k_attn<<<dim3(NNx / 12, HHx, BB), 192>>>();
    k_gemm_out<<<dim3(512 / 64, (BB * NNx) / 128), 256>>>(ow, ob, out);
}

// round 5
// speedup vs baseline: 1.0740x; 1.0740x over previous
#include <cuda_runtime.h>
#include <cstdint>

#define BB 2
#define NNx 768
#define DDx 512
#define HHx 16
#define DHx 32
#define INNERx 512
#define PDx 128
#define NEG_INFx -10000.0f
#define LN_EPS 1e-5f

typedef unsigned long long u64;

// ---------------- f32x2 packed-math helpers (exact fp32 semantics) ----------------
__device__ __forceinline__ void ffma2(u64& d, u64 a, u64 b) {
    asm("fma.rn.f32x2 %0, %1, %2, %0;" : "+l"(d) : "l"(a), "l"(b));
}
__device__ __forceinline__ float2 up2(u64 v) {
    float2 f;
    asm("mov.b64 {%0, %1}, %2;" : "=f"(f.x), "=f"(f.y) : "l"(v));
    return f;
}
__device__ __forceinline__ float hadd2(u64 v) {
    float2 f = up2(v);
    return f.x + f.y;
}
__device__ __forceinline__ uint32_t f2tf32(float f) {
    uint32_t r;
    asm("cvt.rna.tf32.f32 %0, %1;" : "=r"(r) : "f"(f));
    return r;
}
__device__ __forceinline__ void mma_tf32(float& c0, float& c1, float& c2, float& c3,
                                         uint32_t a0, uint32_t a1, uint32_t a2, uint32_t a3,
                                         uint32_t b0, uint32_t b1) {
    asm("mma.sync.aligned.m16n8k8.row.col.f32.tf32.tf32.f32 "
        "{%0,%1,%2,%3}, {%4,%5,%6,%7}, {%8,%9}, {%0,%1,%2,%3};"
        : "+f"(c0), "+f"(c1), "+f"(c2), "+f"(c3)
        : "r"(a0), "r"(a1), "r"(a2), "r"(a3), "r"(b0), "r"(b1));
}

// ---------------- scratch (static device memory: allowed) ----------------
__device__ float g_x[BB * NNx * DDx];
__device__ float g_qkvg[BB * NNx * 2048];                  // [q|k|v|g]
__device__ float g_qh[BB * HHx * NNx * DHx];
__device__ float g_kh[BB * HHx * NNx * DHx];
__device__ float g_vh[BB * HHx * NNx * DHx];
__device__ float g_bias[(size_t)BB * HHx * NNx * NNx];     // masked bias  75.5 MB
__device__ float g_og[BB * NNx * INNERx];
__device__ float g_Wt[HHx * PDx];                          // tf32-rounded W'[h][e]
__device__ float g_sh[HHx];
__device__ float g_th[HHx];

// ---------------- K0: fold pair-LN affine into projection weights ----------------
__global__ void k_prep(const float* __restrict__ bias_w,
                       const float* __restrict__ pnw,
                       const float* __restrict__ pnb) {
    int t = threadIdx.x;
    for (int idx = t; idx < HHx * PDx; idx += blockDim.x) {
        int h = idx >> 7, e = idx & 127;
        uint32_t tv = f2tf32(pnw[e] * bias_w[e * HHx + h]);
        g_Wt[idx] = __uint_as_float(tv);
    }
    if (t < HHx) {
        float s = 0.f, tt = 0.f;
        for (int e = 0; e < PDx; e++) {
            s  += pnw[e] * bias_w[e * HHx + t];
            tt += pnb[e] * bias_w[e * HHx + t];
        }
        g_sh[t] = s;
        g_th[t] = tt;
    }
}

// ---------------- K1: node LayerNorm ----------------
__global__ void k_ln_node(const float* __restrict__ nf,
                          const float* __restrict__ w,
                          const float* __restrict__ bp) {
    int row = blockIdx.x;
    const float* in = nf + (size_t)row * DDx;
    float s = 0.f, ss = 0.f;
    for (int c = threadIdx.x; c < DDx; c += 256) {
        float t = in[c];
        s += t; ss += t * t;
    }
#pragma unroll
    for (int o = 16; o > 0; o >>= 1) {
        s  += __shfl_xor_sync(~0u, s, o);
        ss += __shfl_xor_sync(~0u, ss, o);
    }
    __shared__ float red[16];
    int wid = threadIdx.x >> 5, lid = threadIdx.x & 31;
    if (lid == 0) { red[wid] = s; red[8 + wid] = ss; }
    __syncthreads();
    __shared__ float sm, sr;
    if (threadIdx.x == 0) {
        float S = 0.f, SS = 0.f;
        for (int i = 0; i < 8; i++) { S += red[i]; SS += red[8 + i]; }
        float m = S / DDx;
        sm = m;
        sr = rsqrtf(SS / DDx - m * m + LN_EPS);
    }
    __syncthreads();
    float m = sm, r = sr;
    for (int c = threadIdx.x; c < DDx; c += 256)
        g_x[(size_t)row * DDx + c] = (in[c] - m) * r * w[c] + bp[c];
}

// ---------------- K2/K6: dense GEMM on tensor pipe (tf32 mma) ----------------
// MODE 0: C[1536x2048] = g_x @ [Wqkv | Wg],  biases bq|bg, C = g_qkvg
// MODE 1: C[1536x512]  = g_og @ out_w,       bias bo,      C = Cext
// Block tile 128m x 64n, KTILE 16, 8 warps each 32x32.
#define AST 20
#define BST 72
template<int MODE>
__global__ void k_gemm_tc(const float* __restrict__ B1, const float* __restrict__ B2,
                          const float* __restrict__ bias1, const float* __restrict__ bias2,
                          float* __restrict__ Cext) {
    constexpr int LDC   = (MODE == 0) ? 2048 : 512;
    constexpr int SPLIT = (MODE == 0) ? 1536 : (1 << 30);
    constexpr int LD1   = (MODE == 0) ? 1536 : 512;
    constexpr int LD2   = 512;

    const float* A = (MODE == 0) ? g_x : g_og;
    float* C = (MODE == 0) ? g_qkvg : Cext;

    __shared__ __align__(16) float As[128 * AST];
    __shared__ __align__(16) float Bs[16 * BST];

    int bm = blockIdx.y * 128, bn = blockIdx.x * 64;
    int tid = threadIdx.x, w = tid >> 5, lane = tid & 31;
    int wm = w >> 1, wn = w & 1;
    int lg = lane >> 2, lt = lane & 3;

    float acc[2][4][4] = {};

    int mS = tid >> 1, segS = (tid & 1) * 8;
    int kS = tid >> 4, nS = (tid & 15) * 4;
    int ncol = bn + nS;
    const float* bsrc = (ncol < SPLIT) ? (B1 + ncol) : (B2 + (ncol - SPLIT));
    int ldb = (ncol < SPLIT) ? LD1 : LD2;

    for (int k0 = 0; k0 < 512; k0 += 16) {
        // stage A (128x16, cvt to tf32)
        {
            const float* as = A + (size_t)(bm + mS) * 512 + k0 + segS;
            float4 a0 = *(const float4*)as;
            float4 a1 = *(const float4*)(as + 4);
            uint4 t0 = {f2tf32(a0.x), f2tf32(a0.y), f2tf32(a0.z), f2tf32(a0.w)};
            uint4 t1 = {f2tf32(a1.x), f2tf32(a1.y), f2tf32(a1.z), f2tf32(a1.w)};
            *(uint4*)&As[mS * AST + segS]     = t0;
            *(uint4*)&As[mS * AST + segS + 4] = t1;
        }
        // stage B (16x64, cvt to tf32)
        {
            float4 b = *(const float4*)&bsrc[(size_t)(k0 + kS) * ldb];
            uint4 tb = {f2tf32(b.x), f2tf32(b.y), f2tf32(b.z), f2tf32(b.w)};
            *(uint4*)&Bs[kS * BST + nS] = tb;
        }
        __syncthreads();

#pragma unroll
        for (int ks = 0; ks < 2; ks++) {
            uint32_t af[2][4];
            const float* ab = &As[(wm * 32 + lg) * AST + ks * 8 + lt];
#pragma unroll
            for (int mf = 0; mf < 2; mf++) {
                const float* a = ab + mf * 16 * AST;
                af[mf][0] = __float_as_uint(a[0]);
                af[mf][1] = __float_as_uint(a[8 * AST]);
                af[mf][2] = __float_as_uint(a[4]);
                af[mf][3] = __float_as_uint(a[8 * AST + 4]);
            }
            uint32_t bf[4][2];
            const float* bb = &Bs[(ks * 8 + lt) * BST + wn * 32 + lg];
#pragma unroll
            for (int nf = 0; nf < 4; nf++) {
                bf[nf][0] = __float_as_uint(bb[nf * 8]);
                bf[nf][1] = __float_as_uint(bb[4 * BST + nf * 8]);
            }
#pragma unroll
            for (int mf = 0; mf < 2; mf++)
#pragma unroll
                for (int nf = 0; nf < 4; nf++)
                    mma_tf32(acc[mf][nf][0], acc[mf][nf][1], acc[mf][nf][2], acc[mf][nf][3],
                             af[mf][0], af[mf][1], af[mf][2], af[mf][3],
                             bf[nf][0], bf[nf][1]);
        }
        __syncthreads();
    }

    // epilogue: C frag (c0:(lg,2lt) c1:(lg,2lt+1) c2:(lg+8,2lt) c3:(lg+8,2lt+1))
#pragma unroll
    for (int mf = 0; mf < 2; mf++) {
#pragma unroll
        for (int nf = 0; nf < 4; nf++) {
            int r = bm + wm * 32 + mf * 16 + lg;
            int c = bn + wn * 32 + nf * 8 + 2 * lt;
            float bi0 = (c < SPLIT) ? bias1[c] : bias2[c - SPLIT];
            float bi1 = (c + 1 < SPLIT) ? bias1[c + 1] : bias2[c + 1 - SPLIT];
            float2 v0 = {acc[mf][nf][0] + bi0, acc[mf][nf][1] + bi1};
            float2 v1 = {acc[mf][nf][2] + bi0, acc[mf][nf][3] + bi1};
            *(float2*)&C[(size_t)r * LDC + c]       = v0;
            *(float2*)&C[(size_t)(r + 8) * LDC + c] = v1;
        }
    }
}

// ---------------- K3: q/k LN over INNER + transpose q,k,v to head-major ----------------
__global__ void k_lnqk(const float* __restrict__ qw, const float* __restrict__ qb,
                       const float* __restrict__ kw, const float* __restrict__ kb) {
    int bn = blockIdx.x;
    const float* row = g_qkvg + (size_t)bn * 2048;
    int b = bn / NNx, nn = bn % NNx;
    float s1 = 0.f, ss1 = 0.f, s2 = 0.f, ss2 = 0.f;
    for (int c = threadIdx.x; c < 512; c += 256) {
        float a = row[c], b2 = row[512 + c];
        s1 += a; ss1 += a * a; s2 += b2; ss2 += b2 * b2;
    }
#pragma unroll
    for (int o = 16; o > 0; o >>= 1) {
        s1  += __shfl_xor_sync(~0u, s1, o);  ss1 += __shfl_xor_sync(~0u, ss1, o);
        s2  += __shfl_xor_sync(~0u, s2, o);  ss2 += __shfl_xor_sync(~0u, ss2, o);
    }
    __shared__ float red[4][8];
    int w = threadIdx.x >> 5, lane = threadIdx.x & 31;
    if (lane == 0) { red[0][w] = s1; red[1][w] = ss1; red[2][w] = s2; red[3][w] = ss2; }
    __syncthreads();
    __shared__ float st[4];
    if (threadIdx.x == 0) {
        float a = 0.f, bb = 0.f, c = 0.f, d = 0.f;
        for (int i = 0; i < 8; i++) { a += red[0][i]; bb += red[1][i]; c += red[2][i]; d += red[3][i]; }
        float m1 = a / 512.f, m2 = c / 512.f;
        st[0] = m1; st[1] = rsqrtf(bb / 512.f - m1 * m1 + LN_EPS);
        st[2] = m2; st[3] = rsqrtf(d / 512.f - m2 * m2 + LN_EPS);
    }
    __syncthreads();
    float m1 = st[0], r1 = st[1], m2 = st[2], r2 = st[3];
    for (int c = threadIdx.x; c < 512; c += 256) {
        int h = c >> 5, d = c & 31;
        size_t oidx = (((size_t)(b * HHx + h)) * NNx + nn) * DHx + d;
        g_qh[oidx] = (row[c]       - m1) * r1 * qw[c] + qb[c];
        g_kh[oidx] = (row[512 + c] - m2) * r2 * kw[c] + kb[c];
        g_vh[oidx] = row[1024 + c];
    }
}

// ---------------- K4: pair bias via tf32 mma.sync (LN folded, W in registers) ----------------
#define SPS 132
__global__ void k_pairbias(const float* __restrict__ pair, const int* __restrict__ mask) {
    __shared__ __align__(16) float sp[64 * SPS];
    __shared__ float outT[HHx * 64];
    __shared__ float smM[64], smR[64];
    __shared__ float sh_s[HHx], th_s[HHx];

    int tid = threadIdx.x, w = tid >> 5, lane = tid & 31;
    int j0 = blockIdx.x * 64;
    int i  = blockIdx.y, b = blockIdx.z;
    size_t rowbase = ((size_t)(b * NNx + i)) * NNx;

    int mt = w >> 1, nt = w & 1;
    int lg = lane >> 2, lt = lane & 3;

    uint32_t bfrag[32];
    {
        const float* Wb = g_Wt + (nt * 8 + lg) * PDx + lt;
#pragma unroll
        for (int ks = 0; ks < 16; ks++) {
            bfrag[2 * ks]     = __float_as_uint(Wb[ks * 8]);
            bfrag[2 * ks + 1] = __float_as_uint(Wb[ks * 8 + 4]);
        }
    }
    if (tid < HHx) { sh_s[tid] = g_sh[tid]; th_s[tid] = g_th[tid]; }

    const float* pbase = pair + (rowbase + j0) * (size_t)PDx;
#pragma unroll
    for (int it = 0; it < 8; it++) {
        int f = tid + it * 256;
        int r = f >> 5, c4 = (f & 31) << 2;
        float4 v = *(const float4*)&pbase[(size_t)r * PDx + c4];
        uint4 t;
        t.x = f2tf32(v.x); t.y = f2tf32(v.y); t.z = f2tf32(v.z); t.w = f2tf32(v.w);
        *(uint4*)&sp[r * SPS + c4] = t;
    }
    __syncthreads();

    {
        int r = tid >> 2, seg = tid & 3;
        const float* p = sp + r * SPS + seg * 32;
        float s = 0.f, ss = 0.f;
#pragma unroll
        for (int c = 0; c < 8; c++) {
            float4 v = *(const float4*)&p[c * 4];
            s  += v.x + v.y + v.z + v.w;
            ss += v.x * v.x + v.y * v.y + v.z * v.z + v.w * v.w;
        }
        s  += __shfl_xor_sync(~0u, s, 1);  ss += __shfl_xor_sync(~0u, ss, 1);
        s  += __shfl_xor_sync(~0u, s, 2);  ss += __shfl_xor_sync(~0u, ss, 2);
        if (seg == 0) {
            float m = s * (1.0f / PDx);
            smM[r] = m;
            smR[r] = rsqrtf(ss * (1.0f / PDx) - m * m + LN_EPS);
        }
    }
    __syncthreads();

    float c0 = 0.f, c1 = 0.f, c2 = 0.f, c3 = 0.f;
    const float* Ab = sp + (mt * 16 + lg) * SPS + lt;
#pragma unroll
    for (int ks = 0; ks < 16; ks++) {
        uint32_t a0 = __float_as_uint(Ab[ks * 8]);
        uint32_t a1 = __float_as_uint(Ab[ks * 8 + 8 * SPS]);
        uint32_t a2 = __float_as_uint(Ab[ks * 8 + 4]);
        uint32_t a3 = __float_as_uint(Ab[ks * 8 + 8 * SPS + 4]);
        mma_tf32(c0, c1, c2, c3, a0, a1, a2, a3, bfrag[2 * ks], bfrag[2 * ks + 1]);
    }

    {
        int row0 = mt * 16 + lg;
        int row1 = row0 + 8;
        int col  = nt * 8 + 2 * lt;
        const int* maskrow = mask + rowbase + j0;
        float r0 = smR[row0], m0 = smM[row0];
        float r1 = smR[row1], m1 = smM[row1];
        int mk0 = maskrow[row0], mk1 = maskrow[row1];
        float sh0 = sh_s[col], sh1 = sh_s[col + 1];
        float th0 = th_s[col], th1 = th_s[col + 1];
        float v00 = r0 * c0 - r0 * m0 * sh0 + th0;
        float v01 = r0 * c1 - r0 * m0 * sh1 + th1;
        float v10 = r1 * c2 - r1 * m1 * sh0 + th0;
        float v11 = r1 * c3 - r1 * m1 * sh1 + th1;
        if (mk0 == 0) { v00 = NEG_INFx; v01 = NEG_INFx; }
        if (mk1 == 0) { v10 = NEG_INFx; v11 = NEG_INFx; }
        outT[col * 64 + row0]       = v00;
        outT[(col + 1) * 64 + row0] = v01;
        outT[col * 64 + row1]       = v10;
        outT[(col + 1) * 64 + row1] = v11;
    }
    __syncthreads();

    {
        int h = tid >> 4, c = (tid & 15) << 2;
        float4 v = *(const float4*)&outT[h * 64 + c];
        *(float4*)&g_bias[(((size_t)(b * HHx + h)) * NNx + i) * NNx + j0 + c] = v;
    }
}

// ---------------- K5: attention, 12 rows/block, warp owns 2 rows ----------------
__global__ void k_attn() {
    __shared__ __align__(16) float S[12][NNx];
    __shared__ __align__(16) float qs[12][DHx];
    int i0 = blockIdx.x * 12;
    int h = blockIdx.y, b = blockIdx.z;
    int tid = threadIdx.x;
    int w = tid >> 5, lane = tid & 31;
    size_t bhbase = (size_t)(b * HHx + h) * NNx;

    for (int idx = tid; idx < 12 * DHx; idx += 192) {
        int r = idx >> 5, d = idx & 31;
        qs[r][d] = g_qh[(bhbase + i0 + r) * DHx + d];
    }
    __syncthreads();

    const float scale = 0.17677669529663687f;
    int il0 = 2 * w, il1 = 2 * w + 1;
    int iA = i0 + il0, iB = i0 + il1;
    const float* b0row = g_bias + (bhbase + iA) * NNx;
    const float* b1row = g_bias + (bhbase + iB) * NNx;
    const float* q0p = &qs[il0][0];
    const float* q1p = &qs[il1][0];

    for (int jt = 0; jt < NNx / 32; jt++) {
        int j = jt * 32 + lane;
        const float* kr = g_kh + (bhbase + j) * DHx;
        u64 acc0 = 0, acc1 = 0;
#pragma unroll
        for (int d4 = 0; d4 < 8; d4++) {
            ulonglong2 kv = *(const ulonglong2*)(kr + d4 * 4);
            ulonglong2 q0 = *(const ulonglong2*)(q0p + d4 * 4);
            ulonglong2 q1 = *(const ulonglong2*)(q1p + d4 * 4);
            ffma2(acc0, kv.x, q0.x); ffma2(acc0, kv.y, q0.y);
            ffma2(acc1, kv.x, q1.x); ffma2(acc1, kv.y, q1.y);
        }
        S[il0][j] = hadd2(acc0) * scale + b0row[j];
        S[il1][j] = hadd2(acc1) * scale + b1row[j];
    }
    __syncwarp();

    float inv0, inv1;
#pragma unroll
    for (int rr = 0; rr < 2; rr++) {
        float* Sr = (rr == 0) ? &S[il0][0] : &S[il1][0];
        float mx = -3.4e38f;
        for (int c = lane; c < NNx; c += 32) mx = fmaxf(mx, Sr[c]);
#pragma unroll
        for (int o = 16; o > 0; o >>= 1) mx = fmaxf(mx, __shfl_xor_sync(~0u, mx, o));
        float sum = 0.f;
        for (int c = lane; c < NNx; c += 32) {
            float e = __expf(Sr[c] - mx);
            Sr[c] = e;
            sum += e;
        }
#pragma unroll
        for (int o = 16; o > 0; o >>= 1) sum += __shfl_xor_sync(~0u, sum, o);
        if (rr == 0) inv0 = 1.0f / sum; else inv1 = 1.0f / sum;
    }
    __syncwarp();

    int half = lane >> 4;
    int dp = (lane & 15) * 2;
    const float* vbase = g_vh + bhbase * DHx;
    float a00 = 0.f, a01 = 0.f, a10 = 0.f, a11 = 0.f;
    int jb = half * (NNx / 2);
    for (int jj = 0; jj < NNx / 2; jj += 4) {
        int j = jb + jj;
        float4 pA = *(const float4*)&S[il0][j];
        float4 pB = *(const float4*)&S[il1][j];
        const float* vp = vbase + (size_t)j * DHx + dp;
        float2 v0 = *(const float2*)(vp);
        float2 v1 = *(const float2*)(vp + 32);
        float2 v2 = *(const float2*)(vp + 64);
        float2 v3 = *(const float2*)(vp + 96);
        a00 += pA.x * v0.x + pA.y * v1.x + pA.z * v2.x + pA.w * v3.x;
        a01 += pA.x * v0.y + pA.y * v1.y + pA.z * v2.y + pA.w * v3.y;
        a10 += pB.x * v0.x + pB.y * v1.x + pB.z * v2.x + pB.w * v3.x;
        a11 += pB.x * v0.y + pB.y * v1.y + pB.z * v2.y + pB.w * v3.y;
    }
    a00 += __shfl_down_sync(~0u, a00, 16);
    a01 += __shfl_down_sync(~0u, a01, 16);
    a10 += __shfl_down_sync(~0u, a10, 16);
    a11 += __shfl_down_sync(~0u, a11, 16);

    if (half == 0) {
        size_t bnA = (size_t)b * NNx + iA;
        size_t bnB = (size_t)b * NNx + iB;
        float2 gA = *(const float2*)&g_qkvg[bnA * 2048 + 1536 + h * DHx + dp];
        float2 gB = *(const float2*)&g_qkvg[bnB * 2048 + 1536 + h * DHx + dp];
        float2 oA, oB;
        oA.x = a00 * inv0 * (1.0f / (1.0f + __expf(-gA.x)));
        oA.y = a01 * inv0 * (1.0f / (1.0f + __expf(-gA.y)));
        oB.x = a10 * inv1 * (1.0f / (1.0f + __expf(-gB.x)));
        oB.y = a11 * inv1 * (1.0f / (1.0f + __expf(-gB.y)));
        *(float2*)&g_og[bnA * INNERx + h * DHx + dp] = oA;
        *(float2*)&g_og[bnB * INNERx + h * DHx + dp] = oB;
    }
}

// ---------------- launch ----------------
extern "C" void kernel_launch(void* const* d_in, const int* in_sizes, int n_in,
                              void* d_out, int out_size) {
    const float* node = (const float*)d_in[0];
    const float* pair = (const float*)d_in[1];
    const int*   mask = (const int*)d_in[2];
    const float* nnw  = (const float*)d_in[3];
    const float* nnb  = (const float*)d_in[4];
    const float* qkvw = (const float*)d_in[5];
    const float* qkvb = (const float*)d_in[6];
    const float* gw   = (const float*)d_in[7];
    const float* gb   = (const float*)d_in[8];
    const float* qlw  = (const float*)d_in[9];
    const float* qlb  = (const float*)d_in[10];
    const float* klw  = (const float*)d_in[11];
    const float* klb  = (const float*)d_in[12];
    const float* pnw  = (const float*)d_in[13];
    const float* pnb  = (const float*)d_in[14];
    const float* bw   = (const float*)d_in[15];
    const float* ow   = (const float*)d_in[16];
    const float* ob   = (const float*)d_in[17];
    float* out = (float*)d_out;

    k_prep<<<1, 256>>>(bw, pnw, pnb);
    k_ln_node<<<BB * NNx, 256>>>(node, nnw, nnb);
    k_gemm_tc<0><<<dim3(2048 / 64, (BB * NNx) / 128), 256>>>(qkvw, gw, qkvb, gb, nullptr);
    k_lnqk<<<BB * NNx, 256>>>(qlw, qlb, klw, klb);
    k_pairbias<<<dim3(NNx / 64, NNx, BB), 256>>>(pair, mask);
    k_attn<<<dim3(NNx / 12, HHx, BB), 192>>>();
    k_gemm_tc<1><<<dim3(512 / 64, (BB * NNx) / 128), 256>>>(ow, ow, ob, ob, out);
}

// round 6
// speedup vs baseline: 1.5031x; 1.3995x over previous
#include <cuda_runtime.h>
#include <cstdint>

#define BB 2
#define NNx 768
#define DDx 512
#define HHx 16
#define DHx 32
#define INNERx 512
#define PDx 128
#define NEG_INFx -10000.0f
#define LN_EPS 1e-5f

typedef unsigned long long u64;

// ---------------- f32x2 packed-math helpers (exact fp32 semantics) ----------------
__device__ __forceinline__ void ffma2(u64& d, u64 a, u64 b) {
    asm("fma.rn.f32x2 %0, %1, %2, %0;" : "+l"(d) : "l"(a), "l"(b));
}
__device__ __forceinline__ float2 up2(u64 v) {
    float2 f;
    asm("mov.b64 {%0, %1}, %2;" : "=f"(f.x), "=f"(f.y) : "l"(v));
    return f;
}
__device__ __forceinline__ u64 pack2(float x, float y) {
    u64 r;
    asm("mov.b64 %0, {%1, %2};" : "=l"(r) : "f"(x), "f"(y));
    return r;
}
__device__ __forceinline__ u64 splat2(float x) {
    u64 r;
    asm("mov.b64 %0, {%1, %1};" : "=l"(r) : "f"(x));
    return r;
}
__device__ __forceinline__ uint32_t f2tf32(float f) {
    uint32_t r;
    asm("cvt.rna.tf32.f32 %0, %1;" : "=r"(r) : "f"(f));
    return r;
}
__device__ __forceinline__ void mma_tf32(float& c0, float& c1, float& c2, float& c3,
                                         uint32_t a0, uint32_t a1, uint32_t a2, uint32_t a3,
                                         uint32_t b0, uint32_t b1) {
    asm("mma.sync.aligned.m16n8k8.row.col.f32.tf32.tf32.f32 "
        "{%0,%1,%2,%3}, {%4,%5,%6,%7}, {%8,%9}, {%0,%1,%2,%3};"
        : "+f"(c0), "+f"(c1), "+f"(c2), "+f"(c3)
        : "r"(a0), "r"(a1), "r"(a2), "r"(a3), "r"(b0), "r"(b1));
}

// ---------------- scratch (static device memory: allowed) ----------------
__device__ float g_x[BB * NNx * DDx];
__device__ float g_qkvg[BB * NNx * 2048];                  // [q|k|v|g]
__device__ float g_qh[BB * HHx * NNx * DHx];               // q [b][h][n][d]
__device__ float g_khT[BB * HHx * DHx * NNx];              // k [b][h][d][n]  (transposed!)
__device__ float g_vh[BB * HHx * NNx * DHx];               // v [b][h][n][d]
__device__ float g_bias[(size_t)BB * HHx * NNx * NNx];     // masked bias  75.5 MB
__device__ float g_og[BB * NNx * INNERx];
__device__ float g_Wt[HHx * PDx];                          // tf32-rounded W'[h][e]
__device__ float g_sh[HHx];
__device__ float g_th[HHx];

// ---------------- K0: fold pair-LN affine into projection weights ----------------
__global__ void k_prep(const float* __restrict__ bias_w,
                       const float* __restrict__ pnw,
                       const float* __restrict__ pnb) {
    int t = threadIdx.x;
    for (int idx = t; idx < HHx * PDx; idx += blockDim.x) {
        int h = idx >> 7, e = idx & 127;
        uint32_t tv = f2tf32(pnw[e] * bias_w[e * HHx + h]);
        g_Wt[idx] = __uint_as_float(tv);
    }
    if (t < HHx) {
        float s = 0.f, tt = 0.f;
        for (int e = 0; e < PDx; e++) {
            s  += pnw[e] * bias_w[e * HHx + t];
            tt += pnb[e] * bias_w[e * HHx + t];
        }
        g_sh[t] = s;
        g_th[t] = tt;
    }
}

// ---------------- K1: node LayerNorm ----------------
__global__ void k_ln_node(const float* __restrict__ nf,
                          const float* __restrict__ w,
                          const float* __restrict__ bp) {
    int row = blockIdx.x;
    const float* in = nf + (size_t)row * DDx;
    float s = 0.f, ss = 0.f;
    for (int c = threadIdx.x; c < DDx; c += 256) {
        float t = in[c];
        s += t; ss += t * t;
    }
#pragma unroll
    for (int o = 16; o > 0; o >>= 1) {
        s  += __shfl_xor_sync(~0u, s, o);
        ss += __shfl_xor_sync(~0u, ss, o);
    }
    __shared__ float red[16];
    int wid = threadIdx.x >> 5, lid = threadIdx.x & 31;
    if (lid == 0) { red[wid] = s; red[8 + wid] = ss; }
    __syncthreads();
    __shared__ float sm, sr;
    if (threadIdx.x == 0) {
        float S = 0.f, SS = 0.f;
        for (int i = 0; i < 8; i++) { S += red[i]; SS += red[8 + i]; }
        float m = S / DDx;
        sm = m;
        sr = rsqrtf(SS / DDx - m * m + LN_EPS);
    }
    __syncthreads();
    float m = sm, r = sr;
    for (int c = threadIdx.x; c < DDx; c += 256)
        g_x[(size_t)row * DDx + c] = (in[c] - m) * r * w[c] + bp[c];
}

// ---------------- K2/K6: dense GEMM on tensor pipe (tf32 mma) ----------------
#define AST 20
#define BST 72
template<int MODE>
__global__ void k_gemm_tc(const float* __restrict__ B1, const float* __restrict__ B2,
                          const float* __restrict__ bias1, const float* __restrict__ bias2,
                          float* __restrict__ Cext) {
    constexpr int LDC   = (MODE == 0) ? 2048 : 512;
    constexpr int SPLIT = (MODE == 0) ? 1536 : (1 << 30);
    constexpr int LD1   = (MODE == 0) ? 1536 : 512;
    constexpr int LD2   = 512;

    const float* A = (MODE == 0) ? g_x : g_og;
    float* C = (MODE == 0) ? g_qkvg : Cext;

    __shared__ __align__(16) float As[128 * AST];
    __shared__ __align__(16) float Bs[16 * BST];

    int bm = blockIdx.y * 128, bn = blockIdx.x * 64;
    int tid = threadIdx.x, w = tid >> 5, lane = tid & 31;
    int wm = w >> 1, wn = w & 1;
    int lg = lane >> 2, lt = lane & 3;

    float acc[2][4][4] = {};

    int mS = tid >> 1, segS = (tid & 1) * 8;
    int kS = tid >> 4, nS = (tid & 15) * 4;
    int ncol = bn + nS;
    const float* bsrc = (ncol < SPLIT) ? (B1 + ncol) : (B2 + (ncol - SPLIT));
    int ldb = (ncol < SPLIT) ? LD1 : LD2;

    for (int k0 = 0; k0 < 512; k0 += 16) {
        {
            const float* as = A + (size_t)(bm + mS) * 512 + k0 + segS;
            float4 a0 = *(const float4*)as;
            float4 a1 = *(const float4*)(as + 4);
            uint4 t0 = {f2tf32(a0.x), f2tf32(a0.y), f2tf32(a0.z), f2tf32(a0.w)};
            uint4 t1 = {f2tf32(a1.x), f2tf32(a1.y), f2tf32(a1.z), f2tf32(a1.w)};
            *(uint4*)&As[mS * AST + segS]     = t0;
            *(uint4*)&As[mS * AST + segS + 4] = t1;
        }
        {
            float4 b = *(const float4*)&bsrc[(size_t)(k0 + kS) * ldb];
            uint4 tb = {f2tf32(b.x), f2tf32(b.y), f2tf32(b.z), f2tf32(b.w)};
            *(uint4*)&Bs[kS * BST + nS] = tb;
        }
        __syncthreads();

#pragma unroll
        for (int ks = 0; ks < 2; ks++) {
            uint32_t af[2][4];
            const float* ab = &As[(wm * 32 + lg) * AST + ks * 8 + lt];
#pragma unroll
            for (int mf = 0; mf < 2; mf++) {
                const float* a = ab + mf * 16 * AST;
                af[mf][0] = __float_as_uint(a[0]);
                af[mf][1] = __float_as_uint(a[8 * AST]);
                af[mf][2] = __float_as_uint(a[4]);
                af[mf][3] = __float_as_uint(a[8 * AST + 4]);
            }
            uint32_t bf[4][2];
            const float* bb = &Bs[(ks * 8 + lt) * BST + wn * 32 + lg];
#pragma unroll
            for (int nf = 0; nf < 4; nf++) {
                bf[nf][0] = __float_as_uint(bb[nf * 8]);
                bf[nf][1] = __float_as_uint(bb[4 * BST + nf * 8]);
            }
#pragma unroll
            for (int mf = 0; mf < 2; mf++)
#pragma unroll
                for (int nf = 0; nf < 4; nf++)
                    mma_tf32(acc[mf][nf][0], acc[mf][nf][1], acc[mf][nf][2], acc[mf][nf][3],
                             af[mf][0], af[mf][1], af[mf][2], af[mf][3],
                             bf[nf][0], bf[nf][1]);
        }
        __syncthreads();
    }

#pragma unroll
    for (int mf = 0; mf < 2; mf++) {
#pragma unroll
        for (int nf = 0; nf < 4; nf++) {
            int r = bm + wm * 32 + mf * 16 + lg;
            int c = bn + wn * 32 + nf * 8 + 2 * lt;
            float bi0 = (c < SPLIT) ? bias1[c] : bias2[c - SPLIT];
            float bi1 = (c + 1 < SPLIT) ? bias1[c + 1] : bias2[c + 1 - SPLIT];
            float2 v0 = {acc[mf][nf][0] + bi0, acc[mf][nf][1] + bi1};
            float2 v1 = {acc[mf][nf][2] + bi0, acc[mf][nf][3] + bi1};
            *(float2*)&C[(size_t)r * LDC + c]       = v0;
            *(float2*)&C[(size_t)(r + 8) * LDC + c] = v1;
        }
    }
}

// ---------------- K3: q/k LN over INNER; q,v head-major, k TRANSPOSED ----------------
__global__ void k_lnqk(const float* __restrict__ qw, const float* __restrict__ qb,
                       const float* __restrict__ kw, const float* __restrict__ kb) {
    int bn = blockIdx.x;
    const float* row = g_qkvg + (size_t)bn * 2048;
    int b = bn / NNx, nn = bn % NNx;
    float s1 = 0.f, ss1 = 0.f, s2 = 0.f, ss2 = 0.f;
    for (int c = threadIdx.x; c < 512; c += 256) {
        float a = row[c], b2 = row[512 + c];
        s1 += a; ss1 += a * a; s2 += b2; ss2 += b2 * b2;
    }
#pragma unroll
    for (int o = 16; o > 0; o >>= 1) {
        s1  += __shfl_xor_sync(~0u, s1, o);  ss1 += __shfl_xor_sync(~0u, ss1, o);
        s2  += __shfl_xor_sync(~0u, s2, o);  ss2 += __shfl_xor_sync(~0u, ss2, o);
    }
    __shared__ float red[4][8];
    int w = threadIdx.x >> 5, lane = threadIdx.x & 31;
    if (lane == 0) { red[0][w] = s1; red[1][w] = ss1; red[2][w] = s2; red[3][w] = ss2; }
    __syncthreads();
    __shared__ float st[4];
    if (threadIdx.x == 0) {
        float a = 0.f, bb = 0.f, c = 0.f, d = 0.f;
        for (int i = 0; i < 8; i++) { a += red[0][i]; bb += red[1][i]; c += red[2][i]; d += red[3][i]; }
        float m1 = a / 512.f, m2 = c / 512.f;
        st[0] = m1; st[1] = rsqrtf(bb / 512.f - m1 * m1 + LN_EPS);
        st[2] = m2; st[3] = rsqrtf(d / 512.f - m2 * m2 + LN_EPS);
    }
    __syncthreads();
    float m1 = st[0], r1 = st[1], m2 = st[2], r2 = st[3];
    for (int c = threadIdx.x; c < 512; c += 256) {
        int h = c >> 5, d = c & 31;
        size_t oidx  = (((size_t)(b * HHx + h)) * NNx + nn) * DHx + d;     // [b][h][n][d]
        size_t oidxT = (((size_t)(b * HHx + h)) * DHx + d) * NNx + nn;     // [b][h][d][n]
        g_qh[oidx]   = (row[c]       - m1) * r1 * qw[c] + qb[c];
        g_khT[oidxT] = (row[512 + c] - m2) * r2 * kw[c] + kb[c];
        g_vh[oidx]   = row[1024 + c];
    }
}

// ---------------- K4: pair bias via tf32 mma.sync (LN folded, W in registers) ----------------
#define SPS 132
__global__ void k_pairbias(const float* __restrict__ pair, const int* __restrict__ mask) {
    __shared__ __align__(16) float sp[64 * SPS];
    __shared__ float outT[HHx * 64];
    __shared__ float smM[64], smR[64];
    __shared__ float sh_s[HHx], th_s[HHx];

    int tid = threadIdx.x, w = tid >> 5, lane = tid & 31;
    int j0 = blockIdx.x * 64;
    int i  = blockIdx.y, b = blockIdx.z;
    size_t rowbase = ((size_t)(b * NNx + i)) * NNx;

    int mt = w >> 1, nt = w & 1;
    int lg = lane >> 2, lt = lane & 3;

    uint32_t bfrag[32];
    {
        const float* Wb = g_Wt + (nt * 8 + lg) * PDx + lt;
#pragma unroll
        for (int ks = 0; ks < 16; ks++) {
            bfrag[2 * ks]     = __float_as_uint(Wb[ks * 8]);
            bfrag[2 * ks + 1] = __float_as_uint(Wb[ks * 8 + 4]);
        }
    }
    if (tid < HHx) { sh_s[tid] = g_sh[tid]; th_s[tid] = g_th[tid]; }

    const float* pbase = pair + (rowbase + j0) * (size_t)PDx;
#pragma unroll
    for (int it = 0; it < 8; it++) {
        int f = tid + it * 256;
        int r = f >> 5, c4 = (f & 31) << 2;
        float4 v = *(const float4*)&pbase[(size_t)r * PDx + c4];
        uint4 t;
        t.x = f2tf32(v.x); t.y = f2tf32(v.y); t.z = f2tf32(v.z); t.w = f2tf32(v.w);
        *(uint4*)&sp[r * SPS + c4] = t;
    }
    __syncthreads();

    {
        int r = tid >> 2, seg = tid & 3;
        const float* p = sp + r * SPS + seg * 32;
        float s = 0.f, ss = 0.f;
#pragma unroll
        for (int c = 0; c < 8; c++) {
            float4 v = *(const float4*)&p[c * 4];
            s  += v.x + v.y + v.z + v.w;
            ss += v.x * v.x + v.y * v.y + v.z * v.z + v.w * v.w;
        }
        s  += __shfl_xor_sync(~0u, s, 1);  ss += __shfl_xor_sync(~0u, ss, 1);
        s  += __shfl_xor_sync(~0u, s, 2);  ss += __shfl_xor_sync(~0u, ss, 2);
        if (seg == 0) {
            float m = s * (1.0f / PDx);
            smM[r] = m;
            smR[r] = rsqrtf(ss * (1.0f / PDx) - m * m + LN_EPS);
        }
    }
    __syncthreads();

    float c0 = 0.f, c1 = 0.f, c2 = 0.f, c3 = 0.f;
    const float* Ab = sp + (mt * 16 + lg) * SPS + lt;
#pragma unroll
    for (int ks = 0; ks < 16; ks++) {
        uint32_t a0 = __float_as_uint(Ab[ks * 8]);
        uint32_t a1 = __float_as_uint(Ab[ks * 8 + 8 * SPS]);
        uint32_t a2 = __float_as_uint(Ab[ks * 8 + 4]);
        uint32_t a3 = __float_as_uint(Ab[ks * 8 + 8 * SPS + 4]);
        mma_tf32(c0, c1, c2, c3, a0, a1, a2, a3, bfrag[2 * ks], bfrag[2 * ks + 1]);
    }

    {
        int row0 = mt * 16 + lg;
        int row1 = row0 + 8;
        int col  = nt * 8 + 2 * lt;
        const int* maskrow = mask + rowbase + j0;
        float r0 = smR[row0], m0 = smM[row0];
        float r1 = smR[row1], m1 = smM[row1];
        int mk0 = maskrow[row0], mk1 = maskrow[row1];
        float sh0 = sh_s[col], sh1 = sh_s[col + 1];
        float th0 = th_s[col], th1 = th_s[col + 1];
        float v00 = r0 * c0 - r0 * m0 * sh0 + th0;
        float v01 = r0 * c1 - r0 * m0 * sh1 + th1;
        float v10 = r1 * c2 - r1 * m1 * sh0 + th0;
        float v11 = r1 * c3 - r1 * m1 * sh1 + th1;
        if (mk0 == 0) { v00 = NEG_INFx; v01 = NEG_INFx; }
        if (mk1 == 0) { v10 = NEG_INFx; v11 = NEG_INFx; }
        outT[col * 64 + row0]       = v00;
        outT[(col + 1) * 64 + row0] = v01;
        outT[col * 64 + row1]       = v10;
        outT[(col + 1) * 64 + row1] = v11;
    }
    __syncthreads();

    {
        int h = tid >> 4, c = (tid & 15) << 2;
        float4 v = *(const float4*)&outT[h * 64 + c];
        *(float4*)&g_bias[(((size_t)(b * HHx + h)) * NNx + i) * NNx + j0 + c] = v;
    }
}

// ---------------- K5: attention, 12 rows/block; QK^T over transposed K ----------------
__global__ void k_attn() {
    __shared__ __align__(16) float S[12][NNx];    // 36864 B
    __shared__ __align__(16) u64 qp_s[6][DHx];    //  1536 B  {q_row0[d], q_row1[d]} per warp
    int i0 = blockIdx.x * 12;
    int h = blockIdx.y, b = blockIdx.z;
    int tid = threadIdx.x;
    int w = tid >> 5, lane = tid & 31;
    size_t bhbase = (size_t)(b * HHx + h) * NNx;

    // stage q pairs: idx -> (warp ww, d)
    if (tid < 192) {
        int ww = tid >> 5, d = tid & 31;
        float q0 = g_qh[(bhbase + i0 + 2 * ww) * DHx + d];
        float q1 = g_qh[(bhbase + i0 + 2 * ww + 1) * DHx + d];
        qp_s[ww][d] = pack2(q0, q1);
    }
    __syncthreads();

    const float scale = 0.17677669529663687f;   // 1/sqrt(32)
    int il0 = 2 * w, il1 = 2 * w + 1;
    int iA = i0 + il0, iB = i0 + il1;
    const float* b0row = g_bias + (bhbase + iA) * NNx;
    const float* b1row = g_bias + (bhbase + iB) * NNx;
    const float* kT = g_khT + (size_t)(b * HHx + h) * DHx * NNx;   // [d][j]

    // QK^T: lane owns 4 consecutive j per chunk; coalesced LDG.128 over j
    for (int ck = 0; ck < 6; ck++) {
        int jb = ck * 128 + lane * 4;
        u64 a0x = 0, a0y = 0, a1x = 0, a1y = 0;   // row0:{j0,j1},{j2,j3}; row1 same
#pragma unroll 8
        for (int d = 0; d < DHx; d++) {
            ulonglong2 k2 = *(const ulonglong2*)&kT[(size_t)d * NNx + jb];
            float2 q = up2(qp_s[w][d]);
            u64 q0s = splat2(q.x), q1s = splat2(q.y);
            ffma2(a0x, k2.x, q0s); ffma2(a0y, k2.y, q0s);
            ffma2(a1x, k2.x, q1s); ffma2(a1y, k2.y, q1s);
        }
        float4 bb0 = *(const float4*)&b0row[jb];
        float4 bb1 = *(const float4*)&b1row[jb];
        float2 s00 = up2(a0x), s01 = up2(a0y), s10 = up2(a1x), s11 = up2(a1y);
        float4 r0 = {s00.x * scale + bb0.x, s00.y * scale + bb0.y,
                     s01.x * scale + bb0.z, s01.y * scale + bb0.w};
        float4 r1 = {s10.x * scale + bb1.x, s10.y * scale + bb1.y,
                     s11.x * scale + bb1.z, s11.y * scale + bb1.w};
        *(float4*)&S[il0][jb] = r0;
        *(float4*)&S[il1][jb] = r1;
    }
    __syncwarp();

    // softmax (exp stored unnormalized, inv kept in regs)
    float inv0, inv1;
#pragma unroll
    for (int rr = 0; rr < 2; rr++) {
        float* Sr = (rr == 0) ? &S[il0][0] : &S[il1][0];
        float mx = -3.4e38f;
        for (int c = lane; c < NNx; c += 32) mx = fmaxf(mx, Sr[c]);
#pragma unroll
        for (int o = 16; o > 0; o >>= 1) mx = fmaxf(mx, __shfl_xor_sync(~0u, mx, o));
        float sum = 0.f;
        for (int c = lane; c < NNx; c += 32) {
            float e = __expf(Sr[c] - mx);
            Sr[c] = e;
            sum += e;
        }
#pragma unroll
        for (int o = 16; o > 0; o >>= 1) sum += __shfl_xor_sync(~0u, sum, o);
        if (rr == 0) inv0 = 1.0f / sum; else inv1 = 1.0f / sum;
    }
    __syncwarp();

    // AV: lane = (half, d-pair); half-warps split the j range
    int half = lane >> 4;
    int dp = (lane & 15) * 2;
    const float* vbase = g_vh + bhbase * DHx;
    float a00 = 0.f, a01 = 0.f, a10 = 0.f, a11 = 0.f;
    int jb = half * (NNx / 2);
    for (int jj = 0; jj < NNx / 2; jj += 4) {
        int j = jb + jj;
        float4 pA = *(const float4*)&S[il0][j];
        float4 pB = *(const float4*)&S[il1][j];
        const float* vp = vbase + (size_t)j * DHx + dp;
        float2 v0 = *(const float2*)(vp);
        float2 v1 = *(const float2*)(vp + 32);
        float2 v2 = *(const float2*)(vp + 64);
        float2 v3 = *(const float2*)(vp + 96);
        a00 += pA.x * v0.x + pA.y * v1.x + pA.z * v2.x + pA.w * v3.x;
        a01 += pA.x * v0.y + pA.y * v1.y + pA.z * v2.y + pA.w * v3.y;
        a10 += pB.x * v0.x + pB.y * v1.x + pB.z * v2.x + pB.w * v3.x;
        a11 += pB.x * v0.y + pB.y * v1.y + pB.z * v2.y + pB.w * v3.y;
    }
    a00 += __shfl_down_sync(~0u, a00, 16);
    a01 += __shfl_down_sync(~0u, a01, 16);
    a10 += __shfl_down_sync(~0u, a10, 16);
    a11 += __shfl_down_sync(~0u, a11, 16);

    if (half == 0) {
        size_t bnA = (size_t)b * NNx + iA;
        size_t bnB = (size_t)b * NNx + iB;
        float2 gA = *(const float2*)&g_qkvg[bnA * 2048 + 1536 + h * DHx + dp];
        float2 gB = *(const float2*)&g_qkvg[bnB * 2048 + 1536 + h * DHx + dp];
        float2 oA, oB;
        oA.x = a00 * inv0 * (1.0f / (1.0f + __expf(-gA.x)));
        oA.y = a01 * inv0 * (1.0f / (1.0f + __expf(-gA.y)));
        oB.x = a10 * inv1 * (1.0f / (1.0f + __expf(-gB.x)));
        oB.y = a11 * inv1 * (1.0f / (1.0f + __expf(-gB.y)));
        *(float2*)&g_og[bnA * INNERx + h * DHx + dp] = oA;
        *(float2*)&g_og[bnB * INNERx + h * DHx + dp] = oB;
    }
}

// ---------------- launch ----------------
extern "C" void kernel_launch(void* const* d_in, const int* in_sizes, int n_in,
                              void* d_out, int out_size) {
    const float* node = (const float*)d_in[0];
    const float* pair = (const float*)d_in[1];
    const int*   mask = (const int*)d_in[2];
    const float* nnw  = (const float*)d_in[3];
    const float* nnb  = (const float*)d_in[4];
    const float* qkvw = (const float*)d_in[5];
    const float* qkvb = (const float*)d_in[6];
    const float* gw   = (const float*)d_in[7];
    const float* gb   = (const float*)d_in[8];
    const float* qlw  = (const float*)d_in[9];
    const float* qlb  = (const float*)d_in[10];
    const float* klw  = (const float*)d_in[11];
    const float* klb  = (const float*)d_in[12];
    const float* pnw  = (const float*)d_in[13];
    const float* pnb  = (const float*)d_in[14];
    const float* bw   = (const float*)d_in[15];
    const float* ow   = (const float*)d_in[16];
    const float* ob   = (const float*)d_in[17];
    float* out = (float*)d_out;

    k_prep<<<1, 256>>>(bw, pnw, pnb);
    k_ln_node<<<BB * NNx, 256>>>(node, nnw, nnb);
    k_gemm_tc<0><<<dim3(2048 / 64, (BB * NNx) / 128), 256>>>(qkvw, gw, qkvb, gb, nullptr);
    k_lnqk<<<BB * NNx, 256>>>(qlw, qlb, klw, klb);
    k_pairbias<<<dim3(NNx / 64, NNx, BB), 256>>>(pair, mask);
    k_attn<<<dim3(NNx / 12, HHx, BB), 192>>>();
    k_gemm_tc<1><<<dim3(512 / 64, (BB * NNx) / 128), 256>>>(ow, ow, ob, ob, out);
}

// round 7
// speedup vs baseline: 1.6225x; 1.0795x over previous
#include <cuda_runtime.h>
#include <cstdint>

#define BB 2
#define NNx 768
#define DDx 512
#define HHx 16
#define DHx 32
#define INNERx 512
#define PDx 128
#define NEG_INFx -10000.0f
#define LN_EPS 1e-5f

typedef unsigned long long u64;

// ---------------- f32x2 packed-math helpers (exact fp32 semantics) ----------------
__device__ __forceinline__ void ffma2(u64& d, u64 a, u64 b) {
    asm("fma.rn.f32x2 %0, %1, %2, %0;" : "+l"(d) : "l"(a), "l"(b));
}
__device__ __forceinline__ float2 up2(u64 v) {
    float2 f;
    asm("mov.b64 {%0, %1}, %2;" : "=f"(f.x), "=f"(f.y) : "l"(v));
    return f;
}
__device__ __forceinline__ u64 pack2(float x, float y) {
    u64 r;
    asm("mov.b64 %0, {%1, %2};" : "=l"(r) : "f"(x), "f"(y));
    return r;
}
__device__ __forceinline__ u64 splat2(float x) {
    u64 r;
    asm("mov.b64 %0, {%1, %1};" : "=l"(r) : "f"(x));
    return r;
}
__device__ __forceinline__ uint32_t f2tf32(float f) {
    uint32_t r;
    asm("cvt.rna.tf32.f32 %0, %1;" : "=r"(r) : "f"(f));
    return r;
}
__device__ __forceinline__ void mma_tf32(float& c0, float& c1, float& c2, float& c3,
                                         uint32_t a0, uint32_t a1, uint32_t a2, uint32_t a3,
                                         uint32_t b0, uint32_t b1) {
    asm("mma.sync.aligned.m16n8k8.row.col.f32.tf32.tf32.f32 "
        "{%0,%1,%2,%3}, {%4,%5,%6,%7}, {%8,%9}, {%0,%1,%2,%3};"
        : "+f"(c0), "+f"(c1), "+f"(c2), "+f"(c3)
        : "r"(a0), "r"(a1), "r"(a2), "r"(a3), "r"(b0), "r"(b1));
}

// ---------------- scratch (static device memory: allowed) ----------------
__device__ float g_x[BB * NNx * DDx];
__device__ float g_qkvg[BB * NNx * 2048];                  // [q|k|v|g]
__device__ float g_qh[BB * HHx * NNx * DHx];               // q [b][h][n][d]
__device__ float g_khT[BB * HHx * DHx * NNx];              // k [b][h][d][n]  (transposed)
__device__ float g_vh[BB * HHx * NNx * DHx];               // v [b][h][n][d]
__device__ float g_bias[(size_t)BB * HHx * NNx * NNx];     // masked bias  75.5 MB
__device__ float g_og[BB * NNx * INNERx];
__device__ float g_Wt[HHx * PDx];                          // tf32-rounded W'[h][e]
__device__ float g_sh[HHx];
__device__ float g_th[HHx];

// ---------------- K0: fold pair-LN affine into projection weights ----------------
__global__ void k_prep(const float* __restrict__ bias_w,
                       const float* __restrict__ pnw,
                       const float* __restrict__ pnb) {
    int t = threadIdx.x;
    for (int idx = t; idx < HHx * PDx; idx += blockDim.x) {
        int h = idx >> 7, e = idx & 127;
        uint32_t tv = f2tf32(pnw[e] * bias_w[e * HHx + h]);
        g_Wt[idx] = __uint_as_float(tv);
    }
    if (t < HHx) {
        float s = 0.f, tt = 0.f;
        for (int e = 0; e < PDx; e++) {
            s  += pnw[e] * bias_w[e * HHx + t];
            tt += pnb[e] * bias_w[e * HHx + t];
        }
        g_sh[t] = s;
        g_th[t] = tt;
    }
}

// ---------------- K1: node LayerNorm ----------------
__global__ void k_ln_node(const float* __restrict__ nf,
                          const float* __restrict__ w,
                          const float* __restrict__ bp) {
    int row = blockIdx.x;
    const float* in = nf + (size_t)row * DDx;
    float s = 0.f, ss = 0.f;
    for (int c = threadIdx.x; c < DDx; c += 256) {
        float t = in[c];
        s += t; ss += t * t;
    }
#pragma unroll
    for (int o = 16; o > 0; o >>= 1) {
        s  += __shfl_xor_sync(~0u, s, o);
        ss += __shfl_xor_sync(~0u, ss, o);
    }
    __shared__ float red[16];
    int wid = threadIdx.x >> 5, lid = threadIdx.x & 31;
    if (lid == 0) { red[wid] = s; red[8 + wid] = ss; }
    __syncthreads();
    __shared__ float sm, sr;
    if (threadIdx.x == 0) {
        float S = 0.f, SS = 0.f;
        for (int i = 0; i < 8; i++) { S += red[i]; SS += red[8 + i]; }
        float m = S / DDx;
        sm = m;
        sr = rsqrtf(SS / DDx - m * m + LN_EPS);
    }
    __syncthreads();
    float m = sm, r = sr;
    for (int c = threadIdx.x; c < DDx; c += 256)
        g_x[(size_t)row * DDx + c] = (in[c] - m) * r * w[c] + bp[c];
}

// ---------------- K2/K6: dense GEMM on tensor pipe (tf32 mma, double-buffered) ----------------
#define AST 20
#define BST 72
template<int MODE>
__global__ void k_gemm_tc(const float* __restrict__ B1, const float* __restrict__ B2,
                          const float* __restrict__ bias1, const float* __restrict__ bias2,
                          float* __restrict__ Cext) {
    constexpr int LDC   = (MODE == 0) ? 2048 : 512;
    constexpr int SPLIT = (MODE == 0) ? 1536 : (1 << 30);
    constexpr int LD1   = (MODE == 0) ? 1536 : 512;
    constexpr int LD2   = 512;

    const float* A = (MODE == 0) ? g_x : g_og;
    float* C = (MODE == 0) ? g_qkvg : Cext;

    __shared__ __align__(16) float As[2][128 * AST];
    __shared__ __align__(16) float Bs[2][16 * BST];

    int bm = blockIdx.y * 128, bn = blockIdx.x * 64;
    int tid = threadIdx.x, w = tid >> 5, lane = tid & 31;
    int wm = w >> 1, wn = w & 1;
    int lg = lane >> 2, lt = lane & 3;

    float acc[2][4][4] = {};

    int mS = tid >> 1, segS = (tid & 1) * 8;
    int kS = tid >> 4, nS = (tid & 15) * 4;
    int ncol = bn + nS;
    const float* bsrc = (ncol < SPLIT) ? (B1 + ncol) : (B2 + (ncol - SPLIT));
    int ldb = (ncol < SPLIT) ? LD1 : LD2;
    const float* aS = A + (size_t)(bm + mS) * 512 + segS;

    float4 ra0, ra1, rb;
    // prologue: load k0=0
    ra0 = *(const float4*)(aS);
    ra1 = *(const float4*)(aS + 4);
    rb  = *(const float4*)&bsrc[(size_t)kS * ldb];
    {
        uint4 t0 = {f2tf32(ra0.x), f2tf32(ra0.y), f2tf32(ra0.z), f2tf32(ra0.w)};
        uint4 t1 = {f2tf32(ra1.x), f2tf32(ra1.y), f2tf32(ra1.z), f2tf32(ra1.w)};
        uint4 tb = {f2tf32(rb.x),  f2tf32(rb.y),  f2tf32(rb.z),  f2tf32(rb.w)};
        *(uint4*)&As[0][mS * AST + segS]     = t0;
        *(uint4*)&As[0][mS * AST + segS + 4] = t1;
        *(uint4*)&Bs[0][kS * BST + nS]       = tb;
    }
    __syncthreads();

    for (int k0 = 0; k0 < 512; k0 += 16) {
        int cur = (k0 >> 4) & 1;
        bool more = (k0 + 16) < 512;
        if (more) {
            ra0 = *(const float4*)(aS + k0 + 16);
            ra1 = *(const float4*)(aS + k0 + 20);
            rb  = *(const float4*)&bsrc[(size_t)(k0 + 16 + kS) * ldb];
        }

#pragma unroll
        for (int ks = 0; ks < 2; ks++) {
            uint32_t af[2][4];
            const float* ab = &As[cur][(wm * 32 + lg) * AST + ks * 8 + lt];
#pragma unroll
            for (int mf = 0; mf < 2; mf++) {
                const float* a = ab + mf * 16 * AST;
                af[mf][0] = __float_as_uint(a[0]);
                af[mf][1] = __float_as_uint(a[8 * AST]);
                af[mf][2] = __float_as_uint(a[4]);
                af[mf][3] = __float_as_uint(a[8 * AST + 4]);
            }
            uint32_t bf[4][2];
            const float* bb = &Bs[cur][(ks * 8 + lt) * BST + wn * 32 + lg];
#pragma unroll
            for (int nf = 0; nf < 4; nf++) {
                bf[nf][0] = __float_as_uint(bb[nf * 8]);
                bf[nf][1] = __float_as_uint(bb[4 * BST + nf * 8]);
            }
#pragma unroll
            for (int mf = 0; mf < 2; mf++)
#pragma unroll
                for (int nf = 0; nf < 4; nf++)
                    mma_tf32(acc[mf][nf][0], acc[mf][nf][1], acc[mf][nf][2], acc[mf][nf][3],
                             af[mf][0], af[mf][1], af[mf][2], af[mf][3],
                             bf[nf][0], bf[nf][1]);
        }

        if (more) {
            int nxt = cur ^ 1;
            uint4 t0 = {f2tf32(ra0.x), f2tf32(ra0.y), f2tf32(ra0.z), f2tf32(ra0.w)};
            uint4 t1 = {f2tf32(ra1.x), f2tf32(ra1.y), f2tf32(ra1.z), f2tf32(ra1.w)};
            uint4 tb = {f2tf32(rb.x),  f2tf32(rb.y),  f2tf32(rb.z),  f2tf32(rb.w)};
            *(uint4*)&As[nxt][mS * AST + segS]     = t0;
            *(uint4*)&As[nxt][mS * AST + segS + 4] = t1;
            *(uint4*)&Bs[nxt][kS * BST + nS]       = tb;
        }
        __syncthreads();
    }

#pragma unroll
    for (int mf = 0; mf < 2; mf++) {
#pragma unroll
        for (int nf = 0; nf < 4; nf++) {
            int r = bm + wm * 32 + mf * 16 + lg;
            int c = bn + wn * 32 + nf * 8 + 2 * lt;
            float bi0 = (c < SPLIT) ? bias1[c] : bias2[c - SPLIT];
            float bi1 = (c + 1 < SPLIT) ? bias1[c + 1] : bias2[c + 1 - SPLIT];
            float2 v0 = {acc[mf][nf][0] + bi0, acc[mf][nf][1] + bi1};
            float2 v1 = {acc[mf][nf][2] + bi0, acc[mf][nf][3] + bi1};
            *(float2*)&C[(size_t)r * LDC + c]       = v0;
            *(float2*)&C[(size_t)(r + 8) * LDC + c] = v1;
        }
    }
}

// ---------------- K3: q/k LN over INNER; q,v head-major, k TRANSPOSED ----------------
__global__ void k_lnqk(const float* __restrict__ qw, const float* __restrict__ qb,
                       const float* __restrict__ kw, const float* __restrict__ kb) {
    int bn = blockIdx.x;
    const float* row = g_qkvg + (size_t)bn * 2048;
    int b = bn / NNx, nn = bn % NNx;
    float s1 = 0.f, ss1 = 0.f, s2 = 0.f, ss2 = 0.f;
    for (int c = threadIdx.x; c < 512; c += 256) {
        float a = row[c], b2 = row[512 + c];
        s1 += a; ss1 += a * a; s2 += b2; ss2 += b2 * b2;
    }
#pragma unroll
    for (int o = 16; o > 0; o >>= 1) {
        s1  += __shfl_xor_sync(~0u, s1, o);  ss1 += __shfl_xor_sync(~0u, ss1, o);
        s2  += __shfl_xor_sync(~0u, s2, o);  ss2 += __shfl_xor_sync(~0u, ss2, o);
    }
    __shared__ float red[4][8];
    int w = threadIdx.x >> 5, lane = threadIdx.x & 31;
    if (lane == 0) { red[0][w] = s1; red[1][w] = ss1; red[2][w] = s2; red[3][w] = ss2; }
    __syncthreads();
    __shared__ float st[4];
    if (threadIdx.x == 0) {
        float a = 0.f, bb = 0.f, c = 0.f, d = 0.f;
        for (int i = 0; i < 8; i++) { a += red[0][i]; bb += red[1][i]; c += red[2][i]; d += red[3][i]; }
        float m1 = a / 512.f, m2 = c / 512.f;
        st[0] = m1; st[1] = rsqrtf(bb / 512.f - m1 * m1 + LN_EPS);
        st[2] = m2; st[3] = rsqrtf(d / 512.f - m2 * m2 + LN_EPS);
    }
    __syncthreads();
    float m1 = st[0], r1 = st[1], m2 = st[2], r2 = st[3];
    for (int c = threadIdx.x; c < 512; c += 256) {
        int h = c >> 5, d = c & 31;
        size_t oidx  = (((size_t)(b * HHx + h)) * NNx + nn) * DHx + d;     // [b][h][n][d]
        size_t oidxT = (((size_t)(b * HHx + h)) * DHx + d) * NNx + nn;     // [b][h][d][n]
        g_qh[oidx]   = (row[c]       - m1) * r1 * qw[c] + qb[c];
        g_khT[oidxT] = (row[512 + c] - m2) * r2 * kw[c] + kb[c];
        g_vh[oidx]   = row[1024 + c];
    }
}

// ---------------- K4: pair bias via tf32 mma.sync (LN folded, W in registers) ----------------
#define SPS 132
__global__ void k_pairbias(const float* __restrict__ pair, const int* __restrict__ mask) {
    __shared__ __align__(16) float sp[64 * SPS];
    __shared__ float outT[HHx * 64];
    __shared__ float smM[64], smR[64];
    __shared__ float sh_s[HHx], th_s[HHx];

    int tid = threadIdx.x, w = tid >> 5, lane = tid & 31;
    int j0 = blockIdx.x * 64;
    int i  = blockIdx.y, b = blockIdx.z;
    size_t rowbase = ((size_t)(b * NNx + i)) * NNx;

    int mt = w >> 1, nt = w & 1;
    int lg = lane >> 2, lt = lane & 3;

    uint32_t bfrag[32];
    {
        const float* Wb = g_Wt + (nt * 8 + lg) * PDx + lt;
#pragma unroll
        for (int ks = 0; ks < 16; ks++) {
            bfrag[2 * ks]     = __float_as_uint(Wb[ks * 8]);
            bfrag[2 * ks + 1] = __float_as_uint(Wb[ks * 8 + 4]);
        }
    }
    if (tid < HHx) { sh_s[tid] = g_sh[tid]; th_s[tid] = g_th[tid]; }

    const float* pbase = pair + (rowbase + j0) * (size_t)PDx;
#pragma unroll
    for (int it = 0; it < 8; it++) {
        int f = tid + it * 256;
        int r = f >> 5, c4 = (f & 31) << 2;
        float4 v = *(const float4*)&pbase[(size_t)r * PDx + c4];
        uint4 t;
        t.x = f2tf32(v.x); t.y = f2tf32(v.y); t.z = f2tf32(v.z); t.w = f2tf32(v.w);
        *(uint4*)&sp[r * SPS + c4] = t;
    }
    __syncthreads();

    {
        int r = tid >> 2, seg = tid & 3;
        const float* p = sp + r * SPS + seg * 32;
        float s = 0.f, ss = 0.f;
#pragma unroll
        for (int c = 0; c < 8; c++) {
            float4 v = *(const float4*)&p[c * 4];
            s  += v.x + v.y + v.z + v.w;
            ss += v.x * v.x + v.y * v.y + v.z * v.z + v.w * v.w;
        }
        s  += __shfl_xor_sync(~0u, s, 1);  ss += __shfl_xor_sync(~0u, ss, 1);
        s  += __shfl_xor_sync(~0u, s, 2);  ss += __shfl_xor_sync(~0u, ss, 2);
        if (seg == 0) {
            float m = s * (1.0f / PDx);
            smM[r] = m;
            smR[r] = rsqrtf(ss * (1.0f / PDx) - m * m + LN_EPS);
        }
    }
    __syncthreads();

    float c0 = 0.f, c1 = 0.f, c2 = 0.f, c3 = 0.f;
    const float* Ab = sp + (mt * 16 + lg) * SPS + lt;
#pragma unroll
    for (int ks = 0; ks < 16; ks++) {
        uint32_t a0 = __float_as_uint(Ab[ks * 8]);
        uint32_t a1 = __float_as_uint(Ab[ks * 8 + 8 * SPS]);
        uint32_t a2 = __float_as_uint(Ab[ks * 8 + 4]);
        uint32_t a3 = __float_as_uint(Ab[ks * 8 + 8 * SPS + 4]);
        mma_tf32(c0, c1, c2, c3, a0, a1, a2, a3, bfrag[2 * ks], bfrag[2 * ks + 1]);
    }

    {
        int row0 = mt * 16 + lg;
        int row1 = row0 + 8;
        int col  = nt * 8 + 2 * lt;
        const int* maskrow = mask + rowbase + j0;
        float r0 = smR[row0], m0 = smM[row0];
        float r1 = smR[row1], m1 = smM[row1];
        int mk0 = maskrow[row0], mk1 = maskrow[row1];
        float sh0 = sh_s[col], sh1 = sh_s[col + 1];
        float th0 = th_s[col], th1 = th_s[col + 1];
        float v00 = r0 * c0 - r0 * m0 * sh0 + th0;
        float v01 = r0 * c1 - r0 * m0 * sh1 + th1;
        float v10 = r1 * c2 - r1 * m1 * sh0 + th0;
        float v11 = r1 * c3 - r1 * m1 * sh1 + th1;
        if (mk0 == 0) { v00 = NEG_INFx; v01 = NEG_INFx; }
        if (mk1 == 0) { v10 = NEG_INFx; v11 = NEG_INFx; }
        outT[col * 64 + row0]       = v00;
        outT[(col + 1) * 64 + row0] = v01;
        outT[col * 64 + row1]       = v10;
        outT[(col + 1) * 64 + row1] = v11;
    }
    __syncthreads();

    {
        int h = tid >> 4, c = (tid & 15) << 2;
        float4 v = *(const float4*)&outT[h * 64 + c];
        *(float4*)&g_bias[(((size_t)(b * HHx + h)) * NNx + i) * NNx + j0 + c] = v;
    }
}

// ---------------- K5: attention, 12 rows/block; QK^T over transposed K ----------------
__global__ void k_attn() {
    __shared__ __align__(16) float S[12][NNx];
    __shared__ __align__(16) u64 qp_s[6][DHx];
    int i0 = blockIdx.x * 12;
    int h = blockIdx.y, b = blockIdx.z;
    int tid = threadIdx.x;
    int w = tid >> 5, lane = tid & 31;
    size_t bhbase = (size_t)(b * HHx + h) * NNx;

    if (tid < 192) {
        int ww = tid >> 5, d = tid & 31;
        float q0 = g_qh[(bhbase + i0 + 2 * ww) * DHx + d];
        float q1 = g_qh[(bhbase + i0 + 2 * ww + 1) * DHx + d];
        qp_s[ww][d] = pack2(q0, q1);
    }
    __syncthreads();

    const float scale = 0.17677669529663687f;
    int il0 = 2 * w, il1 = 2 * w + 1;
    int iA = i0 + il0, iB = i0 + il1;
    const float* b0row = g_bias + (bhbase + iA) * NNx;
    const float* b1row = g_bias + (bhbase + iB) * NNx;
    const float* kT = g_khT + (size_t)(b * HHx + h) * DHx * NNx;

    for (int ck = 0; ck < 6; ck++) {
        int jb = ck * 128 + lane * 4;
        u64 a0x = 0, a0y = 0, a1x = 0, a1y = 0;
#pragma unroll 8
        for (int d = 0; d < DHx; d++) {
            ulonglong2 k2 = *(const ulonglong2*)&kT[(size_t)d * NNx + jb];
            float2 q = up2(qp_s[w][d]);
            u64 q0s = splat2(q.x), q1s = splat2(q.y);
            ffma2(a0x, k2.x, q0s); ffma2(a0y, k2.y, q0s);
            ffma2(a1x, k2.x, q1s); ffma2(a1y, k2.y, q1s);
        }
        float4 bb0 = *(const float4*)&b0row[jb];
        float4 bb1 = *(const float4*)&b1row[jb];
        float2 s00 = up2(a0x), s01 = up2(a0y), s10 = up2(a1x), s11 = up2(a1y);
        float4 r0 = {s00.x * scale + bb0.x, s00.y * scale + bb0.y,
                     s01.x * scale + bb0.z, s01.y * scale + bb0.w};
        float4 r1 = {s10.x * scale + bb1.x, s10.y * scale + bb1.y,
                     s11.x * scale + bb1.z, s11.y * scale + bb1.w};
        *(float4*)&S[il0][jb] = r0;
        *(float4*)&S[il1][jb] = r1;
    }
    __syncwarp();

    float inv0, inv1;
#pragma unroll
    for (int rr = 0; rr < 2; rr++) {
        float* Sr = (rr == 0) ? &S[il0][0] : &S[il1][0];
        float mx = -3.4e38f;
        for (int c = lane; c < NNx; c += 32) mx = fmaxf(mx, Sr[c]);
#pragma unroll
        for (int o = 16; o > 0; o >>= 1) mx = fmaxf(mx, __shfl_xor_sync(~0u, mx, o));
        float sum = 0.f;
        for (int c = lane; c < NNx; c += 32) {
            float e = __expf(Sr[c] - mx);
            Sr[c] = e;
            sum += e;
        }
#pragma unroll
        for (int o = 16; o > 0; o >>= 1) sum += __shfl_xor_sync(~0u, sum, o);
        if (rr == 0) inv0 = 1.0f / sum; else inv1 = 1.0f / sum;
    }
    __syncwarp();

    int half = lane >> 4;
    int dp = (lane & 15) * 2;
    const float* vbase = g_vh + bhbase * DHx;
    float a00 = 0.f, a01 = 0.f, a10 = 0.f, a11 = 0.f;
    int jb = half * (NNx / 2);
    for (int jj = 0; jj < NNx / 2; jj += 4) {
        int j = jb + jj;
        float4 pA = *(const float4*)&S[il0][j];
        float4 pB = *(const float4*)&S[il1][j];
        const float* vp = vbase + (size_t)j * DHx + dp;
        float2 v0 = *(const float2*)(vp);
        float2 v1 = *(const float2*)(vp + 32);
        float2 v2 = *(const float2*)(vp + 64);
        float2 v3 = *(const float2*)(vp + 96);
        a00 += pA.x * v0.x + pA.y * v1.x + pA.z * v2.x + pA.w * v3.x;
        a01 += pA.x * v0.y + pA.y * v1.y + pA.z * v2.y + pA.w * v3.y;
        a10 += pB.x * v0.x + pB.y * v1.x + pB.z * v2.x + pB.w * v3.x;
        a11 += pB.x * v0.y + pB.y * v1.y + pB.z * v2.y + pB.w * v3.y;
    }
    a00 += __shfl_down_sync(~0u, a00, 16);
    a01 += __shfl_down_sync(~0u, a01, 16);
    a10 += __shfl_down_sync(~0u, a10, 16);
    a11 += __shfl_down_sync(~0u, a11, 16);

    if (half == 0) {
        size_t bnA = (size_t)b * NNx + iA;
        size_t bnB = (size_t)b * NNx + iB;
        float2 gA = *(const float2*)&g_qkvg[bnA * 2048 + 1536 + h * DHx + dp];
        float2 gB = *(const float2*)&g_qkvg[bnB * 2048 + 1536 + h * DHx + dp];
        float2 oA, oB;
        oA.x = a00 * inv0 * (1.0f / (1.0f + __expf(-gA.x)));
        oA.y = a01 * inv0 * (1.0f / (1.0f + __expf(-gA.y)));
        oB.x = a10 * inv1 * (1.0f / (1.0f + __expf(-gB.x)));
        oB.y = a11 * inv1 * (1.0f / (1.0f + __expf(-gB.y)));
        *(float2*)&g_og[bnA * INNERx + h * DHx + dp] = oA;
        *(float2*)&g_og[bnB * INNERx + h * DHx + dp] = oB;
    }
}

// ---------------- launch ----------------
// NOTE: k_pairbias depends only on k_prep + inputs, so it is hoisted to the
// 4th launch slot (the one ncu's -s/-c window captures) to get its profile.
extern "C" void kernel_launch(void* const* d_in, const int* in_sizes, int n_in,
                              void* d_out, int out_size) {
    const float* node = (const float*)d_in[0];
    const float* pair = (const float*)d_in[1];
    const int*   mask = (const int*)d_in[2];
    const float* nnw  = (const float*)d_in[3];
    const float* nnb  = (const float*)d_in[4];
    const float* qkvw = (const float*)d_in[5];
    const float* qkvb = (const float*)d_in[6];
    const float* gw   = (const float*)d_in[7];
    const float* gb   = (const float*)d_in[8];
    const float* qlw  = (const float*)d_in[9];
    const float* qlb  = (const float*)d_in[10];
    const float* klw  = (const float*)d_in[11];
    const float* klb  = (const float*)d_in[12];
    const float* pnw  = (const float*)d_in[13];
    const float* pnb  = (const float*)d_in[14];
    const float* bw   = (const float*)d_in[15];
    const float* ow   = (const float*)d_in[16];
    const float* ob   = (const float*)d_in[17];
    float* out = (float*)d_out;

    k_prep<<<1, 256>>>(bw, pnw, pnb);
    k_ln_node<<<BB * NNx, 256>>>(node, nnw, nnb);
    k_gemm_tc<0><<<dim3(2048 / 64, (BB * NNx) / 128), 256>>>(qkvw, gw, qkvb, gb, nullptr);
    k_pairbias<<<dim3(NNx / 64, NNx, BB), 256>>>(pair, mask);
    k_lnqk<<<BB * NNx, 256>>>(qlw, qlb, klw, klb);
    k_attn<<<dim3(NNx / 12, HHx, BB), 192>>>();
    k_gemm_tc<1><<<dim3(512 / 64, (BB * NNx) / 128), 256>>>(ow, ow, ob, ob, out);
}

// round 8
// speedup vs baseline: 2.2879x; 1.4101x over previous
#include <cuda_runtime.h>
#include <cstdint>

#define BB 2
#define NNx 768
#define DDx 512
#define HHx 16
#define DHx 32
#define INNERx 512
#define PDx 128
#define NEG_INFx -10000.0f
#define LN_EPS 1e-5f

typedef unsigned long long u64;

// ---------------- f32x2 packed-math helpers (exact fp32 semantics) ----------------
__device__ __forceinline__ void ffma2(u64& d, u64 a, u64 b) {
    asm("fma.rn.f32x2 %0, %1, %2, %0;" : "+l"(d) : "l"(a), "l"(b));
}
__device__ __forceinline__ float2 up2(u64 v) {
    float2 f;
    asm("mov.b64 {%0, %1}, %2;" : "=f"(f.x), "=f"(f.y) : "l"(v));
    return f;
}
__device__ __forceinline__ u64 pack2(float x, float y) {
    u64 r;
    asm("mov.b64 %0, {%1, %2};" : "=l"(r) : "f"(x), "f"(y));
    return r;
}
__device__ __forceinline__ u64 splat2(float x) {
    u64 r;
    asm("mov.b64 %0, {%1, %1};" : "=l"(r) : "f"(x));
    return r;
}
__device__ __forceinline__ uint32_t f2tf32(float f) {
    uint32_t r;
    asm("cvt.rna.tf32.f32 %0, %1;" : "=r"(r) : "f"(f));
    return r;
}
__device__ __forceinline__ void mma_tf32(float& c0, float& c1, float& c2, float& c3,
                                         uint32_t a0, uint32_t a1, uint32_t a2, uint32_t a3,
                                         uint32_t b0, uint32_t b1) {
    asm("mma.sync.aligned.m16n8k8.row.col.f32.tf32.tf32.f32 "
        "{%0,%1,%2,%3}, {%4,%5,%6,%7}, {%8,%9}, {%0,%1,%2,%3};"
        : "+f"(c0), "+f"(c1), "+f"(c2), "+f"(c3)
        : "r"(a0), "r"(a1), "r"(a2), "r"(a3), "r"(b0), "r"(b1));
}

// ---------------- scratch (static device memory: allowed) ----------------
__device__ float g_x[BB * NNx * DDx];
__device__ float g_qkvg[BB * NNx * 2048];                  // [q|k|v|g]
__device__ float g_qh[BB * HHx * NNx * DHx];               // q [b][h][n][d]
__device__ float g_khT[BB * HHx * DHx * NNx];              // k [b][h][d][n]  (transposed)
__device__ float g_vh[BB * HHx * NNx * DHx];               // v [b][h][n][d]
__device__ float g_bias[(size_t)BB * HHx * NNx * NNx];     // masked bias  75.5 MB
__device__ float g_og[BB * NNx * INNERx];
__device__ float g_Wt[HHx * PDx];                          // tf32-rounded W'[h][e]
__device__ float g_sh[HHx];
__device__ float g_th[HHx];

// ---------------- K0: fold pair-LN affine into projection weights ----------------
__global__ void k_prep(const float* __restrict__ bias_w,
                       const float* __restrict__ pnw,
                       const float* __restrict__ pnb) {
    int t = threadIdx.x;
    for (int idx = t; idx < HHx * PDx; idx += blockDim.x) {
        int h = idx >> 7, e = idx & 127;
        uint32_t tv = f2tf32(pnw[e] * bias_w[e * HHx + h]);
        g_Wt[idx] = __uint_as_float(tv);
    }
    if (t < HHx) {
        float s = 0.f, tt = 0.f;
        for (int e = 0; e < PDx; e++) {
            s  += pnw[e] * bias_w[e * HHx + t];
            tt += pnb[e] * bias_w[e * HHx + t];
        }
        g_sh[t] = s;
        g_th[t] = tt;
    }
}

// ---------------- K1: node LayerNorm ----------------
__global__ void k_ln_node(const float* __restrict__ nf,
                          const float* __restrict__ w,
                          const float* __restrict__ bp) {
    int row = blockIdx.x;
    const float* in = nf + (size_t)row * DDx;
    float s = 0.f, ss = 0.f;
    for (int c = threadIdx.x; c < DDx; c += 256) {
        float t = in[c];
        s += t; ss += t * t;
    }
#pragma unroll
    for (int o = 16; o > 0; o >>= 1) {
        s  += __shfl_xor_sync(~0u, s, o);
        ss += __shfl_xor_sync(~0u, ss, o);
    }
    __shared__ float red[16];
    int wid = threadIdx.x >> 5, lid = threadIdx.x & 31;
    if (lid == 0) { red[wid] = s; red[8 + wid] = ss; }
    __syncthreads();
    __shared__ float sm, sr;
    if (threadIdx.x == 0) {
        float S = 0.f, SS = 0.f;
        for (int i = 0; i < 8; i++) { S += red[i]; SS += red[8 + i]; }
        float m = S / DDx;
        sm = m;
        sr = rsqrtf(SS / DDx - m * m + LN_EPS);
    }
    __syncthreads();
    float m = sm, r = sr;
    for (int c = threadIdx.x; c < DDx; c += 256)
        g_x[(size_t)row * DDx + c] = (in[c] - m) * r * w[c] + bp[c];
}

// ---------------- K2/K6: dense GEMM on tensor pipe (tf32 mma, double-buffered) ----------------
#define AST 20
#define BST 72
template<int MODE>
__global__ void k_gemm_tc(const float* __restrict__ B1, const float* __restrict__ B2,
                          const float* __restrict__ bias1, const float* __restrict__ bias2,
                          float* __restrict__ Cext) {
    constexpr int LDC   = (MODE == 0) ? 2048 : 512;
    constexpr int SPLIT = (MODE == 0) ? 1536 : (1 << 30);
    constexpr int LD1   = (MODE == 0) ? 1536 : 512;
    constexpr int LD2   = 512;

    const float* A = (MODE == 0) ? g_x : g_og;
    float* C = (MODE == 0) ? g_qkvg : Cext;

    __shared__ __align__(16) float As[2][128 * AST];
    __shared__ __align__(16) float Bs[2][16 * BST];

    int bm = blockIdx.y * 128, bn = blockIdx.x * 64;
    int tid = threadIdx.x, w = tid >> 5, lane = tid & 31;
    int wm = w >> 1, wn = w & 1;
    int lg = lane >> 2, lt = lane & 3;

    float acc[2][4][4] = {};

    int mS = tid >> 1, segS = (tid & 1) * 8;
    int kS = tid >> 4, nS = (tid & 15) * 4;
    int ncol = bn + nS;
    const float* bsrc = (ncol < SPLIT) ? (B1 + ncol) : (B2 + (ncol - SPLIT));
    int ldb = (ncol < SPLIT) ? LD1 : LD2;
    const float* aS = A + (size_t)(bm + mS) * 512 + segS;

    float4 ra0, ra1, rb;
    ra0 = *(const float4*)(aS);
    ra1 = *(const float4*)(aS + 4);
    rb  = *(const float4*)&bsrc[(size_t)kS * ldb];
    {
        uint4 t0 = {f2tf32(ra0.x), f2tf32(ra0.y), f2tf32(ra0.z), f2tf32(ra0.w)};
        uint4 t1 = {f2tf32(ra1.x), f2tf32(ra1.y), f2tf32(ra1.z), f2tf32(ra1.w)};
        uint4 tb = {f2tf32(rb.x),  f2tf32(rb.y),  f2tf32(rb.z),  f2tf32(rb.w)};
        *(uint4*)&As[0][mS * AST + segS]     = t0;
        *(uint4*)&As[0][mS * AST + segS + 4] = t1;
        *(uint4*)&Bs[0][kS * BST + nS]       = tb;
    }
    __syncthreads();

    for (int k0 = 0; k0 < 512; k0 += 16) {
        int cur = (k0 >> 4) & 1;
        bool more = (k0 + 16) < 512;
        if (more) {
            ra0 = *(const float4*)(aS + k0 + 16);
            ra1 = *(const float4*)(aS + k0 + 20);
            rb  = *(const float4*)&bsrc[(size_t)(k0 + 16 + kS) * ldb];
        }

#pragma unroll
        for (int ks = 0; ks < 2; ks++) {
            uint32_t af[2][4];
            const float* ab = &As[cur][(wm * 32 + lg) * AST + ks * 8 + lt];
#pragma unroll
            for (int mf = 0; mf < 2; mf++) {
                const float* a = ab + mf * 16 * AST;
                af[mf][0] = __float_as_uint(a[0]);
                af[mf][1] = __float_as_uint(a[8 * AST]);
                af[mf][2] = __float_as_uint(a[4]);
                af[mf][3] = __float_as_uint(a[8 * AST + 4]);
            }
            uint32_t bf[4][2];
            const float* bb = &Bs[cur][(ks * 8 + lt) * BST + wn * 32 + lg];
#pragma unroll
            for (int nf = 0; nf < 4; nf++) {
                bf[nf][0] = __float_as_uint(bb[nf * 8]);
                bf[nf][1] = __float_as_uint(bb[4 * BST + nf * 8]);
            }
#pragma unroll
            for (int mf = 0; mf < 2; mf++)
#pragma unroll
                for (int nf = 0; nf < 4; nf++)
                    mma_tf32(acc[mf][nf][0], acc[mf][nf][1], acc[mf][nf][2], acc[mf][nf][3],
                             af[mf][0], af[mf][1], af[mf][2], af[mf][3],
                             bf[nf][0], bf[nf][1]);
        }

        if (more) {
            int nxt = cur ^ 1;
            uint4 t0 = {f2tf32(ra0.x), f2tf32(ra0.y), f2tf32(ra0.z), f2tf32(ra0.w)};
            uint4 t1 = {f2tf32(ra1.x), f2tf32(ra1.y), f2tf32(ra1.z), f2tf32(ra1.w)};
            uint4 tb = {f2tf32(rb.x),  f2tf32(rb.y),  f2tf32(rb.z),  f2tf32(rb.w)};
            *(uint4*)&As[nxt][mS * AST + segS]     = t0;
            *(uint4*)&As[nxt][mS * AST + segS + 4] = t1;
            *(uint4*)&Bs[nxt][kS * BST + nS]       = tb;
        }
        __syncthreads();
    }

#pragma unroll
    for (int mf = 0; mf < 2; mf++) {
#pragma unroll
        for (int nf = 0; nf < 4; nf++) {
            int r = bm + wm * 32 + mf * 16 + lg;
            int c = bn + wn * 32 + nf * 8 + 2 * lt;
            float bi0 = (c < SPLIT) ? bias1[c] : bias2[c - SPLIT];
            float bi1 = (c + 1 < SPLIT) ? bias1[c + 1] : bias2[c + 1 - SPLIT];
            float2 v0 = {acc[mf][nf][0] + bi0, acc[mf][nf][1] + bi1};
            float2 v1 = {acc[mf][nf][2] + bi0, acc[mf][nf][3] + bi1};
            *(float2*)&C[(size_t)r * LDC + c]       = v0;
            *(float2*)&C[(size_t)(r + 8) * LDC + c] = v1;
        }
    }
}

// ---------------- K3: q/k LN over INNER; q,v head-major, k TRANSPOSED ----------------
__global__ void k_lnqk(const float* __restrict__ qw, const float* __restrict__ qb,
                       const float* __restrict__ kw, const float* __restrict__ kb) {
    int bn = blockIdx.x;
    const float* row = g_qkvg + (size_t)bn * 2048;
    int b = bn / NNx, nn = bn % NNx;
    float s1 = 0.f, ss1 = 0.f, s2 = 0.f, ss2 = 0.f;
    for (int c = threadIdx.x; c < 512; c += 256) {
        float a = row[c], b2 = row[512 + c];
        s1 += a; ss1 += a * a; s2 += b2; ss2 += b2 * b2;
    }
#pragma unroll
    for (int o = 16; o > 0; o >>= 1) {
        s1  += __shfl_xor_sync(~0u, s1, o);  ss1 += __shfl_xor_sync(~0u, ss1, o);
        s2  += __shfl_xor_sync(~0u, s2, o);  ss2 += __shfl_xor_sync(~0u, ss2, o);
    }
    __shared__ float red[4][8];
    int w = threadIdx.x >> 5, lane = threadIdx.x & 31;
    if (lane == 0) { red[0][w] = s1; red[1][w] = ss1; red[2][w] = s2; red[3][w] = ss2; }
    __syncthreads();
    __shared__ float st[4];
    if (threadIdx.x == 0) {
        float a = 0.f, bb = 0.f, c = 0.f, d = 0.f;
        for (int i = 0; i < 8; i++) { a += red[0][i]; bb += red[1][i]; c += red[2][i]; d += red[3][i]; }
        float m1 = a / 512.f, m2 = c / 512.f;
        st[0] = m1; st[1] = rsqrtf(bb / 512.f - m1 * m1 + LN_EPS);
        st[2] = m2; st[3] = rsqrtf(d / 512.f - m2 * m2 + LN_EPS);
    }
    __syncthreads();
    float m1 = st[0], r1 = st[1], m2 = st[2], r2 = st[3];
    for (int c = threadIdx.x; c < 512; c += 256) {
        int h = c >> 5, d = c & 31;
        size_t oidx  = (((size_t)(b * HHx + h)) * NNx + nn) * DHx + d;     // [b][h][n][d]
        size_t oidxT = (((size_t)(b * HHx + h)) * DHx + d) * NNx + nn;     // [b][h][d][n]
        g_qh[oidx]   = (row[c]       - m1) * r1 * qw[c] + qb[c];
        g_khT[oidxT] = (row[512 + c] - m2) * r2 * kw[c] + kb[c];
        g_vh[oidx]   = row[1024 + c];
    }
}

// ---------------- K4: pair bias — persistent, B-in-regs, stats-from-fragments ----------------
// Tile: 128 j of one (b,i). 8 warps, warp w owns m-tile rows [16w,16w+16), computes all 16 h.
// B fragments (both h-halves, all 16 k-steps) loaded ONCE per kernel into registers.
// Row stats accumulated from the A fragments themselves; combined with 8 shfls in the
// lt-quad -> land exactly in the lanes holding those C fragments. Direct STG epilogue.
#define SPS 132
#define PB_TILES (BB * NNx * 6)            // 9216
#define PB_SMEM  (128 * SPS * 4)           // 67584 B
__global__ __launch_bounds__(256, 2) void k_pairbias(const float* __restrict__ pair,
                                                     const int* __restrict__ mask) {
    extern __shared__ __align__(16) float sp[];   // [128][SPS] tf32-rounded p tile

    int tid = threadIdx.x, w = tid >> 5, lane = tid & 31;
    int lg = lane >> 2, lt = lane & 3;
    int r0 = w * 16 + lg;                  // thread's m-frag rows: r0, r0+8

    // B fragments for all 16 k-steps, both h-halves: resident in regs all kernel.
    uint32_t blo[32], bhi[32];
#pragma unroll
    for (int ks = 0; ks < 16; ks++) {
        blo[2 * ks]     = __float_as_uint(g_Wt[lg * PDx + ks * 8 + lt]);
        blo[2 * ks + 1] = __float_as_uint(g_Wt[lg * PDx + ks * 8 + lt + 4]);
        bhi[2 * ks]     = __float_as_uint(g_Wt[(8 + lg) * PDx + ks * 8 + lt]);
        bhi[2 * ks + 1] = __float_as_uint(g_Wt[(8 + lg) * PDx + ks * 8 + lt + 4]);
    }
    // sh/th for this thread's 4 h columns
    float shv[4], thv[4];
    {
        int hc[4] = {2 * lt, 2 * lt + 1, 8 + 2 * lt, 9 + 2 * lt};
#pragma unroll
        for (int q = 0; q < 4; q++) { shv[q] = g_sh[hc[q]]; thv[q] = g_th[hc[q]]; }
    }

    for (int T = blockIdx.x; T < PB_TILES; T += gridDim.x) {
        int b   = T / (NNx * 6);
        int rem = T - b * (NNx * 6);
        int i   = rem / 6;
        int jt  = rem - i * 6;
        size_t rowbase = ((size_t)(b * NNx + i)) * NNx + jt * 128;
        const float* pbase = pair + rowbase * (size_t)PDx;

        __syncthreads();   // previous iteration's readers done before overwrite
        // stage 128x128 p tile (tf32-rounded); warp-per-row float4, coalesced
#pragma unroll
        for (int it = 0; it < 16; it++) {
            int f = tid + it * 256;
            int r = f >> 5, c4 = (f & 31) << 2;
            float4 v = *(const float4*)&pbase[(size_t)r * PDx + c4];
            uint4 t = {f2tf32(v.x), f2tf32(v.y), f2tf32(v.z), f2tf32(v.w)};
            *(uint4*)&sp[r * SPS + c4] = t;
        }
        __syncthreads();

        // mainloop: 2 mmas per k-step; stats accumulated from A fragments
        float c0 = 0.f, c1 = 0.f, c2 = 0.f, c3 = 0.f;    // h-lo
        float c4v = 0.f, c5 = 0.f, c6 = 0.f, c7 = 0.f;   // h-hi
        float s0 = 0.f, ss0 = 0.f, s1 = 0.f, ss1 = 0.f;
        const float* Ab = sp + r0 * SPS + lt;
#pragma unroll
        for (int ks = 0; ks < 16; ks++) {
            float a0 = Ab[ks * 8];
            float a1 = Ab[ks * 8 + 8 * SPS];
            float a2 = Ab[ks * 8 + 4];
            float a3 = Ab[ks * 8 + 8 * SPS + 4];
            s0 += a0 + a2;  ss0 += a0 * a0 + a2 * a2;
            s1 += a1 + a3;  ss1 += a1 * a1 + a3 * a3;
            uint32_t u0 = __float_as_uint(a0), u1 = __float_as_uint(a1);
            uint32_t u2 = __float_as_uint(a2), u3 = __float_as_uint(a3);
            mma_tf32(c0, c1, c2, c3, u0, u1, u2, u3, blo[2 * ks], blo[2 * ks + 1]);
            mma_tf32(c4v, c5, c6, c7, u0, u1, u2, u3, bhi[2 * ks], bhi[2 * ks + 1]);
        }

        // combine quarter-row stats across the lt-quad (lanes lg*4 .. lg*4+3)
        s0  += __shfl_xor_sync(~0u, s0, 1);   s0  += __shfl_xor_sync(~0u, s0, 2);
        ss0 += __shfl_xor_sync(~0u, ss0, 1);  ss0 += __shfl_xor_sync(~0u, ss0, 2);
        s1  += __shfl_xor_sync(~0u, s1, 1);   s1  += __shfl_xor_sync(~0u, s1, 2);
        ss1 += __shfl_xor_sync(~0u, ss1, 1);  ss1 += __shfl_xor_sync(~0u, ss1, 2);
        float m0 = s0 * (1.0f / PDx);
        float r0s = rsqrtf(ss0 * (1.0f / PDx) - m0 * m0 + LN_EPS);
        float m1 = s1 * (1.0f / PDx);
        float r1s = rsqrtf(ss1 * (1.0f / PDx) - m1 * m1 + LN_EPS);

        int mk0 = mask[rowbase + r0];
        int mk1 = mask[rowbase + r0 + 8];

        // direct stores: g_bias[((b*16+h)*768 + i)*768 + jt*128 + row]
        size_t pb0 = (((size_t)(b * HHx) * NNx + i)) * NNx + jt * 128;
        float rm0 = r0s * m0, rm1 = r1s * m1;
        float vals[8] = {
            r0s * c0  - rm0 * shv[0] + thv[0],   // (r0,   2lt)
            r0s * c1  - rm0 * shv[1] + thv[1],   // (r0,   2lt+1)
            r1s * c2  - rm1 * shv[0] + thv[0],   // (r0+8, 2lt)
            r1s * c3  - rm1 * shv[1] + thv[1],   // (r0+8, 2lt+1)
            r0s * c4v - rm0 * shv[2] + thv[2],   // (r0,   8+2lt)
            r0s * c5  - rm0 * shv[3] + thv[3],   // (r0,   9+2lt)
            r1s * c6  - rm1 * shv[2] + thv[2],   // (r0+8, 8+2lt)
            r1s * c7  - rm1 * shv[3] + thv[3],   // (r0+8, 9+2lt)
        };
        if (mk0 == 0) { vals[0] = NEG_INFx; vals[1] = NEG_INFx; vals[4] = NEG_INFx; vals[5] = NEG_INFx; }
        if (mk1 == 0) { vals[2] = NEG_INFx; vals[3] = NEG_INFx; vals[6] = NEG_INFx; vals[7] = NEG_INFx; }
        int hcol[4] = {2 * lt, 2 * lt + 1, 8 + 2 * lt, 9 + 2 * lt};
        size_t plane = (size_t)NNx * NNx;
        g_bias[pb0 + hcol[0] * plane + r0]     = vals[0];
        g_bias[pb0 + hcol[1] * plane + r0]     = vals[1];
        g_bias[pb0 + hcol[0] * plane + r0 + 8] = vals[2];
        g_bias[pb0 + hcol[1] * plane + r0 + 8] = vals[3];
        g_bias[pb0 + hcol[2] * plane + r0]     = vals[4];
        g_bias[pb0 + hcol[3] * plane + r0]     = vals[5];
        g_bias[pb0 + hcol[2] * plane + r0 + 8] = vals[6];
        g_bias[pb0 + hcol[3] * plane + r0 + 8] = vals[7];
    }
}

// ---------------- K5: attention, 12 rows/block; QK^T over transposed K ----------------
__global__ void k_attn() {
    __shared__ __align__(16) float S[12][NNx];
    __shared__ __align__(16) u64 qp_s[6][DHx];
    int i0 = blockIdx.x * 12;
    int h = blockIdx.y, b = blockIdx.z;
    int tid = threadIdx.x;
    int w = tid >> 5, lane = tid & 31;
    size_t bhbase = (size_t)(b * HHx + h) * NNx;

    if (tid < 192) {
        int ww = tid >> 5, d = tid & 31;
        float q0 = g_qh[(bhbase + i0 + 2 * ww) * DHx + d];
        float q1 = g_qh[(bhbase + i0 + 2 * ww + 1) * DHx + d];
        qp_s[ww][d] = pack2(q0, q1);
    }
    __syncthreads();

    const float scale = 0.17677669529663687f;
    int il0 = 2 * w, il1 = 2 * w + 1;
    int iA = i0 + il0, iB = i0 + il1;
    const float* b0row = g_bias + (bhbase + iA) * NNx;
    const float* b1row = g_bias + (bhbase + iB) * NNx;
    const float* kT = g_khT + (size_t)(b * HHx + h) * DHx * NNx;

    for (int ck = 0; ck < 6; ck++) {
        int jb = ck * 128 + lane * 4;
        u64 a0x = 0, a0y = 0, a1x = 0, a1y = 0;
#pragma unroll 8
        for (int d = 0; d < DHx; d++) {
            ulonglong2 k2 = *(const ulonglong2*)&kT[(size_t)d * NNx + jb];
            float2 q = up2(qp_s[w][d]);
            u64 q0s = splat2(q.x), q1s = splat2(q.y);
            ffma2(a0x, k2.x, q0s); ffma2(a0y, k2.y, q0s);
            ffma2(a1x, k2.x, q1s); ffma2(a1y, k2.y, q1s);
        }
        float4 bb0 = *(const float4*)&b0row[jb];
        float4 bb1 = *(const float4*)&b1row[jb];
        float2 s00 = up2(a0x), s01 = up2(a0y), s10 = up2(a1x), s11 = up2(a1y);
        float4 r0 = {s00.x * scale + bb0.x, s00.y * scale + bb0.y,
                     s01.x * scale + bb0.z, s01.y * scale + bb0.w};
        float4 r1 = {s10.x * scale + bb1.x, s10.y * scale + bb1.y,
                     s11.x * scale + bb1.z, s11.y * scale + bb1.w};
        *(float4*)&S[il0][jb] = r0;
        *(float4*)&S[il1][jb] = r1;
    }
    __syncwarp();

    float inv0, inv1;
#pragma unroll
    for (int rr = 0; rr < 2; rr++) {
        float* Sr = (rr == 0) ? &S[il0][0] : &S[il1][0];
        float mx = -3.4e38f;
        for (int c = lane; c < NNx; c += 32) mx = fmaxf(mx, Sr[c]);
#pragma unroll
        for (int o = 16; o > 0; o >>= 1) mx = fmaxf(mx, __shfl_xor_sync(~0u, mx, o));
        float sum = 0.f;
        for (int c = lane; c < NNx; c += 32) {
            float e = __expf(Sr[c] - mx);
            Sr[c] = e;
            sum += e;
        }
#pragma unroll
        for (int o = 16; o > 0; o >>= 1) sum += __shfl_xor_sync(~0u, sum, o);
        if (rr == 0) inv0 = 1.0f / sum; else inv1 = 1.0f / sum;
    }
    __syncwarp();

    int half = lane >> 4;
    int dp = (lane & 15) * 2;
    const float* vbase = g_vh + bhbase * DHx;
    float a00 = 0.f, a01 = 0.f, a10 = 0.f, a11 = 0.f;
    int jb = half * (NNx / 2);
    for (int jj = 0; jj < NNx / 2; jj += 4) {
        int j = jb + jj;
        float4 pA = *(const float4*)&S[il0][j];
        float4 pB = *(const float4*)&S[il1][j];
        const float* vp = vbase + (size_t)j * DHx + dp;
        float2 v0 = *(const float2*)(vp);
        float2 v1 = *(const float2*)(vp + 32);
        float2 v2 = *(const float2*)(vp + 64);
        float2 v3 = *(const float2*)(vp + 96);
        a00 += pA.x * v0.x + pA.y * v1.x + pA.z * v2.x + pA.w * v3.x;
        a01 += pA.x * v0.y + pA.y * v1.y + pA.z * v2.y + pA.w * v3.y;
        a10 += pB.x * v0.x + pB.y * v1.x + pB.z * v2.x + pB.w * v3.x;
        a11 += pB.x * v0.y + pB.y * v1.y + pB.z * v2.y + pB.w * v3.y;
    }
    a00 += __shfl_down_sync(~0u, a00, 16);
    a01 += __shfl_down_sync(~0u, a01, 16);
    a10 += __shfl_down_sync(~0u, a10, 16);
    a11 += __shfl_down_sync(~0u, a11, 16);

    if (half == 0) {
        size_t bnA = (size_t)b * NNx + iA;
        size_t bnB = (size_t)b * NNx + iB;
        float2 gA = *(const float2*)&g_qkvg[bnA * 2048 + 1536 + h * DHx + dp];
        float2 gB = *(const float2*)&g_qkvg[bnB * 2048 + 1536 + h * DHx + dp];
        float2 oA, oB;
        oA.x = a00 * inv0 * (1.0f / (1.0f + __expf(-gA.x)));
        oA.y = a01 * inv0 * (1.0f / (1.0f + __expf(-gA.y)));
        oB.x = a10 * inv1 * (1.0f / (1.0f + __expf(-gB.x)));
        oB.y = a11 * inv1 * (1.0f / (1.0f + __expf(-gB.y)));
        *(float2*)&g_og[bnA * INNERx + h * DHx + dp] = oA;
        *(float2*)&g_og[bnB * INNERx + h * DHx + dp] = oB;
    }
}

// ---------------- launch ----------------
extern "C" void kernel_launch(void* const* d_in, const int* in_sizes, int n_in,
                              void* d_out, int out_size) {
    const float* node = (const float*)d_in[0];
    const float* pair = (const float*)d_in[1];
    const int*   mask = (const int*)d_in[2];
    const float* nnw  = (const float*)d_in[3];
    const float* nnb  = (const float*)d_in[4];
    const float* qkvw = (const float*)d_in[5];
    const float* qkvb = (const float*)d_in[6];
    const float* gw   = (const float*)d_in[7];
    const float* gb   = (const float*)d_in[8];
    const float* qlw  = (const float*)d_in[9];
    const float* qlb  = (const float*)d_in[10];
    const float* klw  = (const float*)d_in[11];
    const float* klb  = (const float*)d_in[12];
    const float* pnw  = (const float*)d_in[13];
    const float* pnb  = (const float*)d_in[14];
    const float* bw   = (const float*)d_in[15];
    const float* ow   = (const float*)d_in[16];
    const float* ob   = (const float*)d_in[17];
    float* out = (float*)d_out;

    cudaFuncSetAttribute(k_pairbias, cudaFuncAttributeMaxDynamicSharedMemorySize, PB_SMEM);

    k_prep<<<1, 256>>>(bw, pnw, pnb);
    k_ln_node<<<BB * NNx, 256>>>(node, nnw, nnb);
    k_gemm_tc<0><<<dim3(2048 / 64, (BB * NNx) / 128), 256>>>(qkvw, gw, qkvb, gb, nullptr);
    k_pairbias<<<304, 256, PB_SMEM>>>(pair, mask);
    k_lnqk<<<BB * NNx, 256>>>(qlw, qlb, klw, klb);
    k_attn<<<dim3(NNx / 12, HHx, BB), 192>>>();
    k_gemm_tc<1><<<dim3(512 / 64, (BB * NNx) / 128), 256>>>(ow, ow, ob, ob, out);
}

// round 10
// speedup vs baseline: 2.3935x; 1.0461x over previous
#include <cuda_runtime.h>
#include <cstdint>

#define BB 2
#define NNx 768
#define DDx 512
#define HHx 16
#define DHx 32
#define INNERx 512
#define PDx 128
#define NEG_INFx -10000.0f
#define LN_EPS 1e-5f

typedef unsigned long long u64;

// ---------------- f32x2 packed-math helpers (exact fp32 semantics) ----------------
__device__ __forceinline__ void ffma2(u64& d, u64 a, u64 b) {
    asm("fma.rn.f32x2 %0, %1, %2, %0;" : "+l"(d) : "l"(a), "l"(b));
}
__device__ __forceinline__ float2 up2(u64 v) {
    float2 f;
    asm("mov.b64 {%0, %1}, %2;" : "=f"(f.x), "=f"(f.y) : "l"(v));
    return f;
}
__device__ __forceinline__ u64 pack2(float x, float y) {
    u64 r;
    asm("mov.b64 %0, {%1, %2};" : "=l"(r) : "f"(x), "f"(y));
    return r;
}
__device__ __forceinline__ u64 splat2(float x) {
    u64 r;
    asm("mov.b64 %0, {%1, %1};" : "=l"(r) : "f"(x));
    return r;
}
__device__ __forceinline__ uint32_t f2tf32(float f) {
    uint32_t r;
    asm("cvt.rna.tf32.f32 %0, %1;" : "=r"(r) : "f"(f));
    return r;
}
__device__ __forceinline__ void mma_tf32(float& c0, float& c1, float& c2, float& c3,
                                         uint32_t a0, uint32_t a1, uint32_t a2, uint32_t a3,
                                         uint32_t b0, uint32_t b1) {
    asm("mma.sync.aligned.m16n8k8.row.col.f32.tf32.tf32.f32 "
        "{%0,%1,%2,%3}, {%4,%5,%6,%7}, {%8,%9}, {%0,%1,%2,%3};"
        : "+f"(c0), "+f"(c1), "+f"(c2), "+f"(c3)
        : "r"(a0), "r"(a1), "r"(a2), "r"(a3), "r"(b0), "r"(b1));
}

// ---------------- scratch (static device memory: allowed) ----------------
__device__ float g_x[BB * NNx * DDx];
__device__ float g_qkvg[BB * NNx * 2048];                  // [q|k|v|g]
__device__ float g_qh[BB * HHx * NNx * DHx];               // q [b][h][n][d]
__device__ float g_khT[BB * HHx * DHx * NNx];              // k [b][h][d][n]  (transposed)
__device__ float g_vh[BB * HHx * NNx * DHx];               // v [b][h][n][d]
__device__ float g_bias[(size_t)BB * HHx * NNx * NNx];     // masked bias  75.5 MB
__device__ float g_og[BB * NNx * INNERx];
__device__ float g_Wt[HHx * PDx];                          // tf32-rounded W'[h][e]
__device__ float g_sh[HHx];
__device__ float g_th[HHx];

// ---------------- K0: fold pair-LN affine into projection weights ----------------
__global__ void k_prep(const float* __restrict__ bias_w,
                       const float* __restrict__ pnw,
                       const float* __restrict__ pnb) {
    int t = threadIdx.x;
    for (int idx = t; idx < HHx * PDx; idx += blockDim.x) {
        int h = idx >> 7, e = idx & 127;
        uint32_t tv = f2tf32(pnw[e] * bias_w[e * HHx + h]);
        g_Wt[idx] = __uint_as_float(tv);
    }
    if (t < HHx) {
        float s = 0.f, tt = 0.f;
        for (int e = 0; e < PDx; e++) {
            s  += pnw[e] * bias_w[e * HHx + t];
            tt += pnb[e] * bias_w[e * HHx + t];
        }
        g_sh[t] = s;
        g_th[t] = tt;
    }
}

// ---------------- K1: node LayerNorm ----------------
__global__ void k_ln_node(const float* __restrict__ nf,
                          const float* __restrict__ w,
                          const float* __restrict__ bp) {
    int row = blockIdx.x;
    const float* in = nf + (size_t)row * DDx;
    float s = 0.f, ss = 0.f;
    for (int c = threadIdx.x; c < DDx; c += 256) {
        float t = in[c];
        s += t; ss += t * t;
    }
#pragma unroll
    for (int o = 16; o > 0; o >>= 1) {
        s  += __shfl_xor_sync(~0u, s, o);
        ss += __shfl_xor_sync(~0u, ss, o);
    }
    __shared__ float red[16];
    int wid = threadIdx.x >> 5, lid = threadIdx.x & 31;
    if (lid == 0) { red[wid] = s; red[8 + wid] = ss; }
    __syncthreads();
    __shared__ float sm, sr;
    if (threadIdx.x == 0) {
        float S = 0.f, SS = 0.f;
        for (int i = 0; i < 8; i++) { S += red[i]; SS += red[8 + i]; }
        float m = S / DDx;
        sm = m;
        sr = rsqrtf(SS / DDx - m * m + LN_EPS);
    }
    __syncthreads();
    float m = sm, r = sr;
    for (int c = threadIdx.x; c < DDx; c += 256)
        g_x[(size_t)row * DDx + c] = (in[c] - m) * r * w[c] + bp[c];
}

// ---------------- K2/K6: dense GEMM on tensor pipe (tf32 mma, double-buffered) ----------------
#define AST 20
#define BST 72
template<int MODE>
__global__ void k_gemm_tc(const float* __restrict__ B1, const float* __restrict__ B2,
                          const float* __restrict__ bias1, const float* __restrict__ bias2,
                          float* __restrict__ Cext) {
    constexpr int LDC   = (MODE == 0) ? 2048 : 512;
    constexpr int SPLIT = (MODE == 0) ? 1536 : (1 << 30);
    constexpr int LD1   = (MODE == 0) ? 1536 : 512;
    constexpr int LD2   = 512;

    const float* A = (MODE == 0) ? g_x : g_og;
    float* C = (MODE == 0) ? g_qkvg : Cext;

    __shared__ __align__(16) float As[2][128 * AST];
    __shared__ __align__(16) float Bs[2][16 * BST];

    int bm = blockIdx.y * 128, bn = blockIdx.x * 64;
    int tid = threadIdx.x, w = tid >> 5, lane = tid & 31;
    int wm = w >> 1, wn = w & 1;
    int lg = lane >> 2, lt = lane & 3;

    float acc[2][4][4] = {};

    int mS = tid >> 1, segS = (tid & 1) * 8;
    int kS = tid >> 4, nS = (tid & 15) * 4;
    int ncol = bn + nS;
    const float* bsrc = (ncol < SPLIT) ? (B1 + ncol) : (B2 + (ncol - SPLIT));
    int ldb = (ncol < SPLIT) ? LD1 : LD2;
    const float* aS = A + (size_t)(bm + mS) * 512 + segS;

    float4 ra0, ra1, rb;
    ra0 = *(const float4*)(aS);
    ra1 = *(const float4*)(aS + 4);
    rb  = *(const float4*)&bsrc[(size_t)kS * ldb];
    {
        uint4 t0 = {f2tf32(ra0.x), f2tf32(ra0.y), f2tf32(ra0.z), f2tf32(ra0.w)};
        uint4 t1 = {f2tf32(ra1.x), f2tf32(ra1.y), f2tf32(ra1.z), f2tf32(ra1.w)};
        uint4 tb = {f2tf32(rb.x),  f2tf32(rb.y),  f2tf32(rb.z),  f2tf32(rb.w)};
        *(uint4*)&As[0][mS * AST + segS]     = t0;
        *(uint4*)&As[0][mS * AST + segS + 4] = t1;
        *(uint4*)&Bs[0][kS * BST + nS]       = tb;
    }
    __syncthreads();

    for (int k0 = 0; k0 < 512; k0 += 16) {
        int cur = (k0 >> 4) & 1;
        bool more = (k0 + 16) < 512;
        if (more) {
            ra0 = *(const float4*)(aS + k0 + 16);
            ra1 = *(const float4*)(aS + k0 + 20);
            rb  = *(const float4*)&bsrc[(size_t)(k0 + 16 + kS) * ldb];
        }

#pragma unroll
        for (int ks = 0; ks < 2; ks++) {
            uint32_t af[2][4];
            const float* ab = &As[cur][(wm * 32 + lg) * AST + ks * 8 + lt];
#pragma unroll
            for (int mf = 0; mf < 2; mf++) {
                const float* a = ab + mf * 16 * AST;
                af[mf][0] = __float_as_uint(a[0]);
                af[mf][1] = __float_as_uint(a[8 * AST]);
                af[mf][2] = __float_as_uint(a[4]);
                af[mf][3] = __float_as_uint(a[8 * AST + 4]);
            }
            uint32_t bf[4][2];
            const float* bb = &Bs[cur][(ks * 8 + lt) * BST + wn * 32 + lg];
#pragma unroll
            for (int nf = 0; nf < 4; nf++) {
                bf[nf][0] = __float_as_uint(bb[nf * 8]);
                bf[nf][1] = __float_as_uint(bb[4 * BST + nf * 8]);
            }
#pragma unroll
            for (int mf = 0; mf < 2; mf++)
#pragma unroll
                for (int nf = 0; nf < 4; nf++)
                    mma_tf32(acc[mf][nf][0], acc[mf][nf][1], acc[mf][nf][2], acc[mf][nf][3],
                             af[mf][0], af[mf][1], af[mf][2], af[mf][3],
                             bf[nf][0], bf[nf][1]);
        }

        if (more) {
            int nxt = cur ^ 1;
            uint4 t0 = {f2tf32(ra0.x), f2tf32(ra0.y), f2tf32(ra0.z), f2tf32(ra0.w)};
            uint4 t1 = {f2tf32(ra1.x), f2tf32(ra1.y), f2tf32(ra1.z), f2tf32(ra1.w)};
            uint4 tb = {f2tf32(rb.x),  f2tf32(rb.y),  f2tf32(rb.z),  f2tf32(rb.w)};
            *(uint4*)&As[nxt][mS * AST + segS]     = t0;
            *(uint4*)&As[nxt][mS * AST + segS + 4] = t1;
            *(uint4*)&Bs[nxt][kS * BST + nS]       = tb;
        }
        __syncthreads();
    }

#pragma unroll
    for (int mf = 0; mf < 2; mf++) {
#pragma unroll
        for (int nf = 0; nf < 4; nf++) {
            int r = bm + wm * 32 + mf * 16 + lg;
            int c = bn + wn * 32 + nf * 8 + 2 * lt;
            float bi0 = (c < SPLIT) ? bias1[c] : bias2[c - SPLIT];
            float bi1 = (c + 1 < SPLIT) ? bias1[c + 1] : bias2[c + 1 - SPLIT];
            float2 v0 = {acc[mf][nf][0] + bi0, acc[mf][nf][1] + bi1};
            float2 v1 = {acc[mf][nf][2] + bi0, acc[mf][nf][3] + bi1};
            *(float2*)&C[(size_t)r * LDC + c]       = v0;
            *(float2*)&C[(size_t)(r + 8) * LDC + c] = v1;
        }
    }
}

// ---------------- K3: q/k LN over INNER; q,v head-major, k TRANSPOSED ----------------
__global__ void k_lnqk(const float* __restrict__ qw, const float* __restrict__ qb,
                       const float* __restrict__ kw, const float* __restrict__ kb) {
    int bn = blockIdx.x;
    const float* row = g_qkvg + (size_t)bn * 2048;
    int b = bn / NNx, nn = bn % NNx;
    float s1 = 0.f, ss1 = 0.f, s2 = 0.f, ss2 = 0.f;
    for (int c = threadIdx.x; c < 512; c += 256) {
        float a = row[c], b2 = row[512 + c];
        s1 += a; ss1 += a * a; s2 += b2; ss2 += b2 * b2;
    }
#pragma unroll
    for (int o = 16; o > 0; o >>= 1) {
        s1  += __shfl_xor_sync(~0u, s1, o);  ss1 += __shfl_xor_sync(~0u, ss1, o);
        s2  += __shfl_xor_sync(~0u, s2, o);  ss2 += __shfl_xor_sync(~0u, ss2, o);
    }
    __shared__ float red[4][8];
    int w = threadIdx.x >> 5, lane = threadIdx.x & 31;
    if (lane == 0) { red[0][w] = s1; red[1][w] = ss1; red[2][w] = s2; red[3][w] = ss2; }
    __syncthreads();
    __shared__ float st[4];
    if (threadIdx.x == 0) {
        float a = 0.f, bb = 0.f, c = 0.f, d = 0.f;
        for (int i = 0; i < 8; i++) { a += red[0][i]; bb += red[1][i]; c += red[2][i]; d += red[3][i]; }
        float m1 = a / 512.f, m2 = c / 512.f;
        st[0] = m1; st[1] = rsqrtf(bb / 512.f - m1 * m1 + LN_EPS);
        st[2] = m2; st[3] = rsqrtf(d / 512.f - m2 * m2 + LN_EPS);
    }
    __syncthreads();
    float m1 = st[0], r1 = st[1], m2 = st[2], r2 = st[3];
    for (int c = threadIdx.x; c < 512; c += 256) {
        int h = c >> 5, d = c & 31;
        size_t oidx  = (((size_t)(b * HHx + h)) * NNx + nn) * DHx + d;     // [b][h][n][d]
        size_t oidxT = (((size_t)(b * HHx + h)) * DHx + d) * NNx + nn;     // [b][h][d][n]
        g_qh[oidx]   = (row[c]       - m1) * r1 * qw[c] + qb[c];
        g_khT[oidxT] = (row[512 + c] - m2) * r2 * kw[c] + kb[c];
        g_vh[oidx]   = row[1024 + c];
    }
}

// ---------------- K4: pair bias — persistent + cp.async double-buffered ----------------
// FIXED staging: 16 chunks/thread (4096 x 16B = full 128x128 tile), R8-proven index math.
#define SPS 132
#define PB_TILES (BB * NNx * 6)                 // 9216
#define PB_TILE_F (128 * SPS)                   // floats per buffer
#define PB_SMEM  (2 * PB_TILE_F * 4)            // 135168 B
__device__ __forceinline__ size_t pb_decode(int T, int& b, int& i, int& jt) {
    b = T / (NNx * 6);
    int rem = T - b * (NNx * 6);
    i = rem / 6;
    jt = rem - i * 6;
    return ((size_t)(b * NNx + i)) * NNx + jt * 128;
}
__device__ __forceinline__ void pb_stage(float* buf, const float* pb, int tid) {
#pragma unroll
    for (int it = 0; it < 16; it++) {
        int f = tid + it * 256;                 // float4-chunk index 0..4095
        int r = f >> 5, c4 = (f & 31) << 2;
        unsigned sa = (unsigned)__cvta_generic_to_shared(buf + r * SPS + c4);
        const float* ga = pb + (size_t)r * PDx + c4;
        asm volatile("cp.async.cg.shared.global [%0], [%1], 16;" :: "r"(sa), "l"(ga));
    }
    asm volatile("cp.async.commit_group;");
}
__global__ __launch_bounds__(256) void k_pairbias(const float* __restrict__ pair,
                                                  const int* __restrict__ mask) {
    extern __shared__ __align__(16) float sp[];   // 2 buffers of [128][SPS]

    int tid = threadIdx.x, w = tid >> 5, lane = tid & 31;
    int lg = lane >> 2, lt = lane & 3;
    int r0 = w * 16 + lg;

    uint32_t blo[32], bhi[32];
#pragma unroll
    for (int ks = 0; ks < 16; ks++) {
        blo[2 * ks]     = __float_as_uint(g_Wt[lg * PDx + ks * 8 + lt]);
        blo[2 * ks + 1] = __float_as_uint(g_Wt[lg * PDx + ks * 8 + lt + 4]);
        bhi[2 * ks]     = __float_as_uint(g_Wt[(8 + lg) * PDx + ks * 8 + lt]);
        bhi[2 * ks + 1] = __float_as_uint(g_Wt[(8 + lg) * PDx + ks * 8 + lt + 4]);
    }
    float shv[4], thv[4];
    {
        int hc[4] = {2 * lt, 2 * lt + 1, 8 + 2 * lt, 9 + 2 * lt};
#pragma unroll
        for (int q = 0; q < 4; q++) { shv[q] = g_sh[hc[q]]; thv[q] = g_th[hc[q]]; }
    }

    const int g = gridDim.x;

    // prologue: prefetch first tile into buffer 0
    {
        int b, i, jt;
        size_t rb = pb_decode(blockIdx.x, b, i, jt);
        pb_stage(sp, pair + rb * (size_t)PDx, tid);
    }

    int parity = 0;
    for (int T = blockIdx.x; T < PB_TILES; T += g) {
        asm volatile("cp.async.wait_group 0;" ::: "memory");
        __syncthreads();

        int Tn = T + g;
        if (Tn < PB_TILES) {
            int b2, i2, jt2;
            size_t rb2 = pb_decode(Tn, b2, i2, jt2);
            pb_stage(sp + (parity ^ 1) * PB_TILE_F, pair + rb2 * (size_t)PDx, tid);
        }

        // ---- compute current tile ----
        int b, i, jt;
        size_t rowbase = pb_decode(T, b, i, jt);
        const float* buf = sp + parity * PB_TILE_F;

        float c0 = 0.f, c1 = 0.f, c2 = 0.f, c3 = 0.f;
        float c4v = 0.f, c5 = 0.f, c6 = 0.f, c7 = 0.f;
        float s0 = 0.f, ss0 = 0.f, s1 = 0.f, ss1 = 0.f;
        const float* Ab = buf + r0 * SPS + lt;
#pragma unroll
        for (int ks = 0; ks < 16; ks++) {
            float a0 = Ab[ks * 8];
            float a1 = Ab[ks * 8 + 8 * SPS];
            float a2 = Ab[ks * 8 + 4];
            float a3 = Ab[ks * 8 + 8 * SPS + 4];
            s0 += a0 + a2;  ss0 += a0 * a0 + a2 * a2;
            s1 += a1 + a3;  ss1 += a1 * a1 + a3 * a3;
            uint32_t u0 = __float_as_uint(a0), u1 = __float_as_uint(a1);
            uint32_t u2 = __float_as_uint(a2), u3 = __float_as_uint(a3);
            mma_tf32(c0, c1, c2, c3, u0, u1, u2, u3, blo[2 * ks], blo[2 * ks + 1]);
            mma_tf32(c4v, c5, c6, c7, u0, u1, u2, u3, bhi[2 * ks], bhi[2 * ks + 1]);
        }

        s0  += __shfl_xor_sync(~0u, s0, 1);   s0  += __shfl_xor_sync(~0u, s0, 2);
        ss0 += __shfl_xor_sync(~0u, ss0, 1);  ss0 += __shfl_xor_sync(~0u, ss0, 2);
        s1  += __shfl_xor_sync(~0u, s1, 1);   s1  += __shfl_xor_sync(~0u, s1, 2);
        ss1 += __shfl_xor_sync(~0u, ss1, 1);  ss1 += __shfl_xor_sync(~0u, ss1, 2);
        float m0 = s0 * (1.0f / PDx);
        float r0s = rsqrtf(ss0 * (1.0f / PDx) - m0 * m0 + LN_EPS);
        float m1 = s1 * (1.0f / PDx);
        float r1s = rsqrtf(ss1 * (1.0f / PDx) - m1 * m1 + LN_EPS);

        int mk0 = mask[rowbase + r0];
        int mk1 = mask[rowbase + r0 + 8];

        size_t pb0 = (((size_t)(b * HHx) * NNx + i)) * NNx + jt * 128;
        float rm0 = r0s * m0, rm1 = r1s * m1;
        float vals[8] = {
            r0s * c0  - rm0 * shv[0] + thv[0],
            r0s * c1  - rm0 * shv[1] + thv[1],
            r1s * c2  - rm1 * shv[0] + thv[0],
            r1s * c3  - rm1 * shv[1] + thv[1],
            r0s * c4v - rm0 * shv[2] + thv[2],
            r0s * c5  - rm0 * shv[3] + thv[3],
            r1s * c6  - rm1 * shv[2] + thv[2],
            r1s * c7  - rm1 * shv[3] + thv[3],
        };
        if (mk0 == 0) { vals[0] = NEG_INFx; vals[1] = NEG_INFx; vals[4] = NEG_INFx; vals[5] = NEG_INFx; }
        if (mk1 == 0) { vals[2] = NEG_INFx; vals[3] = NEG_INFx; vals[6] = NEG_INFx; vals[7] = NEG_INFx; }
        int hcol[4] = {2 * lt, 2 * lt + 1, 8 + 2 * lt, 9 + 2 * lt};
        size_t plane = (size_t)NNx * NNx;
        g_bias[pb0 + hcol[0] * plane + r0]     = vals[0];
        g_bias[pb0 + hcol[1] * plane + r0]     = vals[1];
        g_bias[pb0 + hcol[0] * plane + r0 + 8] = vals[2];
        g_bias[pb0 + hcol[1] * plane + r0 + 8] = vals[3];
        g_bias[pb0 + hcol[2] * plane + r0]     = vals[4];
        g_bias[pb0 + hcol[3] * plane + r0]     = vals[5];
        g_bias[pb0 + hcol[2] * plane + r0 + 8] = vals[6];
        g_bias[pb0 + hcol[3] * plane + r0 + 8] = vals[7];

        parity ^= 1;
    }
}

// ---------------- K5: attention — QK column-owned, softmax/AV row-owned ----------------
__global__ void k_attn() {
    __shared__ __align__(16) float S[12][NNx];     // 36864 B
    __shared__ __align__(16) u64 qp2[12][16];      //  1536 B  q packed {2d,2d+1}
    int i0 = blockIdx.x * 12;
    int h = blockIdx.y, b = blockIdx.z;
    int tid = threadIdx.x;
    int w = tid >> 5, lane = tid & 31;
    size_t bhbase = (size_t)(b * HHx + h) * NNx;

    if (tid < 192) {
        int r = tid >> 4, dp = tid & 15;
        const float* qrow = g_qh + (bhbase + i0 + r) * DHx + 2 * dp;
        float2 qv = *(const float2*)qrow;
        qp2[r][dp] = pack2(qv.x, qv.y);
    }
    __syncthreads();

    const float scale = 0.17677669529663687f;   // 1/sqrt(32)
    const float* kT = g_khT + (size_t)(b * HHx + h) * DHx * NNx;

    // ---- QK^T: warp w owns j-chunk w (128 j); accumulates all 12 rows ----
    {
        int jb = w * 128 + lane * 4;
        const float* kTc = kT + jb;
        u64 acc[12][2];
#pragma unroll
        for (int r = 0; r < 12; r++) { acc[r][0] = 0; acc[r][1] = 0; }

#pragma unroll
        for (int dg = 0; dg < 4; dg++) {
            u64 kx[8][2];
#pragma unroll
            for (int dd = 0; dd < 8; dd++) {
                ulonglong2 kv = *(const ulonglong2*)&kTc[(size_t)(dg * 8 + dd) * NNx];
                kx[dd][0] = kv.x; kx[dd][1] = kv.y;
            }
#pragma unroll
            for (int r = 0; r < 12; r++) {
#pragma unroll
                for (int dd = 0; dd < 4; dd++) {
                    float2 q = up2(qp2[r][dg * 4 + dd]);
                    u64 q0 = splat2(q.x), q1 = splat2(q.y);
                    ffma2(acc[r][0], kx[2 * dd][0], q0);
                    ffma2(acc[r][1], kx[2 * dd][1], q0);
                    ffma2(acc[r][0], kx[2 * dd + 1][0], q1);
                    ffma2(acc[r][1], kx[2 * dd + 1][1], q1);
                }
            }
        }

#pragma unroll
        for (int r = 0; r < 12; r++) {
            float4 bb = *(const float4*)&g_bias[(bhbase + i0 + r) * NNx + jb];
            float2 sx = up2(acc[r][0]), sy = up2(acc[r][1]);
            float4 out = {sx.x * scale + bb.x, sx.y * scale + bb.y,
                          sy.x * scale + bb.z, sy.y * scale + bb.w};
            *(float4*)&S[r][jb] = out;
        }
    }
    __syncthreads();

    // ---- softmax: warp w owns rows 2w, 2w+1 ----
    int il0 = 2 * w, il1 = 2 * w + 1;
    int iA = i0 + il0, iB = i0 + il1;
    float inv0, inv1;
#pragma unroll
    for (int rr = 0; rr < 2; rr++) {
        float* Sr = (rr == 0) ? &S[il0][0] : &S[il1][0];
        float mx = -3.4e38f;
        for (int c = lane; c < NNx; c += 32) mx = fmaxf(mx, Sr[c]);
#pragma unroll
        for (int o = 16; o > 0; o >>= 1) mx = fmaxf(mx, __shfl_xor_sync(~0u, mx, o));
        float sum = 0.f;
        for (int c = lane; c < NNx; c += 32) {
            float e = __expf(Sr[c] - mx);
            Sr[c] = e;
            sum += e;
        }
#pragma unroll
        for (int o = 16; o > 0; o >>= 1) sum += __shfl_xor_sync(~0u, sum, o);
        if (rr == 0) inv0 = 1.0f / sum; else inv1 = 1.0f / sum;
    }
    __syncwarp();

    // ---- AV: lane = (half, d-pair); half-warps split j ----
    int half = lane >> 4;
    int dp = (lane & 15) * 2;
    const float* vbase = g_vh + bhbase * DHx;
    float a00 = 0.f, a01 = 0.f, a10 = 0.f, a11 = 0.f;
    int jb = half * (NNx / 2);
    for (int jj = 0; jj < NNx / 2; jj += 4) {
        int j = jb + jj;
        float4 pA = *(const float4*)&S[il0][j];
        float4 pB = *(const float4*)&S[il1][j];
        const float* vp = vbase + (size_t)j * DHx + dp;
        float2 v0 = *(const float2*)(vp);
        float2 v1 = *(const float2*)(vp + 32);
        float2 v2 = *(const float2*)(vp + 64);
        float2 v3 = *(const float2*)(vp + 96);
        a00 += pA.x * v0.x + pA.y * v1.x + pA.z * v2.x + pA.w * v3.x;
        a01 += pA.x * v0.y + pA.y * v1.y + pA.z * v2.y + pA.w * v3.y;
        a10 += pB.x * v0.x + pB.y * v1.x + pB.z * v2.x + pB.w * v3.x;
        a11 += pB.x * v0.y + pB.y * v1.y + pB.z * v2.y + pB.w * v3.y;
    }
    a00 += __shfl_down_sync(~0u, a00, 16);
    a01 += __shfl_down_sync(~0u, a01, 16);
    a10 += __shfl_down_sync(~0u, a10, 16);
    a11 += __shfl_down_sync(~0u, a11, 16);

    if (half == 0) {
        size_t bnA = (size_t)b * NNx + iA;
        size_t bnB = (size_t)b * NNx + iB;
        float2 gA = *(const float2*)&g_qkvg[bnA * 2048 + 1536 + h * DHx + dp];
        float2 gB = *(const float2*)&g_qkvg[bnB * 2048 + 1536 + h * DHx + dp];
        float2 oA, oB;
        oA.x = a00 * inv0 * (1.0f / (1.0f + __expf(-gA.x)));
        oA.y = a01 * inv0 * (1.0f / (1.0f + __expf(-gA.y)));
        oB.x = a10 * inv1 * (1.0f / (1.0f + __expf(-gB.x)));
        oB.y = a11 * inv1 * (1.0f / (1.0f + __expf(-gB.y)));
        *(float2*)&g_og[bnA * INNERx + h * DHx + dp] = oA;
        *(float2*)&g_og[bnB * INNERx + h * DHx + dp] = oB;
    }
}

// ---------------- launch ----------------
extern "C" void kernel_launch(void* const* d_in, const int* in_sizes, int n_in,
                              void* d_out, int out_size) {
    const float* node = (const float*)d_in[0];
    const float* pair = (const float*)d_in[1];
    const int*   mask = (const int*)d_in[2];
    const float* nnw  = (const float*)d_in[3];
    const float* nnb  = (const float*)d_in[4];
    const float* qkvw = (const float*)d_in[5];
    const float* qkvb = (const float*)d_in[6];
    const float* gw   = (const float*)d_in[7];
    const float* gb   = (const float*)d_in[8];
    const float* qlw  = (const float*)d_in[9];
    const float* qlb  = (const float*)d_in[10];
    const float* klw  = (const float*)d_in[11];
    const float* klb  = (const float*)d_in[12];
    const float* pnw  = (const float*)d_in[13];
    const float* pnb  = (const float*)d_in[14];
    const float* bw   = (const float*)d_in[15];
    const float* ow   = (const float*)d_in[16];
    const float* ob   = (const float*)d_in[17];
    float* out = (float*)d_out;

    cudaFuncSetAttribute(k_pairbias, cudaFuncAttributeMaxDynamicSharedMemorySize, PB_SMEM);

    k_prep<<<1, 256>>>(bw, pnw, pnb);
    k_ln_node<<<BB * NNx, 256>>>(node, nnw, nnb);
    k_gemm_tc<0><<<dim3(2048 / 64, (BB * NNx) / 128), 256>>>(qkvw, gw, qkvb, gb, nullptr);
    k_pairbias<<<148, 256, PB_SMEM>>>(pair, mask);
    k_lnqk<<<BB * NNx, 256>>>(qlw, qlb, klw, klb);
    k_attn<<<dim3(NNx / 12, HHx, BB), 192>>>();
    k_gemm_tc<1><<<dim3(512 / 64, (BB * NNx) / 128), 256>>>(ow, ow, ob, ob, out);
}

// round 11
// speedup vs baseline: 2.5703x; 1.0739x over previous
#include <cuda_runtime.h>
#include <cstdint>

#define BB 2
#define NNx 768
#define DDx 512
#define HHx 16
#define DHx 32
#define INNERx 512
#define PDx 128
#define NEG_INFx -10000.0f
#define LN_EPS 1e-5f

typedef unsigned long long u64;

// ---------------- f32x2 packed-math helpers (exact fp32 semantics) ----------------
__device__ __forceinline__ void ffma2(u64& d, u64 a, u64 b) {
    asm("fma.rn.f32x2 %0, %1, %2, %0;" : "+l"(d) : "l"(a), "l"(b));
}
__device__ __forceinline__ float2 up2(u64 v) {
    float2 f;
    asm("mov.b64 {%0, %1}, %2;" : "=f"(f.x), "=f"(f.y) : "l"(v));
    return f;
}
__device__ __forceinline__ u64 pack2(float x, float y) {
    u64 r;
    asm("mov.b64 %0, {%1, %2};" : "=l"(r) : "f"(x), "f"(y));
    return r;
}
__device__ __forceinline__ u64 splat2(float x) {
    u64 r;
    asm("mov.b64 %0, {%1, %1};" : "=l"(r) : "f"(x));
    return r;
}
__device__ __forceinline__ uint32_t f2tf32(float f) {
    uint32_t r;
    asm("cvt.rna.tf32.f32 %0, %1;" : "=r"(r) : "f"(f));
    return r;
}
__device__ __forceinline__ void mma_tf32(float& c0, float& c1, float& c2, float& c3,
                                         uint32_t a0, uint32_t a1, uint32_t a2, uint32_t a3,
                                         uint32_t b0, uint32_t b1) {
    asm("mma.sync.aligned.m16n8k8.row.col.f32.tf32.tf32.f32 "
        "{%0,%1,%2,%3}, {%4,%5,%6,%7}, {%8,%9}, {%0,%1,%2,%3};"
        : "+f"(c0), "+f"(c1), "+f"(c2), "+f"(c3)
        : "r"(a0), "r"(a1), "r"(a2), "r"(a3), "r"(b0), "r"(b1));
}

// ---------------- scratch (static device memory: allowed) ----------------
__device__ float g_x[BB * NNx * DDx];
__device__ float g_qkvg[BB * NNx * 2048];                  // [q|k|v|g]
__device__ float g_qh[BB * HHx * NNx * DHx];               // q [b][h][n][d]
__device__ float g_khT[BB * HHx * DHx * NNx];              // k [b][h][d][n]  (transposed)
__device__ float g_vh[BB * HHx * NNx * DHx];               // v [b][h][n][d]
__device__ float g_bias[(size_t)BB * HHx * NNx * NNx];     // masked bias  75.5 MB
__device__ float g_og[BB * NNx * INNERx];
__device__ float g_Wt[HHx * PDx];                          // tf32-rounded W'[h][e]
__device__ float g_sh[HHx];
__device__ float g_th[HHx];

// ---------------- K0: fold pair-LN affine into projection weights ----------------
__global__ void k_prep(const float* __restrict__ bias_w,
                       const float* __restrict__ pnw,
                       const float* __restrict__ pnb) {
    int t = threadIdx.x;
    for (int idx = t; idx < HHx * PDx; idx += blockDim.x) {
        int h = idx >> 7, e = idx & 127;
        uint32_t tv = f2tf32(pnw[e] * bias_w[e * HHx + h]);
        g_Wt[idx] = __uint_as_float(tv);
    }
    if (t < HHx) {
        float s = 0.f, tt = 0.f;
        for (int e = 0; e < PDx; e++) {
            s  += pnw[e] * bias_w[e * HHx + t];
            tt += pnb[e] * bias_w[e * HHx + t];
        }
        g_sh[t] = s;
        g_th[t] = tt;
    }
}

// ---------------- K1: node LayerNorm ----------------
__global__ void k_ln_node(const float* __restrict__ nf,
                          const float* __restrict__ w,
                          const float* __restrict__ bp) {
    int row = blockIdx.x;
    const float* in = nf + (size_t)row * DDx;
    float s = 0.f, ss = 0.f;
    for (int c = threadIdx.x; c < DDx; c += 256) {
        float t = in[c];
        s += t; ss += t * t;
    }
#pragma unroll
    for (int o = 16; o > 0; o >>= 1) {
        s  += __shfl_xor_sync(~0u, s, o);
        ss += __shfl_xor_sync(~0u, ss, o);
    }
    __shared__ float red[16];
    int wid = threadIdx.x >> 5, lid = threadIdx.x & 31;
    if (lid == 0) { red[wid] = s; red[8 + wid] = ss; }
    __syncthreads();
    __shared__ float sm, sr;
    if (threadIdx.x == 0) {
        float S = 0.f, SS = 0.f;
        for (int i = 0; i < 8; i++) { S += red[i]; SS += red[8 + i]; }
        float m = S / DDx;
        sm = m;
        sr = rsqrtf(SS / DDx - m * m + LN_EPS);
    }
    __syncthreads();
    float m = sm, r = sr;
    for (int c = threadIdx.x; c < DDx; c += 256)
        g_x[(size_t)row * DDx + c] = (in[c] - m) * r * w[c] + bp[c];
}

// ---------------- K2/K6: dense GEMM on tensor pipe (tf32 mma, double-buffered) ----------------
#define AST 20
#define BST 72
template<int MODE>
__global__ void k_gemm_tc(const float* __restrict__ B1, const float* __restrict__ B2,
                          const float* __restrict__ bias1, const float* __restrict__ bias2,
                          float* __restrict__ Cext) {
    constexpr int LDC   = (MODE == 0) ? 2048 : 512;
    constexpr int SPLIT = (MODE == 0) ? 1536 : (1 << 30);
    constexpr int LD1   = (MODE == 0) ? 1536 : 512;
    constexpr int LD2   = 512;

    const float* A = (MODE == 0) ? g_x : g_og;
    float* C = (MODE == 0) ? g_qkvg : Cext;

    __shared__ __align__(16) float As[2][128 * AST];
    __shared__ __align__(16) float Bs[2][16 * BST];

    int bm = blockIdx.y * 128, bn = blockIdx.x * 64;
    int tid = threadIdx.x, w = tid >> 5, lane = tid & 31;
    int wm = w >> 1, wn = w & 1;
    int lg = lane >> 2, lt = lane & 3;

    float acc[2][4][4] = {};

    int mS = tid >> 1, segS = (tid & 1) * 8;
    int kS = tid >> 4, nS = (tid & 15) * 4;
    int ncol = bn + nS;
    const float* bsrc = (ncol < SPLIT) ? (B1 + ncol) : (B2 + (ncol - SPLIT));
    int ldb = (ncol < SPLIT) ? LD1 : LD2;
    const float* aS = A + (size_t)(bm + mS) * 512 + segS;

    float4 ra0, ra1, rb;
    ra0 = *(const float4*)(aS);
    ra1 = *(const float4*)(aS + 4);
    rb  = *(const float4*)&bsrc[(size_t)kS * ldb];
    {
        uint4 t0 = {f2tf32(ra0.x), f2tf32(ra0.y), f2tf32(ra0.z), f2tf32(ra0.w)};
        uint4 t1 = {f2tf32(ra1.x), f2tf32(ra1.y), f2tf32(ra1.z), f2tf32(ra1.w)};
        uint4 tb = {f2tf32(rb.x),  f2tf32(rb.y),  f2tf32(rb.z),  f2tf32(rb.w)};
        *(uint4*)&As[0][mS * AST + segS]     = t0;
        *(uint4*)&As[0][mS * AST + segS + 4] = t1;
        *(uint4*)&Bs[0][kS * BST + nS]       = tb;
    }
    __syncthreads();

    for (int k0 = 0; k0 < 512; k0 += 16) {
        int cur = (k0 >> 4) & 1;
        bool more = (k0 + 16) < 512;
        if (more) {
            ra0 = *(const float4*)(aS + k0 + 16);
            ra1 = *(const float4*)(aS + k0 + 20);
            rb  = *(const float4*)&bsrc[(size_t)(k0 + 16 + kS) * ldb];
        }

#pragma unroll
        for (int ks = 0; ks < 2; ks++) {
            uint32_t af[2][4];
            const float* ab = &As[cur][(wm * 32 + lg) * AST + ks * 8 + lt];
#pragma unroll
            for (int mf = 0; mf < 2; mf++) {
                const float* a = ab + mf * 16 * AST;
                af[mf][0] = __float_as_uint(a[0]);
                af[mf][1] = __float_as_uint(a[8 * AST]);
                af[mf][2] = __float_as_uint(a[4]);
                af[mf][3] = __float_as_uint(a[8 * AST + 4]);
            }
            uint32_t bf[4][2];
            const float* bb = &Bs[cur][(ks * 8 + lt) * BST + wn * 32 + lg];
#pragma unroll
            for (int nf = 0; nf < 4; nf++) {
                bf[nf][0] = __float_as_uint(bb[nf * 8]);
                bf[nf][1] = __float_as_uint(bb[4 * BST + nf * 8]);
            }
#pragma unroll
            for (int mf = 0; mf < 2; mf++)
#pragma unroll
                for (int nf = 0; nf < 4; nf++)
                    mma_tf32(acc[mf][nf][0], acc[mf][nf][1], acc[mf][nf][2], acc[mf][nf][3],
                             af[mf][0], af[mf][1], af[mf][2], af[mf][3],
                             bf[nf][0], bf[nf][1]);
        }

        if (more) {
            int nxt = cur ^ 1;
            uint4 t0 = {f2tf32(ra0.x), f2tf32(ra0.y), f2tf32(ra0.z), f2tf32(ra0.w)};
            uint4 t1 = {f2tf32(ra1.x), f2tf32(ra1.y), f2tf32(ra1.z), f2tf32(ra1.w)};
            uint4 tb = {f2tf32(rb.x),  f2tf32(rb.y),  f2tf32(rb.z),  f2tf32(rb.w)};
            *(uint4*)&As[nxt][mS * AST + segS]     = t0;
            *(uint4*)&As[nxt][mS * AST + segS + 4] = t1;
            *(uint4*)&Bs[nxt][kS * BST + nS]       = tb;
        }
        __syncthreads();
    }

#pragma unroll
    for (int mf = 0; mf < 2; mf++) {
#pragma unroll
        for (int nf = 0; nf < 4; nf++) {
            int r = bm + wm * 32 + mf * 16 + lg;
            int c = bn + wn * 32 + nf * 8 + 2 * lt;
            float bi0 = (c < SPLIT) ? bias1[c] : bias2[c - SPLIT];
            float bi1 = (c + 1 < SPLIT) ? bias1[c + 1] : bias2[c + 1 - SPLIT];
            float2 v0 = {acc[mf][nf][0] + bi0, acc[mf][nf][1] + bi1};
            float2 v1 = {acc[mf][nf][2] + bi0, acc[mf][nf][3] + bi1};
            *(float2*)&C[(size_t)r * LDC + c]       = v0;
            *(float2*)&C[(size_t)(r + 8) * LDC + c] = v1;
        }
    }
}

// ---------------- K3: q/k LN over INNER; q,v head-major, k TRANSPOSED ----------------
__global__ void k_lnqk(const float* __restrict__ qw, const float* __restrict__ qb,
                       const float* __restrict__ kw, const float* __restrict__ kb) {
    int bn = blockIdx.x;
    const float* row = g_qkvg + (size_t)bn * 2048;
    int b = bn / NNx, nn = bn % NNx;
    float s1 = 0.f, ss1 = 0.f, s2 = 0.f, ss2 = 0.f;
    for (int c = threadIdx.x; c < 512; c += 256) {
        float a = row[c], b2 = row[512 + c];
        s1 += a; ss1 += a * a; s2 += b2; ss2 += b2 * b2;
    }
#pragma unroll
    for (int o = 16; o > 0; o >>= 1) {
        s1  += __shfl_xor_sync(~0u, s1, o);  ss1 += __shfl_xor_sync(~0u, ss1, o);
        s2  += __shfl_xor_sync(~0u, s2, o);  ss2 += __shfl_xor_sync(~0u, ss2, o);
    }
    __shared__ float red[4][8];
    int w = threadIdx.x >> 5, lane = threadIdx.x & 31;
    if (lane == 0) { red[0][w] = s1; red[1][w] = ss1; red[2][w] = s2; red[3][w] = ss2; }
    __syncthreads();
    __shared__ float st[4];
    if (threadIdx.x == 0) {
        float a = 0.f, bb = 0.f, c = 0.f, d = 0.f;
        for (int i = 0; i < 8; i++) { a += red[0][i]; bb += red[1][i]; c += red[2][i]; d += red[3][i]; }
        float m1 = a / 512.f, m2 = c / 512.f;
        st[0] = m1; st[1] = rsqrtf(bb / 512.f - m1 * m1 + LN_EPS);
        st[2] = m2; st[3] = rsqrtf(d / 512.f - m2 * m2 + LN_EPS);
    }
    __syncthreads();
    float m1 = st[0], r1 = st[1], m2 = st[2], r2 = st[3];
    for (int c = threadIdx.x; c < 512; c += 256) {
        int h = c >> 5, d = c & 31;
        size_t oidx  = (((size_t)(b * HHx + h)) * NNx + nn) * DHx + d;     // [b][h][n][d]
        size_t oidxT = (((size_t)(b * HHx + h)) * DHx + d) * NNx + nn;     // [b][h][d][n]
        g_qh[oidx]   = (row[c]       - m1) * r1 * qw[c] + qb[c];
        g_khT[oidxT] = (row[512 + c] - m2) * r2 * kw[c] + kb[c];
        g_vh[oidx]   = row[1024 + c];
    }
}

// ---------------- K4: pair bias — persistent, 64-row tiles, 3 CTAs/SM, split chains ----------------
#define SPS 132
#define PB_TR 64                                 // tile rows
#define PB_TILES (BB * NNx * 12)                 // 18432
#define PB_TILE_F (PB_TR * SPS)                  // floats per buffer
#define PB_SMEM  (2 * PB_TILE_F * 4)             // 67584 B
__device__ __forceinline__ size_t pb_decode(int T, int& b, int& i, int& jt) {
    b = T / (NNx * 12);
    int rem = T - b * (NNx * 12);
    i = rem / 12;
    jt = rem - i * 12;
    return ((size_t)(b * NNx + i)) * NNx + jt * PB_TR;
}
__device__ __forceinline__ void pb_stage(float* buf, const float* pb, int tid) {
#pragma unroll
    for (int it = 0; it < 16; it++) {
        int f = tid + it * 128;                  // float4-chunk 0..2047 (64 rows x 32)
        int r = f >> 5, c4 = (f & 31) << 2;
        unsigned sa = (unsigned)__cvta_generic_to_shared(buf + r * SPS + c4);
        const float* ga = pb + (size_t)r * PDx + c4;
        asm volatile("cp.async.cg.shared.global [%0], [%1], 16;" :: "r"(sa), "l"(ga));
    }
    asm volatile("cp.async.commit_group;");
}
__global__ __launch_bounds__(128, 3) void k_pairbias(const float* __restrict__ pair,
                                                     const int* __restrict__ mask) {
    extern __shared__ __align__(16) float sp[];   // 2 buffers of [64][SPS]

    int tid = threadIdx.x, w = tid >> 5, lane = tid & 31;
    int lg = lane >> 2, lt = lane & 3;
    int r0 = w * 16 + lg;                         // warp w owns rows [16w,16w+16)

    uint32_t blo[32], bhi[32];
#pragma unroll
    for (int ks = 0; ks < 16; ks++) {
        blo[2 * ks]     = __float_as_uint(g_Wt[lg * PDx + ks * 8 + lt]);
        blo[2 * ks + 1] = __float_as_uint(g_Wt[lg * PDx + ks * 8 + lt + 4]);
        bhi[2 * ks]     = __float_as_uint(g_Wt[(8 + lg) * PDx + ks * 8 + lt]);
        bhi[2 * ks + 1] = __float_as_uint(g_Wt[(8 + lg) * PDx + ks * 8 + lt + 4]);
    }
    float shv[4], thv[4];
    {
        int hc[4] = {2 * lt, 2 * lt + 1, 8 + 2 * lt, 9 + 2 * lt};
#pragma unroll
        for (int q = 0; q < 4; q++) { shv[q] = g_sh[hc[q]]; thv[q] = g_th[hc[q]]; }
    }

    const int g = gridDim.x;

    {   // prologue: prefetch first tile into buffer 0
        int b, i, jt;
        size_t rb = pb_decode(blockIdx.x, b, i, jt);
        pb_stage(sp, pair + rb * (size_t)PDx, tid);
    }

    int parity = 0;
    for (int T = blockIdx.x; T < PB_TILES; T += g) {
        asm volatile("cp.async.wait_group 0;" ::: "memory");
        __syncthreads();

        int Tn = T + g;
        if (Tn < PB_TILES) {
            int b2, i2, jt2;
            size_t rb2 = pb_decode(Tn, b2, i2, jt2);
            pb_stage(sp + (parity ^ 1) * PB_TILE_F, pair + rb2 * (size_t)PDx, tid);
        }

        int b, i, jt;
        size_t rowbase = pb_decode(T, b, i, jt);
        const float* buf = sp + parity * PB_TILE_F;

        // split accumulator chains: even-ks / odd-ks (depth 8 each)
        float e0 = 0.f, e1 = 0.f, e2 = 0.f, e3 = 0.f;     // lo even
        float o0 = 0.f, o1 = 0.f, o2 = 0.f, o3 = 0.f;     // lo odd
        float E0 = 0.f, E1 = 0.f, E2 = 0.f, E3 = 0.f;     // hi even
        float O0 = 0.f, O1 = 0.f, O2 = 0.f, O3 = 0.f;     // hi odd
        float s0 = 0.f, ss0 = 0.f, s1 = 0.f, ss1 = 0.f;
        const float* Ab = buf + r0 * SPS + lt;
#pragma unroll
        for (int kp = 0; kp < 8; kp++) {
            {   // even ks = 2*kp
                int ks = 2 * kp;
                float a0 = Ab[ks * 8];
                float a1 = Ab[ks * 8 + 8 * SPS];
                float a2 = Ab[ks * 8 + 4];
                float a3 = Ab[ks * 8 + 8 * SPS + 4];
                s0 += a0 + a2;  ss0 += a0 * a0 + a2 * a2;
                s1 += a1 + a3;  ss1 += a1 * a1 + a3 * a3;
                uint32_t u0 = __float_as_uint(a0), u1 = __float_as_uint(a1);
                uint32_t u2 = __float_as_uint(a2), u3 = __float_as_uint(a3);
                mma_tf32(e0, e1, e2, e3, u0, u1, u2, u3, blo[2 * ks], blo[2 * ks + 1]);
                mma_tf32(E0, E1, E2, E3, u0, u1, u2, u3, bhi[2 * ks], bhi[2 * ks + 1]);
            }
            {   // odd ks = 2*kp+1
                int ks = 2 * kp + 1;
                float a0 = Ab[ks * 8];
                float a1 = Ab[ks * 8 + 8 * SPS];
                float a2 = Ab[ks * 8 + 4];
                float a3 = Ab[ks * 8 + 8 * SPS + 4];
                s0 += a0 + a2;  ss0 += a0 * a0 + a2 * a2;
                s1 += a1 + a3;  ss1 += a1 * a1 + a3 * a3;
                uint32_t u0 = __float_as_uint(a0), u1 = __float_as_uint(a1);
                uint32_t u2 = __float_as_uint(a2), u3 = __float_as_uint(a3);
                mma_tf32(o0, o1, o2, o3, u0, u1, u2, u3, blo[2 * ks], blo[2 * ks + 1]);
                mma_tf32(O0, O1, O2, O3, u0, u1, u2, u3, bhi[2 * ks], bhi[2 * ks + 1]);
            }
        }
        float c0 = e0 + o0, c1 = e1 + o1, c2 = e2 + o2, c3 = e3 + o3;
        float c4v = E0 + O0, c5 = E1 + O1, c6 = E2 + O2, c7 = E3 + O3;

        s0  += __shfl_xor_sync(~0u, s0, 1);   s0  += __shfl_xor_sync(~0u, s0, 2);
        ss0 += __shfl_xor_sync(~0u, ss0, 1);  ss0 += __shfl_xor_sync(~0u, ss0, 2);
        s1  += __shfl_xor_sync(~0u, s1, 1);   s1  += __shfl_xor_sync(~0u, s1, 2);
        ss1 += __shfl_xor_sync(~0u, ss1, 1);  ss1 += __shfl_xor_sync(~0u, ss1, 2);
        float m0 = s0 * (1.0f / PDx);
        float r0s = rsqrtf(ss0 * (1.0f / PDx) - m0 * m0 + LN_EPS);
        float m1 = s1 * (1.0f / PDx);
        float r1s = rsqrtf(ss1 * (1.0f / PDx) - m1 * m1 + LN_EPS);

        int mk0 = mask[rowbase + r0];
        int mk1 = mask[rowbase + r0 + 8];

        size_t pb0 = (((size_t)(b * HHx) * NNx + i)) * NNx + jt * PB_TR;
        float rm0 = r0s * m0, rm1 = r1s * m1;
        float vals[8] = {
            r0s * c0  - rm0 * shv[0] + thv[0],
            r0s * c1  - rm0 * shv[1] + thv[1],
            r1s * c2  - rm1 * shv[0] + thv[0],
            r1s * c3  - rm1 * shv[1] + thv[1],
            r0s * c4v - rm0 * shv[2] + thv[2],
            r0s * c5  - rm0 * shv[3] + thv[3],
            r1s * c6  - rm1 * shv[2] + thv[2],
            r1s * c7  - rm1 * shv[3] + thv[3],
        };
        if (mk0 == 0) { vals[0] = NEG_INFx; vals[1] = NEG_INFx; vals[4] = NEG_INFx; vals[5] = NEG_INFx; }
        if (mk1 == 0) { vals[2] = NEG_INFx; vals[3] = NEG_INFx; vals[6] = NEG_INFx; vals[7] = NEG_INFx; }
        int hcol[4] = {2 * lt, 2 * lt + 1, 8 + 2 * lt, 9 + 2 * lt};
        size_t plane = (size_t)NNx * NNx;
        g_bias[pb0 + hcol[0] * plane + r0]     = vals[0];
        g_bias[pb0 + hcol[1] * plane + r0]     = vals[1];
        g_bias[pb0 + hcol[0] * plane + r0 + 8] = vals[2];
        g_bias[pb0 + hcol[1] * plane + r0 + 8] = vals[3];
        g_bias[pb0 + hcol[2] * plane + r0]     = vals[4];
        g_bias[pb0 + hcol[3] * plane + r0]     = vals[5];
        g_bias[pb0 + hcol[2] * plane + r0 + 8] = vals[6];
        g_bias[pb0 + hcol[3] * plane + r0 + 8] = vals[7];

        parity ^= 1;
    }
}

// ---------------- K5: attention — QK column-owned, softmax/AV row-owned ----------------
__global__ void k_attn() {
    __shared__ __align__(16) float S[12][NNx];     // 36864 B
    __shared__ __align__(16) u64 qp2[12][16];      //  1536 B  q packed {2d,2d+1}
    int i0 = blockIdx.x * 12;
    int h = blockIdx.y, b = blockIdx.z;
    int tid = threadIdx.x;
    int w = tid >> 5, lane = tid & 31;
    size_t bhbase = (size_t)(b * HHx + h) * NNx;

    if (tid < 192) {
        int r = tid >> 4, dp = tid & 15;
        const float* qrow = g_qh + (bhbase + i0 + r) * DHx + 2 * dp;
        float2 qv = *(const float2*)qrow;
        qp2[r][dp] = pack2(qv.x, qv.y);
    }
    __syncthreads();

    const float scale = 0.17677669529663687f;   // 1/sqrt(32)
    const float* kT = g_khT + (size_t)(b * HHx + h) * DHx * NNx;

    // ---- QK^T: warp w owns j-chunk w (128 j); accumulates all 12 rows ----
    {
        int jb = w * 128 + lane * 4;
        const float* kTc = kT + jb;
        u64 acc[12][2];
#pragma unroll
        for (int r = 0; r < 12; r++) { acc[r][0] = 0; acc[r][1] = 0; }

#pragma unroll
        for (int dg = 0; dg < 4; dg++) {
            u64 kx[8][2];
#pragma unroll
            for (int dd = 0; dd < 8; dd++) {
                ulonglong2 kv = *(const ulonglong2*)&kTc[(size_t)(dg * 8 + dd) * NNx];
                kx[dd][0] = kv.x; kx[dd][1] = kv.y;
            }
#pragma unroll
            for (int r = 0; r < 12; r++) {
#pragma unroll
                for (int dd = 0; dd < 4; dd++) {
                    float2 q = up2(qp2[r][dg * 4 + dd]);
                    u64 q0 = splat2(q.x), q1 = splat2(q.y);
                    ffma2(acc[r][0], kx[2 * dd][0], q0);
                    ffma2(acc[r][1], kx[2 * dd][1], q0);
                    ffma2(acc[r][0], kx[2 * dd + 1][0], q1);
                    ffma2(acc[r][1], kx[2 * dd + 1][1], q1);
                }
            }
        }

#pragma unroll
        for (int r = 0; r < 12; r++) {
            float4 bb = *(const float4*)&g_bias[(bhbase + i0 + r) * NNx + jb];
            float2 sx = up2(acc[r][0]), sy = up2(acc[r][1]);
            float4 out = {sx.x * scale + bb.x, sx.y * scale + bb.y,
                          sy.x * scale + bb.z, sy.y * scale + bb.w};
            *(float4*)&S[r][jb] = out;
        }
    }
    __syncthreads();

    // ---- softmax: warp w owns rows 2w, 2w+1 ----
    int il0 = 2 * w, il1 = 2 * w + 1;
    int iA = i0 + il0, iB = i0 + il1;
    float inv0, inv1;
#pragma unroll
    for (int rr = 0; rr < 2; rr++) {
        float* Sr = (rr == 0) ? &S[il0][0] : &S[il1][0];
        float mx = -3.4e38f;
        for (int c = lane; c < NNx; c += 32) mx = fmaxf(mx, Sr[c]);
#pragma unroll
        for (int o = 16; o > 0; o >>= 1) mx = fmaxf(mx, __shfl_xor_sync(~0u, mx, o));
        float sum = 0.f;
        for (int c = lane; c < NNx; c += 32) {
            float e = __expf(Sr[c] - mx);
            Sr[c] = e;
            sum += e;
        }
#pragma unroll
        for (int o = 16; o > 0; o >>= 1) sum += __shfl_xor_sync(~0u, sum, o);
        if (rr == 0) inv0 = 1.0f / sum; else inv1 = 1.0f / sum;
    }
    __syncwarp();

    // ---- AV: lane = (half, d-pair); half-warps split j ----
    int half = lane >> 4;
    int dp = (lane & 15) * 2;
    const float* vbase = g_vh + bhbase * DHx;
    float a00 = 0.f, a01 = 0.f, a10 = 0.f, a11 = 0.f;
    int jb = half * (NNx / 2);
    for (int jj = 0; jj < NNx / 2; jj += 4) {
        int j = jb + jj;
        float4 pA = *(const float4*)&S[il0][j];
        float4 pB = *(const float4*)&S[il1][j];
        const float* vp = vbase + (size_t)j * DHx + dp;
        float2 v0 = *(const float2*)(vp);
        float2 v1 = *(const float2*)(vp + 32);
        float2 v2 = *(const float2*)(vp + 64);
        float2 v3 = *(const float2*)(vp + 96);
        a00 += pA.x * v0.x + pA.y * v1.x + pA.z * v2.x + pA.w * v3.x;
        a01 += pA.x * v0.y + pA.y * v1.y + pA.z * v2.y + pA.w * v3.y;
        a10 += pB.x * v0.x + pB.y * v1.x + pB.z * v2.x + pB.w * v3.x;
        a11 += pB.x * v0.y + pB.y * v1.y + pB.z * v2.y + pB.w * v3.y;
    }
    a00 += __shfl_down_sync(~0u, a00, 16);
    a01 += __shfl_down_sync(~0u, a01, 16);
    a10 += __shfl_down_sync(~0u, a10, 16);
    a11 += __shfl_down_sync(~0u, a11, 16);

    if (half == 0) {
        size_t bnA = (size_t)b * NNx + iA;
        size_t bnB = (size_t)b * NNx + iB;
        float2 gA = *(const float2*)&g_qkvg[bnA * 2048 + 1536 + h * DHx + dp];
        float2 gB = *(const float2*)&g_qkvg[bnB * 2048 + 1536 + h * DHx + dp];
        float2 oA, oB;
        oA.x = a00 * inv0 * (1.0f / (1.0f + __expf(-gA.x)));
        oA.y = a01 * inv0 * (1.0f / (1.0f + __expf(-gA.y)));
        oB.x = a10 * inv1 * (1.0f / (1.0f + __expf(-gB.x)));
        oB.y = a11 * inv1 * (1.0f / (1.0f + __expf(-gB.y)));
        *(float2*)&g_og[bnA * INNERx + h * DHx + dp] = oA;
        *(float2*)&g_og[bnB * INNERx + h * DHx + dp] = oB;
    }
}

// ---------------- launch ----------------
extern "C" void kernel_launch(void* const* d_in, const int* in_sizes, int n_in,
                              void* d_out, int out_size) {
    const float* node = (const float*)d_in[0];
    const float* pair = (const float*)d_in[1];
    const int*   mask = (const int*)d_in[2];
    const float* nnw  = (const float*)d_in[3];
    const float* nnb  = (const float*)d_in[4];
    const float* qkvw = (const float*)d_in[5];
    const float* qkvb = (const float*)d_in[6];
    const float* gw   = (const float*)d_in[7];
    const float* gb   = (const float*)d_in[8];
    const float* qlw  = (const float*)d_in[9];
    const float* qlb  = (const float*)d_in[10];
    const float* klw  = (const float*)d_in[11];
    const float* klb  = (const float*)d_in[12];
    const float* pnw  = (const float*)d_in[13];
    const float* pnb  = (const float*)d_in[14];
    const float* bw   = (const float*)d_in[15];
    const float* ow   = (const float*)d_in[16];
    const float* ob   = (const float*)d_in[17];
    float* out = (float*)d_out;

    cudaFuncSetAttribute(k_pairbias, cudaFuncAttributeMaxDynamicSharedMemorySize, PB_SMEM);

    k_prep<<<1, 256>>>(bw, pnw, pnb);
    k_ln_node<<<BB * NNx, 256>>>(node, nnw, nnb);
    k_gemm_tc<0><<<dim3(2048 / 64, (BB * NNx) / 128), 256>>>(qkvw, gw, qkvb, gb, nullptr);
    k_pairbias<<<444, 128, PB_SMEM>>>(pair, mask);
    k_lnqk<<<BB * NNx, 256>>>(qlw, qlb, klw, klb);
    k_attn<<<dim3(NNx / 12, HHx, BB), 192>>>();
    k_gemm_tc<1><<<dim3(512 / 64, (BB * NNx) / 128), 256>>>(ow, ow, ob, ob, out);
}

// round 12
// speedup vs baseline: 2.7721x; 1.0785x over previous
#include <cuda_runtime.h>
#include <cuda_fp16.h>
#include <cstdint>

#define BB 2
#define NNx 768
#define DDx 512
#define HHx 16
#define DHx 32
#define INNERx 512
#define PDx 128
#define NEG_INFx -10000.0f
#define LN_EPS 1e-5f

typedef unsigned long long u64;

// ---------------- f32x2 packed-math helpers (exact fp32 semantics) ----------------
__device__ __forceinline__ void ffma2(u64& d, u64 a, u64 b) {
    asm("fma.rn.f32x2 %0, %1, %2, %0;" : "+l"(d) : "l"(a), "l"(b));
}
__device__ __forceinline__ float2 up2(u64 v) {
    float2 f;
    asm("mov.b64 {%0, %1}, %2;" : "=f"(f.x), "=f"(f.y) : "l"(v));
    return f;
}
__device__ __forceinline__ u64 pack2(float x, float y) {
    u64 r;
    asm("mov.b64 %0, {%1, %2};" : "=l"(r) : "f"(x), "f"(y));
    return r;
}
__device__ __forceinline__ u64 splat2(float x) {
    u64 r;
    asm("mov.b64 %0, {%1, %1};" : "=l"(r) : "f"(x));
    return r;
}
__device__ __forceinline__ uint32_t f2tf32(float f) {
    uint32_t r;
    asm("cvt.rna.tf32.f32 %0, %1;" : "=r"(r) : "f"(f));
    return r;
}
__device__ __forceinline__ void mma_tf32(float& c0, float& c1, float& c2, float& c3,
                                         uint32_t a0, uint32_t a1, uint32_t a2, uint32_t a3,
                                         uint32_t b0, uint32_t b1) {
    asm("mma.sync.aligned.m16n8k8.row.col.f32.tf32.tf32.f32 "
        "{%0,%1,%2,%3}, {%4,%5,%6,%7}, {%8,%9}, {%0,%1,%2,%3};"
        : "+f"(c0), "+f"(c1), "+f"(c2), "+f"(c3)
        : "r"(a0), "r"(a1), "r"(a2), "r"(a3), "r"(b0), "r"(b1));
}

// ---------------- scratch (static device memory: allowed) ----------------
__device__ float g_x[BB * NNx * DDx];
__device__ float g_qkvg[BB * NNx * 2048];                  // [q|k|v|g]
__device__ float g_qh[BB * HHx * NNx * DHx];               // q [b][h][n][d]
__device__ float g_khT[BB * HHx * DHx * NNx];              // k [b][h][d][n]  (transposed)
__device__ float g_vh[BB * HHx * NNx * DHx];               // v [b][h][n][d]
__device__ __half g_bias[(size_t)BB * HHx * NNx * NNx];    // masked bias (fp16, 37.7 MB)
__device__ float g_og[BB * NNx * INNERx];
__device__ float g_Wt[HHx * PDx];                          // tf32-rounded W'[h][e]
__device__ float g_sh[HHx];
__device__ float g_th[HHx];

// ---------------- K0: fold pair-LN affine into projection weights ----------------
__global__ void k_prep(const float* __restrict__ bias_w,
                       const float* __restrict__ pnw,
                       const float* __restrict__ pnb) {
    int t = threadIdx.x;
    for (int idx = t; idx < HHx * PDx; idx += blockDim.x) {
        int h = idx >> 7, e = idx & 127;
        uint32_t tv = f2tf32(pnw[e] * bias_w[e * HHx + h]);
        g_Wt[idx] = __uint_as_float(tv);
    }
    if (t < HHx) {
        float s = 0.f, tt = 0.f;
        for (int e = 0; e < PDx; e++) {
            s  += pnw[e] * bias_w[e * HHx + t];
            tt += pnb[e] * bias_w[e * HHx + t];
        }
        g_sh[t] = s;
        g_th[t] = tt;
    }
}

// ---------------- K1: node LayerNorm ----------------
__global__ void k_ln_node(const float* __restrict__ nf,
                          const float* __restrict__ w,
                          const float* __restrict__ bp) {
    int row = blockIdx.x;
    const float* in = nf + (size_t)row * DDx;
    float s = 0.f, ss = 0.f;
    for (int c = threadIdx.x; c < DDx; c += 256) {
        float t = in[c];
        s += t; ss += t * t;
    }
#pragma unroll
    for (int o = 16; o > 0; o >>= 1) {
        s  += __shfl_xor_sync(~0u, s, o);
        ss += __shfl_xor_sync(~0u, ss, o);
    }
    __shared__ float red[16];
    int wid = threadIdx.x >> 5, lid = threadIdx.x & 31;
    if (lid == 0) { red[wid] = s; red[8 + wid] = ss; }
    __syncthreads();
    __shared__ float sm, sr;
    if (threadIdx.x == 0) {
        float S = 0.f, SS = 0.f;
        for (int i = 0; i < 8; i++) { S += red[i]; SS += red[8 + i]; }
        float m = S / DDx;
        sm = m;
        sr = rsqrtf(SS / DDx - m * m + LN_EPS);
    }
    __syncthreads();
    float m = sm, r = sr;
    for (int c = threadIdx.x; c < DDx; c += 256)
        g_x[(size_t)row * DDx + c] = (in[c] - m) * r * w[c] + bp[c];
}

// ---------------- K2/K6: dense GEMM on tensor pipe (tf32 mma, double-buffered) ----------------
#define AST 20
#define BST 72
template<int MODE>
__global__ void k_gemm_tc(const float* __restrict__ B1, const float* __restrict__ B2,
                          const float* __restrict__ bias1, const float* __restrict__ bias2,
                          float* __restrict__ Cext) {
    constexpr int LDC   = (MODE == 0) ? 2048 : 512;
    constexpr int SPLIT = (MODE == 0) ? 1536 : (1 << 30);
    constexpr int LD1   = (MODE == 0) ? 1536 : 512;
    constexpr int LD2   = 512;

    const float* A = (MODE == 0) ? g_x : g_og;
    float* C = (MODE == 0) ? g_qkvg : Cext;

    __shared__ __align__(16) float As[2][128 * AST];
    __shared__ __align__(16) float Bs[2][16 * BST];

    int bm = blockIdx.y * 128, bn = blockIdx.x * 64;
    int tid = threadIdx.x, w = tid >> 5, lane = tid & 31;
    int wm = w >> 1, wn = w & 1;
    int lg = lane >> 2, lt = lane & 3;

    float acc[2][4][4] = {};

    int mS = tid >> 1, segS = (tid & 1) * 8;
    int kS = tid >> 4, nS = (tid & 15) * 4;
    int ncol = bn + nS;
    const float* bsrc = (ncol < SPLIT) ? (B1 + ncol) : (B2 + (ncol - SPLIT));
    int ldb = (ncol < SPLIT) ? LD1 : LD2;
    const float* aS = A + (size_t)(bm + mS) * 512 + segS;

    float4 ra0, ra1, rb;
    ra0 = *(const float4*)(aS);
    ra1 = *(const float4*)(aS + 4);
    rb  = *(const float4*)&bsrc[(size_t)kS * ldb];
    {
        uint4 t0 = {f2tf32(ra0.x), f2tf32(ra0.y), f2tf32(ra0.z), f2tf32(ra0.w)};
        uint4 t1 = {f2tf32(ra1.x), f2tf32(ra1.y), f2tf32(ra1.z), f2tf32(ra1.w)};
        uint4 tb = {f2tf32(rb.x),  f2tf32(rb.y),  f2tf32(rb.z),  f2tf32(rb.w)};
        *(uint4*)&As[0][mS * AST + segS]     = t0;
        *(uint4*)&As[0][mS * AST + segS + 4] = t1;
        *(uint4*)&Bs[0][kS * BST + nS]       = tb;
    }
    __syncthreads();

    for (int k0 = 0; k0 < 512; k0 += 16) {
        int cur = (k0 >> 4) & 1;
        bool more = (k0 + 16) < 512;
        if (more) {
            ra0 = *(const float4*)(aS + k0 + 16);
            ra1 = *(const float4*)(aS + k0 + 20);
            rb  = *(const float4*)&bsrc[(size_t)(k0 + 16 + kS) * ldb];
        }

#pragma unroll
        for (int ks = 0; ks < 2; ks++) {
            uint32_t af[2][4];
            const float* ab = &As[cur][(wm * 32 + lg) * AST + ks * 8 + lt];
#pragma unroll
            for (int mf = 0; mf < 2; mf++) {
                const float* a = ab + mf * 16 * AST;
                af[mf][0] = __float_as_uint(a[0]);
                af[mf][1] = __float_as_uint(a[8 * AST]);
                af[mf][2] = __float_as_uint(a[4]);
                af[mf][3] = __float_as_uint(a[8 * AST + 4]);
            }
            uint32_t bf[4][2];
            const float* bb = &Bs[cur][(ks * 8 + lt) * BST + wn * 32 + lg];
#pragma unroll
            for (int nf = 0; nf < 4; nf++) {
                bf[nf][0] = __float_as_uint(bb[nf * 8]);
                bf[nf][1] = __float_as_uint(bb[4 * BST + nf * 8]);
            }
#pragma unroll
            for (int mf = 0; mf < 2; mf++)
#pragma unroll
                for (int nf = 0; nf < 4; nf++)
                    mma_tf32(acc[mf][nf][0], acc[mf][nf][1], acc[mf][nf][2], acc[mf][nf][3],
                             af[mf][0], af[mf][1], af[mf][2], af[mf][3],
                             bf[nf][0], bf[nf][1]);
        }

        if (more) {
            int nxt = cur ^ 1;
            uint4 t0 = {f2tf32(ra0.x), f2tf32(ra0.y), f2tf32(ra0.z), f2tf32(ra0.w)};
            uint4 t1 = {f2tf32(ra1.x), f2tf32(ra1.y), f2tf32(ra1.z), f2tf32(ra1.w)};
            uint4 tb = {f2tf32(rb.x),  f2tf32(rb.y),  f2tf32(rb.z),  f2tf32(rb.w)};
            *(uint4*)&As[nxt][mS * AST + segS]     = t0;
            *(uint4*)&As[nxt][mS * AST + segS + 4] = t1;
            *(uint4*)&Bs[nxt][kS * BST + nS]       = tb;
        }
        __syncthreads();
    }

#pragma unroll
    for (int mf = 0; mf < 2; mf++) {
#pragma unroll
        for (int nf = 0; nf < 4; nf++) {
            int r = bm + wm * 32 + mf * 16 + lg;
            int c = bn + wn * 32 + nf * 8 + 2 * lt;
            float bi0 = (c < SPLIT) ? bias1[c] : bias2[c - SPLIT];
            float bi1 = (c + 1 < SPLIT) ? bias1[c + 1] : bias2[c + 1 - SPLIT];
            float2 v0 = {acc[mf][nf][0] + bi0, acc[mf][nf][1] + bi1};
            float2 v1 = {acc[mf][nf][2] + bi0, acc[mf][nf][3] + bi1};
            *(float2*)&C[(size_t)r * LDC + c]       = v0;
            *(float2*)&C[(size_t)(r + 8) * LDC + c] = v1;
        }
    }
}

// ---------------- K3: q/k LN over INNER; q,v head-major, k TRANSPOSED ----------------
__global__ void k_lnqk(const float* __restrict__ qw, const float* __restrict__ qb,
                       const float* __restrict__ kw, const float* __restrict__ kb) {
    int bn = blockIdx.x;
    const float* row = g_qkvg + (size_t)bn * 2048;
    int b = bn / NNx, nn = bn % NNx;
    float s1 = 0.f, ss1 = 0.f, s2 = 0.f, ss2 = 0.f;
    for (int c = threadIdx.x; c < 512; c += 256) {
        float a = row[c], b2 = row[512 + c];
        s1 += a; ss1 += a * a; s2 += b2; ss2 += b2 * b2;
    }
#pragma unroll
    for (int o = 16; o > 0; o >>= 1) {
        s1  += __shfl_xor_sync(~0u, s1, o);  ss1 += __shfl_xor_sync(~0u, ss1, o);
        s2  += __shfl_xor_sync(~0u, s2, o);  ss2 += __shfl_xor_sync(~0u, ss2, o);
    }
    __shared__ float red[4][8];
    int w = threadIdx.x >> 5, lane = threadIdx.x & 31;
    if (lane == 0) { red[0][w] = s1; red[1][w] = ss1; red[2][w] = s2; red[3][w] = ss2; }
    __syncthreads();
    __shared__ float st[4];
    if (threadIdx.x == 0) {
        float a = 0.f, bb = 0.f, c = 0.f, d = 0.f;
        for (int i = 0; i < 8; i++) { a += red[0][i]; bb += red[1][i]; c += red[2][i]; d += red[3][i]; }
        float m1 = a / 512.f, m2 = c / 512.f;
        st[0] = m1; st[1] = rsqrtf(bb / 512.f - m1 * m1 + LN_EPS);
        st[2] = m2; st[3] = rsqrtf(d / 512.f - m2 * m2 + LN_EPS);
    }
    __syncthreads();
    float m1 = st[0], r1 = st[1], m2 = st[2], r2 = st[3];
    for (int c = threadIdx.x; c < 512; c += 256) {
        int h = c >> 5, d = c & 31;
        size_t oidx  = (((size_t)(b * HHx + h)) * NNx + nn) * DHx + d;     // [b][h][n][d]
        size_t oidxT = (((size_t)(b * HHx + h)) * DHx + d) * NNx + nn;     // [b][h][d][n]
        g_qh[oidx]   = (row[c]       - m1) * r1 * qw[c] + qb[c];
        g_khT[oidxT] = (row[512 + c] - m2) * r2 * kw[c] + kb[c];
        g_vh[oidx]   = row[1024 + c];
    }
}

// ---------------- K4: pair bias — persistent, 64-row tiles, 3 CTAs/SM, split chains ----------------
#define SPS 132
#define PB_TR 64
#define PB_TILES (BB * NNx * 12)                 // 18432
#define PB_TILE_F (PB_TR * SPS)
#define PB_SMEM  (2 * PB_TILE_F * 4)             // 67584 B
__device__ __forceinline__ size_t pb_decode(int T, int& b, int& i, int& jt) {
    b = T / (NNx * 12);
    int rem = T - b * (NNx * 12);
    i = rem / 12;
    jt = rem - i * 12;
    return ((size_t)(b * NNx + i)) * NNx + jt * PB_TR;
}
__device__ __forceinline__ void pb_stage(float* buf, const float* pb, int tid) {
#pragma unroll
    for (int it = 0; it < 16; it++) {
        int f = tid + it * 128;
        int r = f >> 5, c4 = (f & 31) << 2;
        unsigned sa = (unsigned)__cvta_generic_to_shared(buf + r * SPS + c4);
        const float* ga = pb + (size_t)r * PDx + c4;
        asm volatile("cp.async.cg.shared.global [%0], [%1], 16;" :: "r"(sa), "l"(ga));
    }
    asm volatile("cp.async.commit_group;");
}
__global__ __launch_bounds__(128, 3) void k_pairbias(const float* __restrict__ pair,
                                                     const int* __restrict__ mask) {
    extern __shared__ __align__(16) float sp[];

    int tid = threadIdx.x, w = tid >> 5, lane = tid & 31;
    int lg = lane >> 2, lt = lane & 3;
    int r0 = w * 16 + lg;

    uint32_t blo[32], bhi[32];
#pragma unroll
    for (int ks = 0; ks < 16; ks++) {
        blo[2 * ks]     = __float_as_uint(g_Wt[lg * PDx + ks * 8 + lt]);
        blo[2 * ks + 1] = __float_as_uint(g_Wt[lg * PDx + ks * 8 + lt + 4]);
        bhi[2 * ks]     = __float_as_uint(g_Wt[(8 + lg) * PDx + ks * 8 + lt]);
        bhi[2 * ks + 1] = __float_as_uint(g_Wt[(8 + lg) * PDx + ks * 8 + lt + 4]);
    }
    float shv[4], thv[4];
    {
        int hc[4] = {2 * lt, 2 * lt + 1, 8 + 2 * lt, 9 + 2 * lt};
#pragma unroll
        for (int q = 0; q < 4; q++) { shv[q] = g_sh[hc[q]]; thv[q] = g_th[hc[q]]; }
    }

    const int g = gridDim.x;

    {
        int b, i, jt;
        size_t rb = pb_decode(blockIdx.x, b, i, jt);
        pb_stage(sp, pair + rb * (size_t)PDx, tid);
    }

    int parity = 0;
    for (int T = blockIdx.x; T < PB_TILES; T += g) {
        asm volatile("cp.async.wait_group 0;" ::: "memory");
        __syncthreads();

        int Tn = T + g;
        if (Tn < PB_TILES) {
            int b2, i2, jt2;
            size_t rb2 = pb_decode(Tn, b2, i2, jt2);
            pb_stage(sp + (parity ^ 1) * PB_TILE_F, pair + rb2 * (size_t)PDx, tid);
        }

        int b, i, jt;
        size_t rowbase = pb_decode(T, b, i, jt);
        const float* buf = sp + parity * PB_TILE_F;

        float e0 = 0.f, e1 = 0.f, e2 = 0.f, e3 = 0.f;
        float o0 = 0.f, o1 = 0.f, o2 = 0.f, o3 = 0.f;
        float E0 = 0.f, E1 = 0.f, E2 = 0.f, E3 = 0.f;
        float O0 = 0.f, O1 = 0.f, O2 = 0.f, O3 = 0.f;
        float s0 = 0.f, ss0 = 0.f, s1 = 0.f, ss1 = 0.f;
        const float* Ab = buf + r0 * SPS + lt;
#pragma unroll
        for (int kp = 0; kp < 8; kp++) {
            {
                int ks = 2 * kp;
                float a0 = Ab[ks * 8];
                float a1 = Ab[ks * 8 + 8 * SPS];
                float a2 = Ab[ks * 8 + 4];
                float a3 = Ab[ks * 8 + 8 * SPS + 4];
                s0 += a0 + a2;  ss0 += a0 * a0 + a2 * a2;
                s1 += a1 + a3;  ss1 += a1 * a1 + a3 * a3;
                uint32_t u0 = __float_as_uint(a0), u1 = __float_as_uint(a1);
                uint32_t u2 = __float_as_uint(a2), u3 = __float_as_uint(a3);
                mma_tf32(e0, e1, e2, e3, u0, u1, u2, u3, blo[2 * ks], blo[2 * ks + 1]);
                mma_tf32(E0, E1, E2, E3, u0, u1, u2, u3, bhi[2 * ks], bhi[2 * ks + 1]);
            }
            {
                int ks = 2 * kp + 1;
                float a0 = Ab[ks * 8];
                float a1 = Ab[ks * 8 + 8 * SPS];
                float a2 = Ab[ks * 8 + 4];
                float a3 = Ab[ks * 8 + 8 * SPS + 4];
                s0 += a0 + a2;  ss0 += a0 * a0 + a2 * a2;
                s1 += a1 + a3;  ss1 += a1 * a1 + a3 * a3;
                uint32_t u0 = __float_as_uint(a0), u1 = __float_as_uint(a1);
                uint32_t u2 = __float_as_uint(a2), u3 = __float_as_uint(a3);
                mma_tf32(o0, o1, o2, o3, u0, u1, u2, u3, blo[2 * ks], blo[2 * ks + 1]);
                mma_tf32(O0, O1, O2, O3, u0, u1, u2, u3, bhi[2 * ks], bhi[2 * ks + 1]);
            }
        }
        float c0 = e0 + o0, c1 = e1 + o1, c2 = e2 + o2, c3 = e3 + o3;
        float c4v = E0 + O0, c5 = E1 + O1, c6 = E2 + O2, c7 = E3 + O3;

        s0  += __shfl_xor_sync(~0u, s0, 1);   s0  += __shfl_xor_sync(~0u, s0, 2);
        ss0 += __shfl_xor_sync(~0u, ss0, 1);  ss0 += __shfl_xor_sync(~0u, ss0, 2);
        s1  += __shfl_xor_sync(~0u, s1, 1);   s1  += __shfl_xor_sync(~0u, s1, 2);
        ss1 += __shfl_xor_sync(~0u, ss1, 1);  ss1 += __shfl_xor_sync(~0u, ss1, 2);
        float m0 = s0 * (1.0f / PDx);
        float r0s = rsqrtf(ss0 * (1.0f / PDx) - m0 * m0 + LN_EPS);
        float m1 = s1 * (1.0f / PDx);
        float r1s = rsqrtf(ss1 * (1.0f / PDx) - m1 * m1 + LN_EPS);

        int mk0 = mask[rowbase + r0];
        int mk1 = mask[rowbase + r0 + 8];

        size_t pb0 = (((size_t)(b * HHx) * NNx + i)) * NNx + jt * PB_TR;
        float rm0 = r0s * m0, rm1 = r1s * m1;
        float vals[8] = {
            r0s * c0  - rm0 * shv[0] + thv[0],
            r0s * c1  - rm0 * shv[1] + thv[1],
            r1s * c2  - rm1 * shv[0] + thv[0],
            r1s * c3  - rm1 * shv[1] + thv[1],
            r0s * c4v - rm0 * shv[2] + thv[2],
            r0s * c5  - rm0 * shv[3] + thv[3],
            r1s * c6  - rm1 * shv[2] + thv[2],
            r1s * c7  - rm1 * shv[3] + thv[3],
        };
        if (mk0 == 0) { vals[0] = NEG_INFx; vals[1] = NEG_INFx; vals[4] = NEG_INFx; vals[5] = NEG_INFx; }
        if (mk1 == 0) { vals[2] = NEG_INFx; vals[3] = NEG_INFx; vals[6] = NEG_INFx; vals[7] = NEG_INFx; }
        int hcol[4] = {2 * lt, 2 * lt + 1, 8 + 2 * lt, 9 + 2 * lt};
        size_t plane = (size_t)NNx * NNx;
        g_bias[pb0 + hcol[0] * plane + r0]     = __float2half_rn(vals[0]);
        g_bias[pb0 + hcol[1] * plane + r0]     = __float2half_rn(vals[1]);
        g_bias[pb0 + hcol[0] * plane + r0 + 8] = __float2half_rn(vals[2]);
        g_bias[pb0 + hcol[1] * plane + r0 + 8] = __float2half_rn(vals[3]);
        g_bias[pb0 + hcol[2] * plane + r0]     = __float2half_rn(vals[4]);
        g_bias[pb0 + hcol[3] * plane + r0]     = __float2half_rn(vals[5]);
        g_bias[pb0 + hcol[2] * plane + r0 + 8] = __float2half_rn(vals[6]);
        g_bias[pb0 + hcol[3] * plane + r0 + 8] = __float2half_rn(vals[7]);

        parity ^= 1;
    }
}

// ---------------- K5: attention — QK & AV column-owned, softmax row-owned ----------------
__global__ void k_attn() {
    __shared__ __align__(16) float S[12][NNx];     // 36864 B
    __shared__ __align__(16) u64 qp2[12][16];      //  1536 B
    __shared__ float part[6][12][32];              //  9216 B  per-warp AV partials
    __shared__ float invs[12];
    int i0 = blockIdx.x * 12;
    int h = blockIdx.y, b = blockIdx.z;
    int tid = threadIdx.x;
    int w = tid >> 5, lane = tid & 31;
    size_t bhbase = (size_t)(b * HHx + h) * NNx;

    if (tid < 192) {
        int r = tid >> 4, dp = tid & 15;
        const float* qrow = g_qh + (bhbase + i0 + r) * DHx + 2 * dp;
        float2 qv = *(const float2*)qrow;
        qp2[r][dp] = pack2(qv.x, qv.y);
    }
    __syncthreads();

    const float scale = 0.17677669529663687f;   // 1/sqrt(32)
    const float* kT = g_khT + (size_t)(b * HHx + h) * DHx * NNx;

    // ---- QK^T: warp w owns j-chunk w (128 j); accumulates all 12 rows ----
    {
        int jb = w * 128 + lane * 4;
        const float* kTc = kT + jb;
        u64 acc[12][2];
#pragma unroll
        for (int r = 0; r < 12; r++) { acc[r][0] = 0; acc[r][1] = 0; }

#pragma unroll
        for (int dg = 0; dg < 4; dg++) {
            u64 kx[8][2];
#pragma unroll
            for (int dd = 0; dd < 8; dd++) {
                ulonglong2 kv = *(const ulonglong2*)&kTc[(size_t)(dg * 8 + dd) * NNx];
                kx[dd][0] = kv.x; kx[dd][1] = kv.y;
            }
#pragma unroll
            for (int r = 0; r < 12; r++) {
#pragma unroll
                for (int dd = 0; dd < 4; dd++) {
                    float2 q = up2(qp2[r][dg * 4 + dd]);
                    u64 q0 = splat2(q.x), q1 = splat2(q.y);
                    ffma2(acc[r][0], kx[2 * dd][0], q0);
                    ffma2(acc[r][1], kx[2 * dd][1], q0);
                    ffma2(acc[r][0], kx[2 * dd + 1][0], q1);
                    ffma2(acc[r][1], kx[2 * dd + 1][1], q1);
                }
            }
        }

#pragma unroll
        for (int r = 0; r < 12; r++) {
            const __half* brow = g_bias + (bhbase + i0 + r) * NNx + jb;
            __half2 b01 = *(const __half2*)(brow);
            __half2 b23 = *(const __half2*)(brow + 2);
            float2 f01 = __half22float2(b01), f23 = __half22float2(b23);
            float2 sx = up2(acc[r][0]), sy = up2(acc[r][1]);
            float4 out = {sx.x * scale + f01.x, sx.y * scale + f01.y,
                          sy.x * scale + f23.x, sy.y * scale + f23.y};
            *(float4*)&S[r][jb] = out;
        }
    }
    __syncthreads();

    // ---- softmax: warp w owns rows 2w, 2w+1 ----
    {
        int il0 = 2 * w, il1 = 2 * w + 1;
        float inv0 = 0.f, inv1 = 0.f;
#pragma unroll
        for (int rr = 0; rr < 2; rr++) {
            float* Sr = (rr == 0) ? &S[il0][0] : &S[il1][0];
            float mx = -3.4e38f;
            for (int c = lane; c < NNx; c += 32) mx = fmaxf(mx, Sr[c]);
#pragma unroll
            for (int o = 16; o > 0; o >>= 1) mx = fmaxf(mx, __shfl_xor_sync(~0u, mx, o));
            float sum = 0.f;
            for (int c = lane; c < NNx; c += 32) {
                float e = __expf(Sr[c] - mx);
                Sr[c] = e;
                sum += e;
            }
#pragma unroll
            for (int o = 16; o > 0; o >>= 1) sum += __shfl_xor_sync(~0u, sum, o);
            if (rr == 0) inv0 = 1.0f / sum; else inv1 = 1.0f / sum;
        }
        if (lane == 0) { invs[il0] = inv0; invs[il1] = inv1; }
    }
    __syncthreads();

    // ---- AV column-owned: warp w owns j-chunk w; partials for all 12 rows ----
    {
        int dp = lane & 15, jh = lane >> 4;
        int jb = w * 128 + jh * 64;
        const float* vbase = g_vh + bhbase * DHx + 2 * dp;
        float acc[12][2];
#pragma unroll
        for (int r = 0; r < 12; r++) { acc[r][0] = 0.f; acc[r][1] = 0.f; }

        for (int jj = 0; jj < 64; jj += 4) {
            int j = jb + jj;
            const float* vp = vbase + (size_t)j * DHx;
            float2 v0 = *(const float2*)(vp);
            float2 v1 = *(const float2*)(vp + 32);
            float2 v2 = *(const float2*)(vp + 64);
            float2 v3 = *(const float2*)(vp + 96);
#pragma unroll
            for (int r = 0; r < 12; r++) {
                float4 p = *(const float4*)&S[r][j];
                acc[r][0] += p.x * v0.x + p.y * v1.x + p.z * v2.x + p.w * v3.x;
                acc[r][1] += p.x * v0.y + p.y * v1.y + p.z * v2.y + p.w * v3.y;
            }
        }
        // combine the two j-halves (lanes dp and dp+16)
#pragma unroll
        for (int r = 0; r < 12; r++) {
            acc[r][0] += __shfl_down_sync(~0u, acc[r][0], 16);
            acc[r][1] += __shfl_down_sync(~0u, acc[r][1], 16);
        }
        if (jh == 0) {
#pragma unroll
            for (int r = 0; r < 12; r++) {
                part[w][r][2 * dp]     = acc[r][0];
                part[w][r][2 * dp + 1] = acc[r][1];
            }
        }
    }
    __syncthreads();

    // ---- reduce 6 warp-partials + normalize + sigmoid gate + store ----
    for (int o = tid; o < 12 * 32; o += 192) {
        int r = o >> 5, d = o & 31;
        float s = part[0][r][d] + part[1][r][d] + part[2][r][d]
                + part[3][r][d] + part[4][r][d] + part[5][r][d];
        s *= invs[r];
        size_t bn = (size_t)b * NNx + i0 + r;
        float gg = g_qkvg[bn * 2048 + 1536 + h * DHx + d];
        float sg = 1.0f / (1.0f + __expf(-gg));
        g_og[bn * INNERx + h * DHx + d] = s * sg;
    }
}

// ---------------- launch ----------------
extern "C" void kernel_launch(void* const* d_in, const int* in_sizes, int n_in,
                              void* d_out, int out_size) {
    const float* node = (const float*)d_in[0];
    const float* pair = (const float*)d_in[1];
    const int*   mask = (const int*)d_in[2];
    const float* nnw  = (const float*)d_in[3];
    const float* nnb  = (const float*)d_in[4];
    const float* qkvw = (const float*)d_in[5];
    const float* qkvb = (const float*)d_in[6];
    const float* gw   = (const float*)d_in[7];
    const float* gb   = (const float*)d_in[8];
    const float* qlw  = (const float*)d_in[9];
    const float* qlb  = (const float*)d_in[10];
    const float* klw  = (const float*)d_in[11];
    const float* klb  = (const float*)d_in[12];
    const float* pnw  = (const float*)d_in[13];
    const float* pnb  = (const float*)d_in[14];
    const float* bw   = (const float*)d_in[15];
    const float* ow   = (const float*)d_in[16];
    const float* ob   = (const float*)d_in[17];
    float* out = (float*)d_out;

    cudaFuncSetAttribute(k_pairbias, cudaFuncAttributeMaxDynamicSharedMemorySize, PB_SMEM);

    k_prep<<<1, 256>>>(bw, pnw, pnb);
    k_ln_node<<<BB * NNx, 256>>>(node, nnw, nnb);
    k_gemm_tc<0><<<dim3(2048 / 64, (BB * NNx) / 128), 256>>>(qkvw, gw, qkvb, gb, nullptr);
    k_pairbias<<<444, 128, PB_SMEM>>>(pair, mask);
    k_lnqk<<<BB * NNx, 256>>>(qlw, qlb, klw, klb);
    k_attn<<<dim3(NNx / 12, HHx, BB), 192>>>();
    k_gemm_tc<1><<<dim3(512 / 64, (BB * NNx) / 128), 256>>>(ow, ow, ob, ob, out);
}

// round 13
// speedup vs baseline: 2.8085x; 1.0131x over previous
#include <cuda_runtime.h>
#include <cuda_fp16.h>
#include <cstdint>

#define BB 2
#define NNx 768
#define DDx 512
#define HHx 16
#define DHx 32
#define INNERx 512
#define PDx 128
#define NEG_INFx -10000.0f
#define LN_EPS 1e-5f

typedef unsigned long long u64;

// ---------------- helpers ----------------
__device__ __forceinline__ void ffma2(u64& d, u64 a, u64 b) {
    asm("fma.rn.f32x2 %0, %1, %2, %0;" : "+l"(d) : "l"(a), "l"(b));
}
__device__ __forceinline__ float2 up2(u64 v) {
    float2 f;
    asm("mov.b64 {%0, %1}, %2;" : "=f"(f.x), "=f"(f.y) : "l"(v));
    return f;
}
__device__ __forceinline__ u64 pack2(float x, float y) {
    u64 r;
    asm("mov.b64 %0, {%1, %2};" : "=l"(r) : "f"(x), "f"(y));
    return r;
}
__device__ __forceinline__ u64 splat2(float x) {
    u64 r;
    asm("mov.b64 %0, {%1, %1};" : "=l"(r) : "f"(x));
    return r;
}
__device__ __forceinline__ uint32_t f2tf32(float f) {
    uint32_t r;
    asm("cvt.rna.tf32.f32 %0, %1;" : "=r"(r) : "f"(f));
    return r;
}
__device__ __forceinline__ void mma_tf32(float& c0, float& c1, float& c2, float& c3,
                                         uint32_t a0, uint32_t a1, uint32_t a2, uint32_t a3,
                                         uint32_t b0, uint32_t b1) {
    asm("mma.sync.aligned.m16n8k8.row.col.f32.tf32.tf32.f32 "
        "{%0,%1,%2,%3}, {%4,%5,%6,%7}, {%8,%9}, {%0,%1,%2,%3};"
        : "+f"(c0), "+f"(c1), "+f"(c2), "+f"(c3)
        : "r"(a0), "r"(a1), "r"(a2), "r"(a3), "r"(b0), "r"(b1));
}

// ---------------- scratch ----------------
__device__ float g_x[BB * NNx * DDx];
__device__ float g_qkvg[BB * NNx * 2048];
__device__ float g_qh[BB * HHx * NNx * DHx];
__device__ float g_khT[BB * HHx * DHx * NNx];
__device__ float g_vh[BB * HHx * NNx * DHx];
__device__ __half g_bias[(size_t)BB * HHx * NNx * NNx];
__device__ float g_og[BB * NNx * INNERx];

// ---------------- K1 fused: pairbias (persistent, inline prep) + node LN tail ----------------
#define SPS 132
#define PB_TR 64
#define PB_GRID 444
#define PB_TILES (BB * NNx * 12)                 // 18432
#define PB_TILE_F (PB_TR * SPS)
#define PB_SMEM  (2 * PB_TILE_F * 4)             // 67584 B
__device__ __forceinline__ size_t pb_decode(int T, int& b, int& i, int& jt) {
    b = T / (NNx * 12);
    int rem = T - b * (NNx * 12);
    i = rem / 12;
    jt = rem - i * 12;
    return ((size_t)(b * NNx + i)) * NNx + jt * PB_TR;
}
__device__ __forceinline__ void pb_stage(float* buf, const float* pb, int tid) {
#pragma unroll
    for (int it = 0; it < 16; it++) {
        int f = tid + it * 128;
        int r = f >> 5, c4 = (f & 31) << 2;
        unsigned sa = (unsigned)__cvta_generic_to_shared(buf + r * SPS + c4);
        const float* ga = pb + (size_t)r * PDx + c4;
        asm volatile("cp.async.cg.shared.global [%0], [%1], 16;" :: "r"(sa), "l"(ga));
    }
    asm volatile("cp.async.commit_group;");
}
__global__ __launch_bounds__(128, 3) void k_fused1(
    const float* __restrict__ pair, const int* __restrict__ mask,
    const float* __restrict__ node, const float* __restrict__ nnw, const float* __restrict__ nnb,
    const float* __restrict__ bias_w, const float* __restrict__ pnw, const float* __restrict__ pnb) {
    extern __shared__ __align__(16) float sp[];
    int tid = threadIdx.x;

    if (blockIdx.x >= PB_GRID) {
        // ---- node LayerNorm, one row per block, 128 threads ----
        int row = blockIdx.x - PB_GRID;
        const float* in = node + (size_t)row * DDx;
        float s = 0.f, ss = 0.f;
        for (int c = tid; c < DDx; c += 128) {
            float t = in[c];
            s += t; ss += t * t;
        }
#pragma unroll
        for (int o = 16; o > 0; o >>= 1) {
            s  += __shfl_xor_sync(~0u, s, o);
            ss += __shfl_xor_sync(~0u, ss, o);
        }
        __shared__ float red[8];
        int wd = tid >> 5, ln = tid & 31;
        if (ln == 0) { red[wd] = s; red[4 + wd] = ss; }
        __syncthreads();
        __shared__ float sm2, sr2;
        if (tid == 0) {
            float S = red[0] + red[1] + red[2] + red[3];
            float SS = red[4] + red[5] + red[6] + red[7];
            float m = S / DDx;
            sm2 = m;
            sr2 = rsqrtf(SS / DDx - m * m + LN_EPS);
        }
        __syncthreads();
        float m = sm2, r = sr2;
        for (int c = tid; c < DDx; c += 128)
            g_x[(size_t)row * DDx + c] = (in[c] - m) * r * nnw[c] + nnb[c];
        return;
    }

    // ---- pairbias persistent blocks ----
    int w = tid >> 5, lane = tid & 31;
    int lg = lane >> 2, lt = lane & 3;
    int r0 = w * 16 + lg;

    // inline prep: tf32-rounded W' fragments + sh/th for this thread's h-columns
    uint32_t blo[32], bhi[32];
#pragma unroll
    for (int ks = 0; ks < 16; ks++) {
        int e0 = ks * 8 + lt, e1 = ks * 8 + lt + 4;
        blo[2 * ks]     = f2tf32(pnw[e0] * bias_w[e0 * HHx + lg]);
        blo[2 * ks + 1] = f2tf32(pnw[e1] * bias_w[e1 * HHx + lg]);
        bhi[2 * ks]     = f2tf32(pnw[e0] * bias_w[e0 * HHx + 8 + lg]);
        bhi[2 * ks + 1] = f2tf32(pnw[e1] * bias_w[e1 * HHx + 8 + lg]);
    }
    float shv[4], thv[4];
    {
        int hc[4] = {2 * lt, 2 * lt + 1, 8 + 2 * lt, 9 + 2 * lt};
#pragma unroll
        for (int q = 0; q < 4; q++) {
            float s = 0.f, t = 0.f;
            for (int e = 0; e < PDx; e++) {
                float bw = bias_w[e * HHx + hc[q]];
                s += pnw[e] * bw;
                t += pnb[e] * bw;
            }
            shv[q] = s; thv[q] = t;
        }
    }

    const int g = PB_GRID;
    {
        int b, i, jt;
        size_t rb = pb_decode(blockIdx.x, b, i, jt);
        pb_stage(sp, pair + rb * (size_t)PDx, tid);
    }

    int parity = 0;
    for (int T = blockIdx.x; T < PB_TILES; T += g) {
        asm volatile("cp.async.wait_group 0;" ::: "memory");
        __syncthreads();

        int Tn = T + g;
        if (Tn < PB_TILES) {
            int b2, i2, jt2;
            size_t rb2 = pb_decode(Tn, b2, i2, jt2);
            pb_stage(sp + (parity ^ 1) * PB_TILE_F, pair + rb2 * (size_t)PDx, tid);
        }

        int b, i, jt;
        size_t rowbase = pb_decode(T, b, i, jt);
        const float* buf = sp + parity * PB_TILE_F;

        float e0 = 0.f, e1 = 0.f, e2 = 0.f, e3 = 0.f;
        float o0 = 0.f, o1 = 0.f, o2 = 0.f, o3 = 0.f;
        float E0 = 0.f, E1 = 0.f, E2 = 0.f, E3 = 0.f;
        float O0 = 0.f, O1 = 0.f, O2 = 0.f, O3 = 0.f;
        float s0 = 0.f, ss0 = 0.f, s1 = 0.f, ss1 = 0.f;
        const float* Ab = buf + r0 * SPS + lt;
#pragma unroll
        for (int kp = 0; kp < 8; kp++) {
            {
                int ks = 2 * kp;
                float a0 = Ab[ks * 8];
                float a1 = Ab[ks * 8 + 8 * SPS];
                float a2 = Ab[ks * 8 + 4];
                float a3 = Ab[ks * 8 + 8 * SPS + 4];
                s0 += a0 + a2;  ss0 += a0 * a0 + a2 * a2;
                s1 += a1 + a3;  ss1 += a1 * a1 + a3 * a3;
                uint32_t u0 = __float_as_uint(a0), u1 = __float_as_uint(a1);
                uint32_t u2 = __float_as_uint(a2), u3 = __float_as_uint(a3);
                mma_tf32(e0, e1, e2, e3, u0, u1, u2, u3, blo[2 * ks], blo[2 * ks + 1]);
                mma_tf32(E0, E1, E2, E3, u0, u1, u2, u3, bhi[2 * ks], bhi[2 * ks + 1]);
            }
            {
                int ks = 2 * kp + 1;
                float a0 = Ab[ks * 8];
                float a1 = Ab[ks * 8 + 8 * SPS];
                float a2 = Ab[ks * 8 + 4];
                float a3 = Ab[ks * 8 + 8 * SPS + 4];
                s0 += a0 + a2;  ss0 += a0 * a0 + a2 * a2;
                s1 += a1 + a3;  ss1 += a1 * a1 + a3 * a3;
                uint32_t u0 = __float_as_uint(a0), u1 = __float_as_uint(a1);
                uint32_t u2 = __float_as_uint(a2), u3 = __float_as_uint(a3);
                mma_tf32(o0, o1, o2, o3, u0, u1, u2, u3, blo[2 * ks], blo[2 * ks + 1]);
                mma_tf32(O0, O1, O2, O3, u0, u1, u2, u3, bhi[2 * ks], bhi[2 * ks + 1]);
            }
        }
        float c0 = e0 + o0, c1 = e1 + o1, c2 = e2 + o2, c3 = e3 + o3;
        float c4v = E0 + O0, c5 = E1 + O1, c6 = E2 + O2, c7 = E3 + O3;

        s0  += __shfl_xor_sync(~0u, s0, 1);   s0  += __shfl_xor_sync(~0u, s0, 2);
        ss0 += __shfl_xor_sync(~0u, ss0, 1);  ss0 += __shfl_xor_sync(~0u, ss0, 2);
        s1  += __shfl_xor_sync(~0u, s1, 1);   s1  += __shfl_xor_sync(~0u, s1, 2);
        ss1 += __shfl_xor_sync(~0u, ss1, 1);  ss1 += __shfl_xor_sync(~0u, ss1, 2);
        float m0 = s0 * (1.0f / PDx);
        float r0s = rsqrtf(ss0 * (1.0f / PDx) - m0 * m0 + LN_EPS);
        float m1 = s1 * (1.0f / PDx);
        float r1s = rsqrtf(ss1 * (1.0f / PDx) - m1 * m1 + LN_EPS);

        int mk0 = mask[rowbase + r0];
        int mk1 = mask[rowbase + r0 + 8];

        size_t pb0 = (((size_t)(b * HHx) * NNx + i)) * NNx + jt * PB_TR;
        float rm0 = r0s * m0, rm1 = r1s * m1;
        float vals[8] = {
            r0s * c0  - rm0 * shv[0] + thv[0],
            r0s * c1  - rm0 * shv[1] + thv[1],
            r1s * c2  - rm1 * shv[0] + thv[0],
            r1s * c3  - rm1 * shv[1] + thv[1],
            r0s * c4v - rm0 * shv[2] + thv[2],
            r0s * c5  - rm0 * shv[3] + thv[3],
            r1s * c6  - rm1 * shv[2] + thv[2],
            r1s * c7  - rm1 * shv[3] + thv[3],
        };
        if (mk0 == 0) { vals[0] = NEG_INFx; vals[1] = NEG_INFx; vals[4] = NEG_INFx; vals[5] = NEG_INFx; }
        if (mk1 == 0) { vals[2] = NEG_INFx; vals[3] = NEG_INFx; vals[6] = NEG_INFx; vals[7] = NEG_INFx; }
        int hcol[4] = {2 * lt, 2 * lt + 1, 8 + 2 * lt, 9 + 2 * lt};
        size_t plane = (size_t)NNx * NNx;
        g_bias[pb0 + hcol[0] * plane + r0]     = __float2half_rn(vals[0]);
        g_bias[pb0 + hcol[1] * plane + r0]     = __float2half_rn(vals[1]);
        g_bias[pb0 + hcol[0] * plane + r0 + 8] = __float2half_rn(vals[2]);
        g_bias[pb0 + hcol[1] * plane + r0 + 8] = __float2half_rn(vals[3]);
        g_bias[pb0 + hcol[2] * plane + r0]     = __float2half_rn(vals[4]);
        g_bias[pb0 + hcol[3] * plane + r0]     = __float2half_rn(vals[5]);
        g_bias[pb0 + hcol[2] * plane + r0 + 8] = __float2half_rn(vals[6]);
        g_bias[pb0 + hcol[3] * plane + r0 + 8] = __float2half_rn(vals[7]);

        parity ^= 1;
    }
}

// ---------------- K2/K5: dense GEMM (tf32 mma, double-buffered) ----------------
#define AST 20
#define BST 72
template<int MODE>
__global__ void k_gemm_tc(const float* __restrict__ B1, const float* __restrict__ B2,
                          const float* __restrict__ bias1, const float* __restrict__ bias2,
                          float* __restrict__ Cext) {
    constexpr int LDC   = (MODE == 0) ? 2048 : 512;
    constexpr int SPLIT = (MODE == 0) ? 1536 : (1 << 30);
    constexpr int LD1   = (MODE == 0) ? 1536 : 512;
    constexpr int LD2   = 512;

    const float* A = (MODE == 0) ? g_x : g_og;
    float* C = (MODE == 0) ? g_qkvg : Cext;

    __shared__ __align__(16) float As[2][128 * AST];
    __shared__ __align__(16) float Bs[2][16 * BST];

    int bm = blockIdx.y * 128, bn = blockIdx.x * 64;
    int tid = threadIdx.x, w = tid >> 5, lane = tid & 31;
    int wm = w >> 1, wn = w & 1;
    int lg = lane >> 2, lt = lane & 3;

    float acc[2][4][4] = {};

    int mS = tid >> 1, segS = (tid & 1) * 8;
    int kS = tid >> 4, nS = (tid & 15) * 4;
    int ncol = bn + nS;
    const float* bsrc = (ncol < SPLIT) ? (B1 + ncol) : (B2 + (ncol - SPLIT));
    int ldb = (ncol < SPLIT) ? LD1 : LD2;
    const float* aS = A + (size_t)(bm + mS) * 512 + segS;

    float4 ra0, ra1, rb;
    ra0 = *(const float4*)(aS);
    ra1 = *(const float4*)(aS + 4);
    rb  = *(const float4*)&bsrc[(size_t)kS * ldb];
    {
        uint4 t0 = {f2tf32(ra0.x), f2tf32(ra0.y), f2tf32(ra0.z), f2tf32(ra0.w)};
        uint4 t1 = {f2tf32(ra1.x), f2tf32(ra1.y), f2tf32(ra1.z), f2tf32(ra1.w)};
        uint4 tb = {f2tf32(rb.x),  f2tf32(rb.y),  f2tf32(rb.z),  f2tf32(rb.w)};
        *(uint4*)&As[0][mS * AST + segS]     = t0;
        *(uint4*)&As[0][mS * AST + segS + 4] = t1;
        *(uint4*)&Bs[0][kS * BST + nS]       = tb;
    }
    __syncthreads();

    for (int k0 = 0; k0 < 512; k0 += 16) {
        int cur = (k0 >> 4) & 1;
        bool more = (k0 + 16) < 512;
        if (more) {
            ra0 = *(const float4*)(aS + k0 + 16);
            ra1 = *(const float4*)(aS + k0 + 20);
            rb  = *(const float4*)&bsrc[(size_t)(k0 + 16 + kS) * ldb];
        }

#pragma unroll
        for (int ks = 0; ks < 2; ks++) {
            uint32_t af[2][4];
            const float* ab = &As[cur][(wm * 32 + lg) * AST + ks * 8 + lt];
#pragma unroll
            for (int mf = 0; mf < 2; mf++) {
                const float* a = ab + mf * 16 * AST;
                af[mf][0] = __float_as_uint(a[0]);
                af[mf][1] = __float_as_uint(a[8 * AST]);
                af[mf][2] = __float_as_uint(a[4]);
                af[mf][3] = __float_as_uint(a[8 * AST + 4]);
            }
            uint32_t bf[4][2];
            const float* bb = &Bs[cur][(ks * 8 + lt) * BST + wn * 32 + lg];
#pragma unroll
            for (int nf = 0; nf < 4; nf++) {
                bf[nf][0] = __float_as_uint(bb[nf * 8]);
                bf[nf][1] = __float_as_uint(bb[4 * BST + nf * 8]);
            }
#pragma unroll
            for (int mf = 0; mf < 2; mf++)
#pragma unroll
                for (int nf = 0; nf < 4; nf++)
                    mma_tf32(acc[mf][nf][0], acc[mf][nf][1], acc[mf][nf][2], acc[mf][nf][3],
                             af[mf][0], af[mf][1], af[mf][2], af[mf][3],
                             bf[nf][0], bf[nf][1]);
        }

        if (more) {
            int nxt = cur ^ 1;
            uint4 t0 = {f2tf32(ra0.x), f2tf32(ra0.y), f2tf32(ra0.z), f2tf32(ra0.w)};
            uint4 t1 = {f2tf32(ra1.x), f2tf32(ra1.y), f2tf32(ra1.z), f2tf32(ra1.w)};
            uint4 tb = {f2tf32(rb.x),  f2tf32(rb.y),  f2tf32(rb.z),  f2tf32(rb.w)};
            *(uint4*)&As[nxt][mS * AST + segS]     = t0;
            *(uint4*)&As[nxt][mS * AST + segS + 4] = t1;
            *(uint4*)&Bs[nxt][kS * BST + nS]       = tb;
        }
        __syncthreads();
    }

#pragma unroll
    for (int mf = 0; mf < 2; mf++) {
#pragma unroll
        for (int nf = 0; nf < 4; nf++) {
            int r = bm + wm * 32 + mf * 16 + lg;
            int c = bn + wn * 32 + nf * 8 + 2 * lt;
            float bi0 = (c < SPLIT) ? bias1[c] : bias2[c - SPLIT];
            float bi1 = (c + 1 < SPLIT) ? bias1[c + 1] : bias2[c + 1 - SPLIT];
            float2 v0 = {acc[mf][nf][0] + bi0, acc[mf][nf][1] + bi1};
            float2 v1 = {acc[mf][nf][2] + bi0, acc[mf][nf][3] + bi1};
            *(float2*)&C[(size_t)r * LDC + c]       = v0;
            *(float2*)&C[(size_t)(r + 8) * LDC + c] = v1;
        }
    }
}

// ---------------- K3: q/k LN; q,v head-major, k transposed ----------------
__global__ void k_lnqk(const float* __restrict__ qw, const float* __restrict__ qb,
                       const float* __restrict__ kw, const float* __restrict__ kb) {
    int bn = blockIdx.x;
    const float* row = g_qkvg + (size_t)bn * 2048;
    int b = bn / NNx, nn = bn % NNx;
    float s1 = 0.f, ss1 = 0.f, s2 = 0.f, ss2 = 0.f;
    for (int c = threadIdx.x; c < 512; c += 256) {
        float a = row[c], b2 = row[512 + c];
        s1 += a; ss1 += a * a; s2 += b2; ss2 += b2 * b2;
    }
#pragma unroll
    for (int o = 16; o > 0; o >>= 1) {
        s1  += __shfl_xor_sync(~0u, s1, o);  ss1 += __shfl_xor_sync(~0u, ss1, o);
        s2  += __shfl_xor_sync(~0u, s2, o);  ss2 += __shfl_xor_sync(~0u, ss2, o);
    }
    __shared__ float red[4][8];
    int w = threadIdx.x >> 5, lane = threadIdx.x & 31;
    if (lane == 0) { red[0][w] = s1; red[1][w] = ss1; red[2][w] = s2; red[3][w] = ss2; }
    __syncthreads();
    __shared__ float st[4];
    if (threadIdx.x == 0) {
        float a = 0.f, bb = 0.f, c = 0.f, d = 0.f;
        for (int i = 0; i < 8; i++) { a += red[0][i]; bb += red[1][i]; c += red[2][i]; d += red[3][i]; }
        float m1 = a / 512.f, m2 = c / 512.f;
        st[0] = m1; st[1] = rsqrtf(bb / 512.f - m1 * m1 + LN_EPS);
        st[2] = m2; st[3] = rsqrtf(d / 512.f - m2 * m2 + LN_EPS);
    }
    __syncthreads();
    float m1 = st[0], r1 = st[1], m2 = st[2], r2 = st[3];
    for (int c = threadIdx.x; c < 512; c += 256) {
        int h = c >> 5, d = c & 31;
        size_t oidx  = (((size_t)(b * HHx + h)) * NNx + nn) * DHx + d;
        size_t oidxT = (((size_t)(b * HHx + h)) * DHx + d) * NNx + nn;
        g_qh[oidx]   = (row[c]       - m1) * r1 * qw[c] + qb[c];
        g_khT[oidxT] = (row[512 + c] - m2) * r2 * kw[c] + kb[c];
        g_vh[oidx]   = row[1024 + c];
    }
}

// ---------------- K4: attention — 16-row tiles, QK & AV column-owned ----------------
#define AR 16
__global__ __launch_bounds__(192) void k_attn() {
    __shared__ __align__(16) float S[AR][NNx];     // 49152 B
    __shared__ __align__(16) u64 qp2[AR][16];      //  2048 B
    __shared__ float part[6][AR][32];              // 12288 B
    __shared__ float invs[AR];
    int i0 = blockIdx.x * AR;
    int h = blockIdx.y, b = blockIdx.z;
    int tid = threadIdx.x;
    int w = tid >> 5, lane = tid & 31;
    size_t bhbase = (size_t)(b * HHx + h) * NNx;

    for (int idx = tid; idx < AR * 16; idx += 192) {
        int r = idx >> 4, dp = idx & 15;
        const float* qrow = g_qh + (bhbase + i0 + r) * DHx + 2 * dp;
        float2 qv = *(const float2*)qrow;
        qp2[r][dp] = pack2(qv.x, qv.y);
    }
    __syncthreads();

    const float scale = 0.17677669529663687f;
    const float* kT = g_khT + (size_t)(b * HHx + h) * DHx * NNx;

    // ---- QK^T: warp w owns j-chunk w (128 j); all 16 rows ----
    {
        int jb = w * 128 + lane * 4;
        const float* kTc = kT + jb;
        u64 acc[AR][2];
#pragma unroll
        for (int r = 0; r < AR; r++) { acc[r][0] = 0; acc[r][1] = 0; }

#pragma unroll
        for (int dg = 0; dg < 4; dg++) {
            u64 kx[8][2];
#pragma unroll
            for (int dd = 0; dd < 8; dd++) {
                ulonglong2 kv = *(const ulonglong2*)&kTc[(size_t)(dg * 8 + dd) * NNx];
                kx[dd][0] = kv.x; kx[dd][1] = kv.y;
            }
#pragma unroll
            for (int r = 0; r < AR; r++) {
#pragma unroll
                for (int dd = 0; dd < 4; dd++) {
                    float2 q = up2(qp2[r][dg * 4 + dd]);
                    u64 q0 = splat2(q.x), q1 = splat2(q.y);
                    ffma2(acc[r][0], kx[2 * dd][0], q0);
                    ffma2(acc[r][1], kx[2 * dd][1], q0);
                    ffma2(acc[r][0], kx[2 * dd + 1][0], q1);
                    ffma2(acc[r][1], kx[2 * dd + 1][1], q1);
                }
            }
        }

#pragma unroll
        for (int r = 0; r < AR; r++) {
            const __half* brow = g_bias + (bhbase + i0 + r) * NNx + jb;
            __half2 b01 = *(const __half2*)(brow);
            __half2 b23 = *(const __half2*)(brow + 2);
            float2 f01 = __half22float2(b01), f23 = __half22float2(b23);
            float2 sx = up2(acc[r][0]), sy = up2(acc[r][1]);
            float4 out = {sx.x * scale + f01.x, sx.y * scale + f01.y,
                          sy.x * scale + f23.x, sy.y * scale + f23.y};
            *(float4*)&S[r][jb] = out;
        }
    }
    __syncthreads();

    // ---- softmax: rows distributed r = w, w+6, ... ----
    for (int r = w; r < AR; r += 6) {
        float* Sr = &S[r][0];
        float mx = -3.4e38f;
        for (int c = lane; c < NNx; c += 32) mx = fmaxf(mx, Sr[c]);
#pragma unroll
        for (int o = 16; o > 0; o >>= 1) mx = fmaxf(mx, __shfl_xor_sync(~0u, mx, o));
        float sum = 0.f;
        for (int c = lane; c < NNx; c += 32) {
            float e = __expf(Sr[c] - mx);
            Sr[c] = e;
            sum += e;
        }
#pragma unroll
        for (int o = 16; o > 0; o >>= 1) sum += __shfl_xor_sync(~0u, sum, o);
        if (lane == 0) invs[r] = 1.0f / sum;
    }
    __syncthreads();

    // ---- AV column-owned: warp w owns j-chunk w; partials for all 16 rows ----
    {
        int dp = lane & 15, jh = lane >> 4;
        int jb = w * 128 + jh * 64;
        const float* vbase = g_vh + bhbase * DHx + 2 * dp;
        float acc[AR][2];
#pragma unroll
        for (int r = 0; r < AR; r++) { acc[r][0] = 0.f; acc[r][1] = 0.f; }

        for (int jj = 0; jj < 64; jj += 4) {
            int j = jb + jj;
            const float* vp = vbase + (size_t)j * DHx;
            float2 v0 = *(const float2*)(vp);
            float2 v1 = *(const float2*)(vp + 32);
            float2 v2 = *(const float2*)(vp + 64);
            float2 v3 = *(const float2*)(vp + 96);
#pragma unroll
            for (int r = 0; r < AR; r++) {
                float4 p = *(const float4*)&S[r][j];
                acc[r][0] += p.x * v0.x + p.y * v1.x + p.z * v2.x + p.w * v3.x;
                acc[r][1] += p.x * v0.y + p.y * v1.y + p.z * v2.y + p.w * v3.y;
            }
        }
#pragma unroll
        for (int r = 0; r < AR; r++) {
            acc[r][0] += __shfl_down_sync(~0u, acc[r][0], 16);
            acc[r][1] += __shfl_down_sync(~0u, acc[r][1], 16);
        }
        if (jh == 0) {
#pragma unroll
            for (int r = 0; r < AR; r++) {
                part[w][r][2 * dp]     = acc[r][0];
                part[w][r][2 * dp + 1] = acc[r][1];
            }
        }
    }
    __syncthreads();

    // ---- reduce partials + normalize + sigmoid gate + store ----
    for (int o = tid; o < AR * 32; o += 192) {
        int r = o >> 5, d = o & 31;
        float s = part[0][r][d] + part[1][r][d] + part[2][r][d]
                + part[3][r][d] + part[4][r][d] + part[5][r][d];
        s *= invs[r];
        size_t bn = (size_t)b * NNx + i0 + r;
        float gg = g_qkvg[bn * 2048 + 1536 + h * DHx + d];
        float sg = 1.0f / (1.0f + __expf(-gg));
        g_og[bn * INNERx + h * DHx + d] = s * sg;
    }
}

// ---------------- launch ----------------
extern "C" void kernel_launch(void* const* d_in, const int* in_sizes, int n_in,
                              void* d_out, int out_size) {
    const float* node = (const float*)d_in[0];
    const float* pair = (const float*)d_in[1];
    const int*   mask = (const int*)d_in[2];
    const float* nnw  = (const float*)d_in[3];
    const float* nnb  = (const float*)d_in[4];
    const float* qkvw = (const float*)d_in[5];
    const float* qkvb = (const float*)d_in[6];
    const float* gw   = (const float*)d_in[7];
    const float* gb   = (const float*)d_in[8];
    const float* qlw  = (const float*)d_in[9];
    const float* qlb  = (const float*)d_in[10];
    const float* klw  = (const float*)d_in[11];
    const float* klb  = (const float*)d_in[12];
    const float* pnw  = (const float*)d_in[13];
    const float* pnb  = (const float*)d_in[14];
    const float* bw   = (const float*)d_in[15];
    const float* ow   = (const float*)d_in[16];
    const float* ob   = (const float*)d_in[17];
    float* out = (float*)d_out;

    cudaFuncSetAttribute(k_fused1, cudaFuncAttributeMaxDynamicSharedMemorySize, PB_SMEM);

    k_fused1<<<PB_GRID + BB * NNx, 128, PB_SMEM>>>(pair, mask, node, nnw, nnb, bw, pnw, pnb);
    k_gemm_tc<0><<<dim3(2048 / 64, (BB * NNx) / 128), 256>>>(qkvw, gw, qkvb, gb, nullptr);
    k_lnqk<<<BB * NNx, 256>>>(qlw, qlb, klw, klb);
    k_attn<<<dim3(NNx / AR, HHx, BB), 192>>>();
    k_gemm_tc<1><<<dim3(512 / 64, (BB * NNx) / 128), 256>>>(ow, ow, ob, ob, out);
}

// round 14
// speedup vs baseline: 3.0090x; 1.0714x over previous
#include <cuda_runtime.h>
#include <cuda_fp16.h>
#include <cstdint>

#define BB 2
#define NNx 768
#define DDx 512
#define HHx 16
#define DHx 32
#define INNERx 512
#define PDx 128
#define NEG_INFx -10000.0f
#define LN_EPS 1e-5f

typedef unsigned long long u64;

// ---------------- helpers ----------------
__device__ __forceinline__ void ffma2(u64& d, u64 a, u64 b) {
    asm("fma.rn.f32x2 %0, %1, %2, %0;" : "+l"(d) : "l"(a), "l"(b));
}
__device__ __forceinline__ float2 up2(u64 v) {
    float2 f;
    asm("mov.b64 {%0, %1}, %2;" : "=f"(f.x), "=f"(f.y) : "l"(v));
    return f;
}
__device__ __forceinline__ u64 pack2(float x, float y) {
    u64 r;
    asm("mov.b64 %0, {%1, %2};" : "=l"(r) : "f"(x), "f"(y));
    return r;
}
__device__ __forceinline__ u64 splat2(float x) {
    u64 r;
    asm("mov.b64 %0, {%1, %1};" : "=l"(r) : "f"(x));
    return r;
}
__device__ __forceinline__ uint32_t f2tf32(float f) {
    uint32_t r;
    asm("cvt.rna.tf32.f32 %0, %1;" : "=r"(r) : "f"(f));
    return r;
}
__device__ __forceinline__ void mma_tf32(float& c0, float& c1, float& c2, float& c3,
                                         uint32_t a0, uint32_t a1, uint32_t a2, uint32_t a3,
                                         uint32_t b0, uint32_t b1) {
    asm("mma.sync.aligned.m16n8k8.row.col.f32.tf32.tf32.f32 "
        "{%0,%1,%2,%3}, {%4,%5,%6,%7}, {%8,%9}, {%0,%1,%2,%3};"
        : "+f"(c0), "+f"(c1), "+f"(c2), "+f"(c3)
        : "r"(a0), "r"(a1), "r"(a2), "r"(a3), "r"(b0), "r"(b1));
}

// ---------------- scratch ----------------
__device__ float g_x[BB * NNx * DDx];
__device__ float g_qkvg[BB * NNx * 2048];
__device__ float g_qh[BB * HHx * NNx * DHx];
__device__ float g_khT[BB * HHx * DHx * NNx];
__device__ float g_vh[BB * HHx * NNx * DHx];
__device__ __half g_bias[(size_t)BB * HHx * NNx * NNx];
__device__ float g_og[BB * NNx * INNERx];

// ---------------- K1 fused: pairbias (persistent, inline prep) + node LN tail ----------------
#define SPS 132
#define PB_TR 64
#define PB_GRID 444
#define PB_TILES (BB * NNx * 12)
#define PB_TILE_F (PB_TR * SPS)
#define PB_SMEM  (2 * PB_TILE_F * 4)             // 67584 B
__device__ __forceinline__ size_t pb_decode(int T, int& b, int& i, int& jt) {
    b = T / (NNx * 12);
    int rem = T - b * (NNx * 12);
    i = rem / 12;
    jt = rem - i * 12;
    return ((size_t)(b * NNx + i)) * NNx + jt * PB_TR;
}
__device__ __forceinline__ void pb_stage(float* buf, const float* pb, int tid) {
#pragma unroll
    for (int it = 0; it < 16; it++) {
        int f = tid + it * 128;
        int r = f >> 5, c4 = (f & 31) << 2;
        unsigned sa = (unsigned)__cvta_generic_to_shared(buf + r * SPS + c4);
        const float* ga = pb + (size_t)r * PDx + c4;
        asm volatile("cp.async.cg.shared.global [%0], [%1], 16;" :: "r"(sa), "l"(ga));
    }
    asm volatile("cp.async.commit_group;");
}
__global__ __launch_bounds__(128, 3) void k_fused1(
    const float* __restrict__ pair, const int* __restrict__ mask,
    const float* __restrict__ node, const float* __restrict__ nnw, const float* __restrict__ nnb,
    const float* __restrict__ bias_w, const float* __restrict__ pnw, const float* __restrict__ pnb) {
    extern __shared__ __align__(16) float sp[];
    int tid = threadIdx.x;

    if (blockIdx.x >= PB_GRID) {
        int row = blockIdx.x - PB_GRID;
        const float* in = node + (size_t)row * DDx;
        float s = 0.f, ss = 0.f;
        for (int c = tid; c < DDx; c += 128) {
            float t = in[c];
            s += t; ss += t * t;
        }
#pragma unroll
        for (int o = 16; o > 0; o >>= 1) {
            s  += __shfl_xor_sync(~0u, s, o);
            ss += __shfl_xor_sync(~0u, ss, o);
        }
        __shared__ float red[8];
        int wd = tid >> 5, ln = tid & 31;
        if (ln == 0) { red[wd] = s; red[4 + wd] = ss; }
        __syncthreads();
        __shared__ float sm2, sr2;
        if (tid == 0) {
            float S = red[0] + red[1] + red[2] + red[3];
            float SS = red[4] + red[5] + red[6] + red[7];
            float m = S / DDx;
            sm2 = m;
            sr2 = rsqrtf(SS / DDx - m * m + LN_EPS);
        }
        __syncthreads();
        float m = sm2, r = sr2;
        for (int c = tid; c < DDx; c += 128)
            g_x[(size_t)row * DDx + c] = (in[c] - m) * r * nnw[c] + nnb[c];
        return;
    }

    int w = tid >> 5, lane = tid & 31;
    int lg = lane >> 2, lt = lane & 3;
    int r0 = w * 16 + lg;

    uint32_t blo[32], bhi[32];
#pragma unroll
    for (int ks = 0; ks < 16; ks++) {
        int e0 = ks * 8 + lt, e1 = ks * 8 + lt + 4;
        blo[2 * ks]     = f2tf32(pnw[e0] * bias_w[e0 * HHx + lg]);
        blo[2 * ks + 1] = f2tf32(pnw[e1] * bias_w[e1 * HHx + lg]);
        bhi[2 * ks]     = f2tf32(pnw[e0] * bias_w[e0 * HHx + 8 + lg]);
        bhi[2 * ks + 1] = f2tf32(pnw[e1] * bias_w[e1 * HHx + 8 + lg]);
    }
    float shv[4], thv[4];
    {
        int hc[4] = {2 * lt, 2 * lt + 1, 8 + 2 * lt, 9 + 2 * lt};
#pragma unroll
        for (int q = 0; q < 4; q++) {
            float s = 0.f, t = 0.f;
            for (int e = 0; e < PDx; e++) {
                float bw = bias_w[e * HHx + hc[q]];
                s += pnw[e] * bw;
                t += pnb[e] * bw;
            }
            shv[q] = s; thv[q] = t;
        }
    }

    const int g = PB_GRID;
    {
        int b, i, jt;
        size_t rb = pb_decode(blockIdx.x, b, i, jt);
        pb_stage(sp, pair + rb * (size_t)PDx, tid);
    }

    int parity = 0;
    for (int T = blockIdx.x; T < PB_TILES; T += g) {
        asm volatile("cp.async.wait_group 0;" ::: "memory");
        __syncthreads();

        int Tn = T + g;
        if (Tn < PB_TILES) {
            int b2, i2, jt2;
            size_t rb2 = pb_decode(Tn, b2, i2, jt2);
            pb_stage(sp + (parity ^ 1) * PB_TILE_F, pair + rb2 * (size_t)PDx, tid);
        }

        int b, i, jt;
        size_t rowbase = pb_decode(T, b, i, jt);
        const float* buf = sp + parity * PB_TILE_F;

        float e0 = 0.f, e1 = 0.f, e2 = 0.f, e3 = 0.f;
        float o0 = 0.f, o1 = 0.f, o2 = 0.f, o3 = 0.f;
        float E0 = 0.f, E1 = 0.f, E2 = 0.f, E3 = 0.f;
        float O0 = 0.f, O1 = 0.f, O2 = 0.f, O3 = 0.f;
        float s0 = 0.f, ss0 = 0.f, s1 = 0.f, ss1 = 0.f;
        const float* Ab = buf + r0 * SPS + lt;
#pragma unroll
        for (int kp = 0; kp < 8; kp++) {
            {
                int ks = 2 * kp;
                float a0 = Ab[ks * 8];
                float a1 = Ab[ks * 8 + 8 * SPS];
                float a2 = Ab[ks * 8 + 4];
                float a3 = Ab[ks * 8 + 8 * SPS + 4];
                s0 += a0 + a2;  ss0 += a0 * a0 + a2 * a2;
                s1 += a1 + a3;  ss1 += a1 * a1 + a3 * a3;
                uint32_t u0 = __float_as_uint(a0), u1 = __float_as_uint(a1);
                uint32_t u2 = __float_as_uint(a2), u3 = __float_as_uint(a3);
                mma_tf32(e0, e1, e2, e3, u0, u1, u2, u3, blo[2 * ks], blo[2 * ks + 1]);
                mma_tf32(E0, E1, E2, E3, u0, u1, u2, u3, bhi[2 * ks], bhi[2 * ks + 1]);
            }
            {
                int ks = 2 * kp + 1;
                float a0 = Ab[ks * 8];
                float a1 = Ab[ks * 8 + 8 * SPS];
                float a2 = Ab[ks * 8 + 4];
                float a3 = Ab[ks * 8 + 8 * SPS + 4];
                s0 += a0 + a2;  ss0 += a0 * a0 + a2 * a2;
                s1 += a1 + a3;  ss1 += a1 * a1 + a3 * a3;
                uint32_t u0 = __float_as_uint(a0), u1 = __float_as_uint(a1);
                uint32_t u2 = __float_as_uint(a2), u3 = __float_as_uint(a3);
                mma_tf32(o0, o1, o2, o3, u0, u1, u2, u3, blo[2 * ks], blo[2 * ks + 1]);
                mma_tf32(O0, O1, O2, O3, u0, u1, u2, u3, bhi[2 * ks], bhi[2 * ks + 1]);
            }
        }
        float c0 = e0 + o0, c1 = e1 + o1, c2 = e2 + o2, c3 = e3 + o3;
        float c4v = E0 + O0, c5 = E1 + O1, c6 = E2 + O2, c7 = E3 + O3;

        s0  += __shfl_xor_sync(~0u, s0, 1);   s0  += __shfl_xor_sync(~0u, s0, 2);
        ss0 += __shfl_xor_sync(~0u, ss0, 1);  ss0 += __shfl_xor_sync(~0u, ss0, 2);
        s1  += __shfl_xor_sync(~0u, s1, 1);   s1  += __shfl_xor_sync(~0u, s1, 2);
        ss1 += __shfl_xor_sync(~0u, ss1, 1);  ss1 += __shfl_xor_sync(~0u, ss1, 2);
        float m0 = s0 * (1.0f / PDx);
        float r0s = rsqrtf(ss0 * (1.0f / PDx) - m0 * m0 + LN_EPS);
        float m1 = s1 * (1.0f / PDx);
        float r1s = rsqrtf(ss1 * (1.0f / PDx) - m1 * m1 + LN_EPS);

        int mk0 = mask[rowbase + r0];
        int mk1 = mask[rowbase + r0 + 8];

        size_t pb0 = (((size_t)(b * HHx) * NNx + i)) * NNx + jt * PB_TR;
        float rm0 = r0s * m0, rm1 = r1s * m1;
        float vals[8] = {
            r0s * c0  - rm0 * shv[0] + thv[0],
            r0s * c1  - rm0 * shv[1] + thv[1],
            r1s * c2  - rm1 * shv[0] + thv[0],
            r1s * c3  - rm1 * shv[1] + thv[1],
            r0s * c4v - rm0 * shv[2] + thv[2],
            r0s * c5  - rm0 * shv[3] + thv[3],
            r1s * c6  - rm1 * shv[2] + thv[2],
            r1s * c7  - rm1 * shv[3] + thv[3],
        };
        if (mk0 == 0) { vals[0] = NEG_INFx; vals[1] = NEG_INFx; vals[4] = NEG_INFx; vals[5] = NEG_INFx; }
        if (mk1 == 0) { vals[2] = NEG_INFx; vals[3] = NEG_INFx; vals[6] = NEG_INFx; vals[7] = NEG_INFx; }
        int hcol[4] = {2 * lt, 2 * lt + 1, 8 + 2 * lt, 9 + 2 * lt};
        size_t plane = (size_t)NNx * NNx;
        g_bias[pb0 + hcol[0] * plane + r0]     = __float2half_rn(vals[0]);
        g_bias[pb0 + hcol[1] * plane + r0]     = __float2half_rn(vals[1]);
        g_bias[pb0 + hcol[0] * plane + r0 + 8] = __float2half_rn(vals[2]);
        g_bias[pb0 + hcol[1] * plane + r0 + 8] = __float2half_rn(vals[3]);
        g_bias[pb0 + hcol[2] * plane + r0]     = __float2half_rn(vals[4]);
        g_bias[pb0 + hcol[3] * plane + r0]     = __float2half_rn(vals[5]);
        g_bias[pb0 + hcol[2] * plane + r0 + 8] = __float2half_rn(vals[6]);
        g_bias[pb0 + hcol[3] * plane + r0 + 8] = __float2half_rn(vals[7]);

        parity ^= 1;
    }
}

// ---------------- K2/K5: dense GEMM (tf32 mma, double-buffered) ----------------
#define AST 20
#define BST 72
template<int MODE>
__global__ void k_gemm_tc(const float* __restrict__ B1, const float* __restrict__ B2,
                          const float* __restrict__ bias1, const float* __restrict__ bias2,
                          float* __restrict__ Cext) {
    constexpr int LDC   = (MODE == 0) ? 2048 : 512;
    constexpr int SPLIT = (MODE == 0) ? 1536 : (1 << 30);
    constexpr int LD1   = (MODE == 0) ? 1536 : 512;
    constexpr int LD2   = 512;

    const float* A = (MODE == 0) ? g_x : g_og;
    float* C = (MODE == 0) ? g_qkvg : Cext;

    __shared__ __align__(16) float As[2][128 * AST];
    __shared__ __align__(16) float Bs[2][16 * BST];

    int bm = blockIdx.y * 128, bn = blockIdx.x * 64;
    int tid = threadIdx.x, w = tid >> 5, lane = tid & 31;
    int wm = w >> 1, wn = w & 1;
    int lg = lane >> 2, lt = lane & 3;

    float acc[2][4][4] = {};

    int mS = tid >> 1, segS = (tid & 1) * 8;
    int kS = tid >> 4, nS = (tid & 15) * 4;
    int ncol = bn + nS;
    const float* bsrc = (ncol < SPLIT) ? (B1 + ncol) : (B2 + (ncol - SPLIT));
    int ldb = (ncol < SPLIT) ? LD1 : LD2;
    const float* aS = A + (size_t)(bm + mS) * 512 + segS;

    float4 ra0, ra1, rb;
    ra0 = *(const float4*)(aS);
    ra1 = *(const float4*)(aS + 4);
    rb  = *(const float4*)&bsrc[(size_t)kS * ldb];
    {
        uint4 t0 = {f2tf32(ra0.x), f2tf32(ra0.y), f2tf32(ra0.z), f2tf32(ra0.w)};
        uint4 t1 = {f2tf32(ra1.x), f2tf32(ra1.y), f2tf32(ra1.z), f2tf32(ra1.w)};
        uint4 tb = {f2tf32(rb.x),  f2tf32(rb.y),  f2tf32(rb.z),  f2tf32(rb.w)};
        *(uint4*)&As[0][mS * AST + segS]     = t0;
        *(uint4*)&As[0][mS * AST + segS + 4] = t1;
        *(uint4*)&Bs[0][kS * BST + nS]       = tb;
    }
    __syncthreads();

    for (int k0 = 0; k0 < 512; k0 += 16) {
        int cur = (k0 >> 4) & 1;
        bool more = (k0 + 16) < 512;
        if (more) {
            ra0 = *(const float4*)(aS + k0 + 16);
            ra1 = *(const float4*)(aS + k0 + 20);
            rb  = *(const float4*)&bsrc[(size_t)(k0 + 16 + kS) * ldb];
        }

#pragma unroll
        for (int ks = 0; ks < 2; ks++) {
            uint32_t af[2][4];
            const float* ab = &As[cur][(wm * 32 + lg) * AST + ks * 8 + lt];
#pragma unroll
            for (int mf = 0; mf < 2; mf++) {
                const float* a = ab + mf * 16 * AST;
                af[mf][0] = __float_as_uint(a[0]);
                af[mf][1] = __float_as_uint(a[8 * AST]);
                af[mf][2] = __float_as_uint(a[4]);
                af[mf][3] = __float_as_uint(a[8 * AST + 4]);
            }
            uint32_t bf[4][2];
            const float* bb = &Bs[cur][(ks * 8 + lt) * BST + wn * 32 + lg];
#pragma unroll
            for (int nf = 0; nf < 4; nf++) {
                bf[nf][0] = __float_as_uint(bb[nf * 8]);
                bf[nf][1] = __float_as_uint(bb[4 * BST + nf * 8]);
            }
#pragma unroll
            for (int mf = 0; mf < 2; mf++)
#pragma unroll
                for (int nf = 0; nf < 4; nf++)
                    mma_tf32(acc[mf][nf][0], acc[mf][nf][1], acc[mf][nf][2], acc[mf][nf][3],
                             af[mf][0], af[mf][1], af[mf][2], af[mf][3],
                             bf[nf][0], bf[nf][1]);
        }

        if (more) {
            int nxt = cur ^ 1;
            uint4 t0 = {f2tf32(ra0.x), f2tf32(ra0.y), f2tf32(ra0.z), f2tf32(ra0.w)};
            uint4 t1 = {f2tf32(ra1.x), f2tf32(ra1.y), f2tf32(ra1.z), f2tf32(ra1.w)};
            uint4 tb = {f2tf32(rb.x),  f2tf32(rb.y),  f2tf32(rb.z),  f2tf32(rb.w)};
            *(uint4*)&As[nxt][mS * AST + segS]     = t0;
            *(uint4*)&As[nxt][mS * AST + segS + 4] = t1;
            *(uint4*)&Bs[nxt][kS * BST + nS]       = tb;
        }
        __syncthreads();
    }

#pragma unroll
    for (int mf = 0; mf < 2; mf++) {
#pragma unroll
        for (int nf = 0; nf < 4; nf++) {
            int r = bm + wm * 32 + mf * 16 + lg;
            int c = bn + wn * 32 + nf * 8 + 2 * lt;
            float bi0 = (c < SPLIT) ? bias1[c] : bias2[c - SPLIT];
            float bi1 = (c + 1 < SPLIT) ? bias1[c + 1] : bias2[c + 1 - SPLIT];
            float2 v0 = {acc[mf][nf][0] + bi0, acc[mf][nf][1] + bi1};
            float2 v1 = {acc[mf][nf][2] + bi0, acc[mf][nf][3] + bi1};
            *(float2*)&C[(size_t)r * LDC + c]       = v0;
            *(float2*)&C[(size_t)(r + 8) * LDC + c] = v1;
        }
    }
}

// ---------------- K3: q/k LN; q,v head-major, k transposed ----------------
__global__ void k_lnqk(const float* __restrict__ qw, const float* __restrict__ qb,
                       const float* __restrict__ kw, const float* __restrict__ kb) {
    int bn = blockIdx.x;
    const float* row = g_qkvg + (size_t)bn * 2048;
    int b = bn / NNx, nn = bn % NNx;
    float s1 = 0.f, ss1 = 0.f, s2 = 0.f, ss2 = 0.f;
    for (int c = threadIdx.x; c < 512; c += 256) {
        float a = row[c], b2 = row[512 + c];
        s1 += a; ss1 += a * a; s2 += b2; ss2 += b2 * b2;
    }
#pragma unroll
    for (int o = 16; o > 0; o >>= 1) {
        s1  += __shfl_xor_sync(~0u, s1, o);  ss1 += __shfl_xor_sync(~0u, ss1, o);
        s2  += __shfl_xor_sync(~0u, s2, o);  ss2 += __shfl_xor_sync(~0u, ss2, o);
    }
    __shared__ float red[4][8];
    int w = threadIdx.x >> 5, lane = threadIdx.x & 31;
    if (lane == 0) { red[0][w] = s1; red[1][w] = ss1; red[2][w] = s2; red[3][w] = ss2; }
    __syncthreads();
    __shared__ float st[4];
    if (threadIdx.x == 0) {
        float a = 0.f, bb = 0.f, c = 0.f, d = 0.f;
        for (int i = 0; i < 8; i++) { a += red[0][i]; bb += red[1][i]; c += red[2][i]; d += red[3][i]; }
        float m1 = a / 512.f, m2 = c / 512.f;
        st[0] = m1; st[1] = rsqrtf(bb / 512.f - m1 * m1 + LN_EPS);
        st[2] = m2; st[3] = rsqrtf(d / 512.f - m2 * m2 + LN_EPS);
    }
    __syncthreads();
    float m1 = st[0], r1 = st[1], m2 = st[2], r2 = st[3];
    for (int c = threadIdx.x; c < 512; c += 256) {
        int h = c >> 5, d = c & 31;
        size_t oidx  = (((size_t)(b * HHx + h)) * NNx + nn) * DHx + d;
        size_t oidxT = (((size_t)(b * HHx + h)) * DHx + d) * NNx + nn;
        g_qh[oidx]   = (row[c]       - m1) * r1 * qw[c] + qb[c];
        g_khT[oidxT] = (row[512 + c] - m2) * r2 * kw[c] + kb[c];
        g_vh[oidx]   = row[1024 + c];
    }
}

// ---------------- K4: attention — 16 rows, 12 warps (64-j chunks), dynamic smem ----------------
#define AR 16
#define AT_S_OFF   0
#define AT_QP_OFF  (AR * NNx * 4)                      // 49152
#define AT_PART_OFF (AT_QP_OFF + AR * 16 * 8)          // +2048
#define AT_INV_OFF (AT_PART_OFF + 12 * AR * 32 * 4)    // +24576
#define AT_SMEM    (AT_INV_OFF + AR * 4)               // 75904 B
__global__ __launch_bounds__(384, 2) void k_attn() {
    extern __shared__ __align__(16) char smraw[];
    float (*S)[NNx]      = (float(*)[NNx])(smraw + AT_S_OFF);
    u64   (*qp2)[16]     = (u64(*)[16])(smraw + AT_QP_OFF);
    float (*part)[AR][32] = (float(*)[AR][32])(smraw + AT_PART_OFF);
    float* invs          = (float*)(smraw + AT_INV_OFF);

    int i0 = blockIdx.x * AR;
    int h = blockIdx.y, b = blockIdx.z;
    int tid = threadIdx.x;
    int w = tid >> 5, lane = tid & 31;
    size_t bhbase = (size_t)(b * HHx + h) * NNx;

    if (tid < AR * 16) {
        int r = tid >> 4, dp = tid & 15;
        const float* qrow = g_qh + (bhbase + i0 + r) * DHx + 2 * dp;
        float2 qv = *(const float2*)qrow;
        qp2[r][dp] = pack2(qv.x, qv.y);
    }
    __syncthreads();

    const float scale = 0.17677669529663687f;
    const float* kT = g_khT + (size_t)(b * HHx + h) * DHx * NNx;

    // ---- QK^T: warp w owns 64-j chunk; lane owns 2 j; all 16 rows ----
    {
        int jb = w * 64 + lane * 2;
        const float* kTc = kT + jb;
        u64 acc[AR];
#pragma unroll
        for (int r = 0; r < AR; r++) acc[r] = 0;

#pragma unroll
        for (int dg = 0; dg < 4; dg++) {
            u64 kx[8];
#pragma unroll
            for (int dd = 0; dd < 8; dd++)
                kx[dd] = *(const u64*)&kTc[(size_t)(dg * 8 + dd) * NNx];
#pragma unroll
            for (int r = 0; r < AR; r++) {
#pragma unroll
                for (int dd = 0; dd < 4; dd++) {
                    float2 q = up2(qp2[r][dg * 4 + dd]);
                    ffma2(acc[r], kx[2 * dd], splat2(q.x));
                    ffma2(acc[r], kx[2 * dd + 1], splat2(q.y));
                }
            }
        }

#pragma unroll
        for (int r = 0; r < AR; r++) {
            __half2 bh = *(const __half2*)(g_bias + (bhbase + i0 + r) * NNx + jb);
            float2 bf = __half22float2(bh);
            float2 sx = up2(acc[r]);
            float2 out = {sx.x * scale + bf.x, sx.y * scale + bf.y};
            *(float2*)&S[r][jb] = out;
        }
    }
    __syncthreads();

    // ---- softmax: rows r = w, w+12 ----
    for (int r = w; r < AR; r += 12) {
        float* Sr = &S[r][0];
        float mx = -3.4e38f;
        for (int c = lane; c < NNx; c += 32) mx = fmaxf(mx, Sr[c]);
#pragma unroll
        for (int o = 16; o > 0; o >>= 1) mx = fmaxf(mx, __shfl_xor_sync(~0u, mx, o));
        float sum = 0.f;
        for (int c = lane; c < NNx; c += 32) {
            float e = __expf(Sr[c] - mx);
            Sr[c] = e;
            sum += e;
        }
#pragma unroll
        for (int o = 16; o > 0; o >>= 1) sum += __shfl_xor_sync(~0u, sum, o);
        if (lane == 0) invs[r] = 1.0f / sum;
    }
    __syncthreads();

    // ---- AV: warp w owns 64-j chunk; half-warps split it; partials for 16 rows ----
    {
        int dp = lane & 15, jh = lane >> 4;
        int jb = w * 64 + jh * 32;
        const float* vbase = g_vh + bhbase * DHx + 2 * dp;
        float acc[AR][2];
#pragma unroll
        for (int r = 0; r < AR; r++) { acc[r][0] = 0.f; acc[r][1] = 0.f; }

#pragma unroll 2
        for (int jj = 0; jj < 32; jj += 4) {
            int j = jb + jj;
            const float* vp = vbase + (size_t)j * DHx;
            float2 v0 = *(const float2*)(vp);
            float2 v1 = *(const float2*)(vp + 32);
            float2 v2 = *(const float2*)(vp + 64);
            float2 v3 = *(const float2*)(vp + 96);
#pragma unroll
            for (int r = 0; r < AR; r++) {
                float4 p = *(const float4*)&S[r][j];
                acc[r][0] += p.x * v0.x + p.y * v1.x + p.z * v2.x + p.w * v3.x;
                acc[r][1] += p.x * v0.y + p.y * v1.y + p.z * v2.y + p.w * v3.y;
            }
        }
#pragma unroll
        for (int r = 0; r < AR; r++) {
            acc[r][0] += __shfl_down_sync(~0u, acc[r][0], 16);
            acc[r][1] += __shfl_down_sync(~0u, acc[r][1], 16);
        }
        if (jh == 0) {
#pragma unroll
            for (int r = 0; r < AR; r++) {
                part[w][r][2 * dp]     = acc[r][0];
                part[w][r][2 * dp + 1] = acc[r][1];
            }
        }
    }
    __syncthreads();

    // ---- reduce 12 partials + normalize + sigmoid gate + store ----
    for (int o = tid; o < AR * 32; o += 384) {
        int r = o >> 5, d = o & 31;
        float s = 0.f;
#pragma unroll
        for (int ww = 0; ww < 12; ww++) s += part[ww][r][d];
        s *= invs[r];
        size_t bn = (size_t)b * NNx + i0 + r;
        float gg = g_qkvg[bn * 2048 + 1536 + h * DHx + d];
        float sg = 1.0f / (1.0f + __expf(-gg));
        g_og[bn * INNERx + h * DHx + d] = s * sg;
    }
}

// ---------------- launch ----------------
extern "C" void kernel_launch(void* const* d_in, const int* in_sizes, int n_in,
                              void* d_out, int out_size) {
    const float* node = (const float*)d_in[0];
    const float* pair = (const float*)d_in[1];
    const int*   mask = (const int*)d_in[2];
    const float* nnw  = (const float*)d_in[3];
    const float* nnb  = (const float*)d_in[4];
    const float* qkvw = (const float*)d_in[5];
    const float* qkvb = (const float*)d_in[6];
    const float* gw   = (const float*)d_in[7];
    const float* gb   = (const float*)d_in[8];
    const float* qlw  = (const float*)d_in[9];
    const float* qlb  = (const float*)d_in[10];
    const float* klw  = (const float*)d_in[11];
    const float* klb  = (const float*)d_in[12];
    const float* pnw  = (const float*)d_in[13];
    const float* pnb  = (const float*)d_in[14];
    const float* bw   = (const float*)d_in[15];
    const float* ow   = (const float*)d_in[16];
    const float* ob   = (const float*)d_in[17];
    float* out = (float*)d_out;

    cudaFuncSetAttribute(k_fused1, cudaFuncAttributeMaxDynamicSharedMemorySize, PB_SMEM);
    cudaFuncSetAttribute(k_attn, cudaFuncAttributeMaxDynamicSharedMemorySize, AT_SMEM);

    k_fused1<<<PB_GRID + BB * NNx, 128, PB_SMEM>>>(pair, mask, node, nnw, nnb, bw, pnw, pnb);
    k_gemm_tc<0><<<dim3(2048 / 64, (BB * NNx) / 128), 256>>>(qkvw, gw, qkvb, gb, nullptr);
    k_lnqk<<<BB * NNx, 256>>>(qlw, qlb, klw, klb);
    k_attn<<<dim3(NNx / AR, HHx, BB), 384, AT_SMEM>>>();
    k_gemm_tc<1><<<dim3(512 / 64, (BB * NNx) / 128), 256>>>(ow, ow, ob, ob, out);
}